// round 8
// baseline (speedup 1.0000x reference)
#include <cuda_runtime.h>
#include <math.h>

// Problem constants
#define kN 4
#define kH 96
#define kW 96
#define kCh 256
#define kC 64
#define kL 9216          // 96*96
#define kNH 4
#define kHB 64           // hash buckets
#define kCHK 144
#define kTOTJ 36864      // kNH*kL
#define kJW 432          // 3*kCHK

// smem strides (attn)
#define QRS 68
#define KCS 76
#define VSTR 260
#define PSTR 76
#define ATHR 576

// conv packed layouts
#define WNY 66           // float4 row stride for packed weights in smem

__device__ __forceinline__ float cvt_tf32(float f) {
    unsigned r; asm("cvt.rna.tf32.f32 %0,%1;" : "=r"(r) : "f"(f));
    return __uint_as_float(r);
}
__device__ __forceinline__ void mma_tf32(float* d, const unsigned* a, unsigned b0, unsigned b1) {
    asm("mma.sync.aligned.m16n8k8.row.col.f32.tf32.tf32.f32 "
        "{%0,%1,%2,%3},{%4,%5,%6,%7},{%8,%9},{%0,%1,%2,%3};"
        : "+f"(d[0]), "+f"(d[1]), "+f"(d[2]), "+f"(d[3])
        : "r"(a[0]), "r"(a[1]), "r"(a[2]), "r"(a[3]), "r"(b0), "r"(b1));
}
__device__ __forceinline__ void cp16(float4* dst, const float4* src) {
    unsigned s = (unsigned)__cvta_generic_to_shared(dst);
    asm volatile("cp.async.cg.shared.global [%0],[%1],16;" :: "r"(s), "l"(src));
}
__device__ __forceinline__ void cp_commit() { asm volatile("cp.async.commit_group;"); }
__device__ __forceinline__ void cp_wait1() { asm volatile("cp.async.wait_group 1;"); }
__device__ __forceinline__ void cp_wait0() { asm volatile("cp.async.wait_group 0;"); }

// -------- scratch (device globals; no allocation allowed) --------
__device__ float g_x[(size_t)kN*kL*kC];            // x_embed (n,t,f)
__device__ float g_y[(size_t)kN*kL*kCh];           // y_embed (n,t,e)
__device__ int   g_codes[kN*kTOTJ];
__device__ int   g_sorted[kN*kTOTJ];
__device__ int   g_hist[kN*144*256];
__device__ float g_ret[(size_t)kN*kNH*kL*kCh];     // attention out (n,h,t,e)
__device__ float g_bs[kN*kNH*kL];                  // lse (n,h,t)
// prepacked operands
__device__ float4 g_wyp[4*16*36*64];               // convy weights [cog][sl][r][nn]
__device__ float4 g_wxh[16*36*64];                 // convx weights hi
__device__ float4 g_wxl[16*36*64];                 // convx weights lo
__device__ float  g_xih[(size_t)kN*kL*kCh];        // input hi (NHWC)
__device__ float  g_xil[(size_t)kN*kL*kCh];        // input lo

// ---------------- prepack kernels ----------------
__global__ __launch_bounds__(256) void prep_in_kernel(const float* __restrict__ in)
{
    size_t i = (size_t)blockIdx.x*256 + threadIdx.x;   // f4 index, total kN*kL*64
    float4 v = ((const float4*)in)[i];
    float4 vh, vl;
    vh.x = cvt_tf32(v.x); vl.x = cvt_tf32(v.x - vh.x);
    vh.y = cvt_tf32(v.y); vl.y = cvt_tf32(v.y - vh.y);
    vh.z = cvt_tf32(v.z); vl.z = cvt_tf32(v.z - vh.z);
    vh.w = cvt_tf32(v.w); vl.w = cvt_tf32(v.w - vh.w);
    ((float4*)g_xih)[i] = vh;
    ((float4*)g_xil)[i] = vl;
}

__global__ __launch_bounds__(256) void prep_wx_kernel(const float* __restrict__ w)
{
    int i = blockIdx.x*256 + threadIdx.x;              // < 36864 = 16*36*64
    int nn = i & 63;
    int r  = (i >> 6) % 36;
    int sl = i / 2304;
    int tap = r >> 2, kq4 = r & 3;
    int cin = sl*16 + 4*kq4;
    const float* wp = &w[(tap*kCh + cin)*kC + nn];
    float f0 = wp[0], f1 = wp[kC], f2 = wp[2*kC], f3 = wp[3*kC];
    float4 vh, vl;
    vh.x = cvt_tf32(f0); vl.x = cvt_tf32(f0 - vh.x);
    vh.y = cvt_tf32(f1); vl.y = cvt_tf32(f1 - vh.y);
    vh.z = cvt_tf32(f2); vl.z = cvt_tf32(f2 - vh.z);
    vh.w = cvt_tf32(f3); vl.w = cvt_tf32(f3 - vh.w);
    g_wxh[i] = vh; g_wxl[i] = vl;
}

__global__ __launch_bounds__(256) void prep_wy_kernel(const float* __restrict__ w)
{
    int i = blockIdx.x*256 + threadIdx.x;              // < 4*36864
    int j = i % 36864;
    int cog = i / 36864;
    int nn = j & 63;
    int r  = (j >> 6) % 36;
    int sl = j / 2304;
    int tap = r >> 2, kq4 = r & 3;
    int cin = sl*16 + 4*kq4;
    const float* wp = &w[(size_t)(tap*kCh + cin)*kCh + cog*64 + nn];
    float4 v;
    v.x = wp[0]; v.y = wp[kCh]; v.z = wp[2*kCh]; v.w = wp[3*kCh];
    g_wyp[i] = v;
}

// ---------------- match conv (x path), 3xTF32 MMA, cp.async double-buffer --
// block tile: 128 pixels (8x16) x 64 cout. warps 4(M)x2(N). K sliced 16 cin.
__global__ __launch_bounds__(256, 1) void convx_mma_kernel(const float* __restrict__ bias)
{
    extern __shared__ float4 smx[];
    float4* pH[2] = {smx,        smx + 720};
    float4* pL[2] = {smx + 1440, smx + 2160};
    float4* wH[2] = {smx + 2880, smx + 2880 + 2376};
    float4* wL[2] = {smx + 7632, smx + 7632 + 2376};

    int n    = blockIdx.x / 72;
    int tile = blockIdx.x % 72;
    int by = (tile / 6) * 8, bx = (tile % 6) * 16;
    int tid = threadIdx.x;
    int wid = tid >> 5, lane = tid & 31;
    int m0w = (wid >> 1) * 32;
    int n0w = (wid & 1) * 32;
    int kq = lane & 3, nq = lane >> 2;

    // hoisted staging offsets
    int p_goff[3];
#pragma unroll
    for (int i = 0; i < 3; i++) {
        int lin = tid + i*256;
        p_goff[i] = -1;
        if (lin < 720) {
            int pos = lin >> 2, kq4 = lin & 3;
            int yy = pos / 18, xx = pos % 18;
            int hh = by + yy - 1, ww = bx + xx - 1;
            if (hh >= 0 && hh < kH && ww >= 0 && ww < kW)
                p_goff[i] = (((n*kH + hh)*kW + ww) << 8) + 4*kq4;
        }
    }
    // zero OOB patch slots in both buffers
#pragma unroll
    for (int i = 0; i < 3; i++) {
        int lin = tid + i*256;
        if (lin < 720 && p_goff[i] < 0) {
            float4 z = {0.f,0.f,0.f,0.f};
            pH[0][lin] = z; pH[1][lin] = z;
            pL[0][lin] = z; pL[1][lin] = z;
        }
    }

    float acc[8][4];
#pragma unroll
    for (int i = 0; i < 8; i++)
#pragma unroll
        for (int j = 0; j < 4; j++) acc[i][j] = 0.f;

    int pb[4];
#pragma unroll
    for (int t = 0; t < 4; t++) {
        int m = m0w + t*8 + nq;
        pb[t] = (m >> 4)*18 + (m & 15);
    }

    auto stage = [&](int sl, int buf) {
#pragma unroll
        for (int i = 0; i < 3; i++) {
            int lin = tid + i*256;
            if (lin < 720 && p_goff[i] >= 0) {
                cp16(&pH[buf][lin], (const float4*)&g_xih[p_goff[i] + sl*16]);
                cp16(&pL[buf][lin], (const float4*)&g_xil[p_goff[i] + sl*16]);
            }
        }
#pragma unroll
        for (int i = 0; i < 9; i++) {
            int lin = tid + i*256;
            int r = lin >> 6, nn = lin & 63;
            int didx = r*WNY + nn;
            int sidx = sl*2304 + lin;
            cp16(&wH[buf][didx], &g_wxh[sidx]);
            cp16(&wL[buf][didx], &g_wxl[sidx]);
        }
    };

    stage(0, 0); cp_commit();
    for (int sl = 0; sl < 16; sl++) {
        int buf = sl & 1;
        if (sl < 15) { stage(sl + 1, buf ^ 1); cp_commit(); cp_wait1(); }
        else cp_wait0();
        __syncthreads();
        float4* p4h = pH[buf]; float4* p4l = pL[buf];
        float4* w4h = wH[buf]; float4* w4l = wL[buf];

#pragma unroll
        for (int tap = 0; tap < 9; tap++) {
            int posoff = (tap/3)*18 + (tap%3);
            float4 ah[4], al[4];
#pragma unroll
            for (int t = 0; t < 4; t++) {
                int o = (pb[t] + posoff)*4 + kq;
                ah[t] = p4h[o]; al[t] = p4l[o];
            }
            unsigned Ah00[4] = {__float_as_uint(ah[0].x), __float_as_uint(ah[1].x),
                                __float_as_uint(ah[0].y), __float_as_uint(ah[1].y)};
            unsigned Ah01[4] = {__float_as_uint(ah[0].z), __float_as_uint(ah[1].z),
                                __float_as_uint(ah[0].w), __float_as_uint(ah[1].w)};
            unsigned Ah10[4] = {__float_as_uint(ah[2].x), __float_as_uint(ah[3].x),
                                __float_as_uint(ah[2].y), __float_as_uint(ah[3].y)};
            unsigned Ah11[4] = {__float_as_uint(ah[2].z), __float_as_uint(ah[3].z),
                                __float_as_uint(ah[2].w), __float_as_uint(ah[3].w)};
            unsigned Al00[4] = {__float_as_uint(al[0].x), __float_as_uint(al[1].x),
                                __float_as_uint(al[0].y), __float_as_uint(al[1].y)};
            unsigned Al01[4] = {__float_as_uint(al[0].z), __float_as_uint(al[1].z),
                                __float_as_uint(al[0].w), __float_as_uint(al[1].w)};
            unsigned Al10[4] = {__float_as_uint(al[2].x), __float_as_uint(al[3].x),
                                __float_as_uint(al[2].y), __float_as_uint(al[3].y)};
            unsigned Al11[4] = {__float_as_uint(al[2].z), __float_as_uint(al[3].z),
                                __float_as_uint(al[2].w), __float_as_uint(al[3].w)};
            int wr = (tap*4 + kq)*WNY + n0w + nq;
#pragma unroll
            for (int nt = 0; nt < 4; nt++) {
                float4 bh = w4h[wr + nt*8];
                float4 bl = w4l[wr + nt*8];
                unsigned bhx = __float_as_uint(bh.x), bhy = __float_as_uint(bh.y);
                unsigned bhz = __float_as_uint(bh.z), bhw = __float_as_uint(bh.w);
                unsigned blx = __float_as_uint(bl.x), bly = __float_as_uint(bl.y);
                unsigned blz = __float_as_uint(bl.z), blw = __float_as_uint(bl.w);
                mma_tf32(acc[nt], Ah00, bhx, bhy);
                mma_tf32(acc[nt], Ah01, bhz, bhw);
                mma_tf32(acc[nt], Ah00, blx, bly);
                mma_tf32(acc[nt], Ah01, blz, blw);
                mma_tf32(acc[nt], Al00, bhx, bhy);
                mma_tf32(acc[nt], Al01, bhz, bhw);
                mma_tf32(acc[4+nt], Ah10, bhx, bhy);
                mma_tf32(acc[4+nt], Ah11, bhz, bhw);
                mma_tf32(acc[4+nt], Ah10, blx, bly);
                mma_tf32(acc[4+nt], Ah11, blz, blw);
                mma_tf32(acc[4+nt], Al10, bhx, bhy);
                mma_tf32(acc[4+nt], Al11, bhz, bhw);
            }
        }
        __syncthreads();
    }

    // epilogue: scatter to g_x embed layout (p = f*144 + t/64, c = t%64)
#pragma unroll
    for (int mt = 0; mt < 2; mt++) {
#pragma unroll
        for (int half = 0; half < 2; half++) {
            int m = m0w + mt*16 + half*8 + nq;
            int py = by + (m >> 4), px = bx + (m & 15);
            int p = py*kW + px;
            int f = p / 144, pm = p % 144;
#pragma unroll
            for (int nt = 0; nt < 4; nt++) {
                int c = n0w + nt*8 + 2*kq;
                float v0 = acc[mt*4 + nt][half*2]     + bias[c];
                float v1 = acc[mt*4 + nt][half*2 + 1] + bias[c+1];
                g_x[((size_t)n*kL + pm*64 + c    )*kC + f] = v0;
                g_x[((size_t)n*kL + pm*64 + c + 1)*kC + f] = v1;
            }
        }
    }
}

// ---------------- asm conv (y path), tf32 MMA, cp.async double-buffer ------
// block tile: 256 pixels (16x16 region) x 64 cout. warp M=64 (4 m-tiles).
__global__ __launch_bounds__(256, 1) void convy_mma_kernel(
    const float* __restrict__ in, const float* __restrict__ bias)
{
    extern __shared__ float4 smy[];
    float4* pB[2] = {smy,        smy + 1296};
    float4* wB[2] = {smy + 2592, smy + 2592 + 2376};

    int n    = blockIdx.x / 36;
    int tile = blockIdx.x % 36;
    int by = (tile / 6) * 16, bx = (tile % 6) * 16;
    int cog = blockIdx.y;
    int co0 = cog * 64;
    int tid = threadIdx.x;
    int wid = tid >> 5, lane = tid & 31;
    int m0w = (wid >> 1) * 64;
    int n0w = (wid & 1) * 32;
    int kq = lane & 3;
    int nq = lane >> 2;

    int p_goff[6];
#pragma unroll
    for (int i = 0; i < 6; i++) {
        int lin = tid + i*256;
        p_goff[i] = -1;
        if (lin < 1296) {
            int pos = lin >> 2, kq4 = lin & 3;
            int yy = pos / 18, xx = pos % 18;
            int hh = by + yy - 1, ww = bx + xx - 1;
            if (hh >= 0 && hh < kH && ww >= 0 && ww < kW)
                p_goff[i] = (((n*kH + hh)*kW + ww) << 8) + 4*kq4;
        }
    }
#pragma unroll
    for (int i = 0; i < 6; i++) {
        int lin = tid + i*256;
        if (lin < 1296 && p_goff[i] < 0) {
            float4 z = {0.f,0.f,0.f,0.f};
            pB[0][lin] = z; pB[1][lin] = z;
        }
    }

    float acc[16][4];
#pragma unroll
    for (int i = 0; i < 16; i++)
#pragma unroll
        for (int j = 0; j < 4; j++) acc[i][j] = 0.f;

    int pb[8];
#pragma unroll
    for (int t = 0; t < 8; t++) {
        int m = m0w + t*8 + nq;
        pb[t] = (m >> 4)*18 + (m & 15);
    }

    const float4* wsrc = &g_wyp[cog*36864];

    auto stage = [&](int sl, int buf) {
#pragma unroll
        for (int i = 0; i < 6; i++) {
            int lin = tid + i*256;
            if (lin < 1296 && p_goff[i] >= 0)
                cp16(&pB[buf][lin], (const float4*)&in[p_goff[i] + sl*16]);
        }
#pragma unroll
        for (int i = 0; i < 9; i++) {
            int lin = tid + i*256;
            int r = lin >> 6, nn = lin & 63;
            cp16(&wB[buf][r*WNY + nn], &wsrc[sl*2304 + lin]);
        }
    };

    stage(0, 0); cp_commit();
    for (int sl = 0; sl < 16; sl++) {
        int buf = sl & 1;
        if (sl < 15) { stage(sl + 1, buf ^ 1); cp_commit(); cp_wait1(); }
        else cp_wait0();
        __syncthreads();
        float4* patch4 = pB[buf];
        float4* wtp4   = wB[buf];

#pragma unroll
        for (int tap = 0; tap < 9; tap++) {
            int posoff = (tap/3)*18 + (tap%3);
            float4 a4[8];
#pragma unroll
            for (int t = 0; t < 8; t++)
                a4[t] = patch4[(pb[t] + posoff)*4 + kq];
            unsigned A0[4][4], A1[4][4];
#pragma unroll
            for (int mt = 0; mt < 4; mt++) {
                A0[mt][0] = __float_as_uint(a4[2*mt].x);
                A0[mt][1] = __float_as_uint(a4[2*mt+1].x);
                A0[mt][2] = __float_as_uint(a4[2*mt].y);
                A0[mt][3] = __float_as_uint(a4[2*mt+1].y);
                A1[mt][0] = __float_as_uint(a4[2*mt].z);
                A1[mt][1] = __float_as_uint(a4[2*mt+1].z);
                A1[mt][2] = __float_as_uint(a4[2*mt].w);
                A1[mt][3] = __float_as_uint(a4[2*mt+1].w);
            }
            int wr = (tap*4 + kq)*WNY + n0w + nq;
#pragma unroll
            for (int nt = 0; nt < 4; nt++) {
                float4 b4 = wtp4[wr + nt*8];
                unsigned bx0 = __float_as_uint(b4.x), by0 = __float_as_uint(b4.y);
                unsigned bz0 = __float_as_uint(b4.z), bw0 = __float_as_uint(b4.w);
#pragma unroll
                for (int mt = 0; mt < 4; mt++) {
                    mma_tf32(acc[mt*4 + nt], A0[mt], bx0, by0);
                    mma_tf32(acc[mt*4 + nt], A1[mt], bz0, bw0);
                }
            }
        }
        __syncthreads();
    }

#pragma unroll
    for (int mt = 0; mt < 4; mt++) {
#pragma unroll
        for (int half = 0; half < 2; half++) {
            int m = m0w + mt*16 + half*8 + nq;
            int py = by + (m >> 4), px = bx + (m & 15);
            int p = py*kW + px;
            int e = p / 36, pm = p % 36;
#pragma unroll
            for (int nt = 0; nt < 4; nt++) {
                int c = co0 + n0w + nt*8 + 2*kq;
                float v0 = acc[mt*4 + nt][half*2]     + bias[c];
                float v1 = acc[mt*4 + nt][half*2 + 1] + bias[c+1];
                g_y[((size_t)n*kL + pm*256 + c    )*kCh + e] = v0;
                g_y[((size_t)n*kL + pm*256 + c + 1)*kCh + e] = v1;
            }
        }
    }
}

// ---------------- LSH hashing ----------------
__global__ __launch_bounds__(256) void hash_kernel(const float* __restrict__ rot)
{
    __shared__ float Rsm[8192];
    __shared__ float xrow[8][64];
    int tid = threadIdx.x;
    for (int lin = tid; lin < 8192; lin += 256) Rsm[lin] = rot[lin];
    int wid = tid >> 5, lane = tid & 31;
    int idx = blockIdx.x*8 + wid;
    int n = idx / kL, t = idx % kL;
    const float* xr = &g_x[((size_t)n*kL + t)*kC];
    xrow[wid][lane]      = xr[lane];
    xrow[wid][lane + 32] = xr[lane + 32];
    __syncthreads();
#pragma unroll
    for (int h = 0; h < 4; h++) {
        float s = 0.f;
#pragma unroll
        for (int f = 0; f < 64; f++) s += xrow[wid][f] * Rsm[f*128 + h*32 + lane];
        float bv; int bi;
        if (s >= -s) { bv = s;  bi = lane; }
        else         { bv = -s; bi = lane + 32; }
#pragma unroll
        for (int off = 16; off > 0; off >>= 1) {
            float ov = __shfl_xor_sync(0xffffffffu, bv, off);
            int   oi = __shfl_xor_sync(0xffffffffu, bi, off);
            if (ov > bv || (ov == bv && oi < bi)) { bv = ov; bi = oi; }
        }
        if (lane == 0) g_codes[n*kTOTJ + h*kL + t] = bi + h*kHB;
    }
}

// ---------------- stable counting sort (argsort) ----------------
__global__ __launch_bounds__(256) void sortA_kernel()
{
    __shared__ int hist[256];
    int b = blockIdx.x; int n = b / 144, blk = b % 144; int tid = threadIdx.x;
    hist[tid] = 0; __syncthreads();
    int code = g_codes[n*kTOTJ + blk*256 + tid];
    atomicAdd(&hist[code], 1);
    __syncthreads();
    g_hist[(n*144 + blk)*256 + tid] = hist[tid];
}

__global__ __launch_bounds__(256) void sortBC_kernel()
{
    __shared__ int scanbuf[256];
    __shared__ int comb[256];
    __shared__ int cs[256];
    int b = blockIdx.x; int n = b / 144, blk = b % 144; int v = threadIdx.x;

    int tot = 0, off = 0;
    const int* hb = &g_hist[n*144*256 + v];
    for (int bb = 0; bb < 144; bb++) {
        int hv = hb[bb*256];
        tot += hv;
        if (bb < blk) off += hv;
    }
    scanbuf[v] = tot;
    __syncthreads();
    for (int d = 1; d < 256; d <<= 1) {
        int y = (v >= d) ? scanbuf[v - d] : 0;
        __syncthreads();
        scanbuf[v] += y;
        __syncthreads();
    }
    comb[v] = (scanbuf[v] - tot) + off;
    int c = g_codes[n*kTOTJ + blk*256 + v];
    cs[v] = c;
    __syncthreads();
    int rank = 0;
    for (int j = 0; j < v; j++) rank += (cs[j] == c);
    g_sorted[n*kTOTJ + comb[c] + rank] = blk*256 + v;
}

// ---------------- fused chunk attention (tf32 MMA, no global scratch) ------
__global__ __launch_bounds__(ATHR, 1) void attn_kernel()
{
    extern __shared__ float sm[];
    float* Qr  = sm;                      // 144*QRS
    float* Kc  = Qr + 144*QRS;            // 64*KCS
    float* Vsm = Kc + 64*KCS;             // 72*VSTR
    float* Psm = Vsm + 72*VSTR;           // 144*PSTR
    float* m_r = Psm + 144*PSTR;          // 144
    float* rowsumA = m_r + 144;           // 144
    float* rowsumB = rowsumA + 144;       // 144
    int* tIdx = (int*)(rowsumB + 144);    // 432

    int g = blockIdx.x;
    int n = g >> 8, k = g & 255;
    int h = k >> 6, kl = k & 63;
    int tid = threadIdx.x;
    int wid = tid >> 5, lane = tid & 31;
    int kq = lane & 3, nq = lane >> 2;

    for (int j = tid; j < kJW; j += ATHR) {
        int cchunk = j / kCHK, i = j % kCHK;
        int skl = (cchunk == 0) ? kl : (cchunk == 1) ? ((kl + 63) & 63) : ((kl + 1) & 63);
        int s = (h*64 + skl)*kCHK + i;
        tIdx[j] = g_sorted[n*kTOTJ + s] % kL;
    }
    for (int i = tid; i < kCHK; i += ATHR) { rowsumA[i] = 0.f; rowsumB[i] = 0.f; }
    __syncthreads();

    {
#pragma unroll
        for (int rr = 0; rr < 8; rr++) {
            int r = wid*8 + rr;
            const float* xr = &g_x[((size_t)n*kL + tIdx[r])*kC];
            float a = xr[lane], b = xr[lane + 32];
            Qr[r*QRS + lane] = a;
            Qr[r*QRS + lane + 32] = b;
            float ss = a*a + b*b;
#pragma unroll
            for (int off = 16; off > 0; off >>= 1)
                ss += __shfl_xor_sync(0xffffffffu, ss, off);
            if (lane == 0) m_r[r] = ss * rsqrtf(fmaxf(ss, 5e-5f));
        }
    }
    __syncthreads();

    int wq = wid % 9;
    int halfq = wid / 9;
    int m0 = wq * 16;
    float mA = m_r[m0 + nq], mB = m_r[m0 + 8 + nq];

    float Oacc[16][4];
#pragma unroll
    for (int i = 0; i < 16; i++)
#pragma unroll
        for (int j = 0; j < 4; j++) Oacc[i][j] = 0.f;

    for (int jc = 0; jc < 6; jc++) {
        int j0 = jc*72;
        if (wid < 9) {
            int col = wid*8 + (lane >> 2);
            int fs = (lane & 3) * 16;
            const float4* xr = (const float4*)&g_x[((size_t)n*kL + tIdx[j0 + col])*kC + fs];
            float4 v0 = xr[0], v1 = xr[1], v2 = xr[2], v3 = xr[3];
            float ss = v0.x*v0.x + v0.y*v0.y + v0.z*v0.z + v0.w*v0.w
                     + v1.x*v1.x + v1.y*v1.y + v1.z*v1.z + v1.w*v1.w
                     + v2.x*v2.x + v2.y*v2.y + v2.z*v2.z + v2.w*v2.w
                     + v3.x*v3.x + v3.y*v3.y + v3.z*v3.z + v3.w*v3.w;
            ss += __shfl_xor_sync(0xffffffffu, ss, 1);
            ss += __shfl_xor_sync(0xffffffffu, ss, 2);
            float r = rsqrtf(fmaxf(ss, 5e-5f));
            float* kcb = &Kc[fs*KCS + col];
            kcb[0*KCS] = v0.x*r; kcb[1*KCS] = v0.y*r;
            kcb[2*KCS] = v0.z*r; kcb[3*KCS] = v0.w*r;
            kcb[4*KCS] = v1.x*r; kcb[5*KCS] = v1.y*r;
            kcb[6*KCS] = v1.z*r; kcb[7*KCS] = v1.w*r;
            kcb[8*KCS] = v2.x*r; kcb[9*KCS] = v2.y*r;
            kcb[10*KCS] = v2.z*r; kcb[11*KCS] = v2.w*r;
            kcb[12*KCS] = v3.x*r; kcb[13*KCS] = v3.y*r;
            kcb[14*KCS] = v3.z*r; kcb[15*KCS] = v3.w*r;
        } else {
            int w2 = wid - 9;
#pragma unroll
            for (int rr = 0; rr < 8; rr++) {
                int row = w2*8 + rr;
                const float4* yr = (const float4*)&g_y[((size_t)n*kL + tIdx[j0 + row])*kCh];
                *(float4*)&Vsm[row*VSTR + lane*4]      = yr[lane];
                *(float4*)&Vsm[row*VSTR + (lane+32)*4] = yr[lane + 32];
            }
        }
        __syncthreads();

        {
            unsigned Af[8][4];
#pragma unroll
            for (int ks = 0; ks < 8; ks++) {
                const float* q0 = &Qr[(m0 + nq)*QRS + ks*8 + kq];
                const float* q1 = &Qr[(m0 + 8 + nq)*QRS + ks*8 + kq];
                Af[ks][0] = __float_as_uint(q0[0]);
                Af[ks][1] = __float_as_uint(q1[0]);
                Af[ks][2] = __float_as_uint(q0[4]);
                Af[ks][3] = __float_as_uint(q1[4]);
            }
            float s0 = 0.f, s1 = 0.f;
            int ntBeg = halfq ? 5 : 0;
            int ntEnd = halfq ? 9 : 5;
            for (int nt = ntBeg; nt < ntEnd; nt++) {
                float acc[4] = {0.f, 0.f, 0.f, 0.f};
#pragma unroll
                for (int ks = 0; ks < 8; ks++) {
                    unsigned b0 = __float_as_uint(Kc[(ks*8 + kq)*KCS + nt*8 + nq]);
                    unsigned b1 = __float_as_uint(Kc[(ks*8 + 4 + kq)*KCS + nt*8 + nq]);
                    mma_tf32(acc, Af[ks], b0, b1);
                }
                float e0 = __expf(acc[0] - mA), e1 = __expf(acc[1] - mA);
                float e2 = __expf(acc[2] - mB), e3 = __expf(acc[3] - mB);
                s0 += e0 + e1; s1 += e2 + e3;
                float2 pA; pA.x = e0; pA.y = e1;
                float2 pB2; pB2.x = e2; pB2.y = e3;
                *(float2*)&Psm[(m0 + nq)*PSTR + nt*8 + 2*kq] = pA;
                *(float2*)&Psm[(m0 + 8 + nq)*PSTR + nt*8 + 2*kq] = pB2;
            }
            s0 += __shfl_xor_sync(0xffffffffu, s0, 1);
            s0 += __shfl_xor_sync(0xffffffffu, s0, 2);
            s1 += __shfl_xor_sync(0xffffffffu, s1, 1);
            s1 += __shfl_xor_sync(0xffffffffu, s1, 2);
            if (kq == 0) {
                float* rs = halfq ? rowsumB : rowsumA;
                rs[m0 + nq] += s0;
                rs[m0 + 8 + nq] += s1;
            }
        }
        __syncthreads();

        {
            int n0 = halfq * 128;
#pragma unroll
            for (int ks = 0; ks < 9; ks++) {
                unsigned A[4];
                const float* p0 = &Psm[(m0 + nq)*PSTR + ks*8 + kq];
                const float* p1 = &Psm[(m0 + 8 + nq)*PSTR + ks*8 + kq];
                A[0] = __float_as_uint(p0[0]);
                A[1] = __float_as_uint(p1[0]);
                A[2] = __float_as_uint(p0[4]);
                A[3] = __float_as_uint(p1[4]);
                const float* vb0 = &Vsm[(ks*8 + kq)*VSTR + n0 + nq];
                const float* vb1 = &Vsm[(ks*8 + 4 + kq)*VSTR + n0 + nq];
#pragma unroll
                for (int nt = 0; nt < 16; nt++) {
                    unsigned b0 = __float_as_uint(vb0[nt*8]);
                    unsigned b1 = __float_as_uint(vb1[nt*8]);
                    mma_tf32(Oacc[nt], A, b0, b1);
                }
            }
        }
        __syncthreads();
    }

    {
        int n0 = halfq * 128;
        int rA = m0 + nq, rB = rA + 8;
        float sumA = rowsumA[rA] + rowsumB[rA];
        float sumB = rowsumA[rB] + rowsumB[rB];
        float invA = 1.f / sumA;
        float invB = 1.f / sumB;
        size_t baseA = ((size_t)(n*4 + h)*kL + tIdx[rA])*kCh;
        size_t baseB = ((size_t)(n*4 + h)*kL + tIdx[rB])*kCh;
#pragma unroll
        for (int nt = 0; nt < 16; nt++) {
            int cA = n0 + nt*8 + 2*kq;
            float2 oA; oA.x = Oacc[nt][0]*invA; oA.y = Oacc[nt][1]*invA;
            float2 oB; oB.x = Oacc[nt][2]*invB; oB.y = Oacc[nt][3]*invB;
            *(float2*)&g_ret[baseA + cA] = oA;
            *(float2*)&g_ret[baseB + cA] = oB;
        }
        if (wid < 9 && lane < 16) {
            int row = wid*16 + lane;
            float s = rowsumA[row] + rowsumB[row];
            g_bs[(size_t)(n*4 + h)*kL + tIdx[row]] = m_r[row] + __logf(s);
        }
    }
}

// ---------------- head combine + residual + output layout ----------------
__global__ __launch_bounds__(256) void combine_kernel(
    const float* __restrict__ in, float* __restrict__ out)
{
    __shared__ float accs[256*33];
    __shared__ float probs[4*256];
    int n = blockIdx.x / 36, q = blockIdx.x % 36;
    int e0 = blockIdx.y * 32;
    int tid = threadIdx.x;

    {
        int t = q*256 + tid;
        float b0 = g_bs[(size_t)(n*4 + 0)*kL + t];
        float b1 = g_bs[(size_t)(n*4 + 1)*kL + t];
        float b2 = g_bs[(size_t)(n*4 + 2)*kL + t];
        float b3 = g_bs[(size_t)(n*4 + 3)*kL + t];
        float m = fmaxf(fmaxf(b0, b1), fmaxf(b2, b3));
        float x0 = __expf(b0 - m), x1 = __expf(b1 - m);
        float x2 = __expf(b2 - m), x3 = __expf(b3 - m);
        float sinv = 1.f / (x0 + x1 + x2 + x3);
        probs[0*256 + tid] = x0*sinv; probs[1*256 + tid] = x1*sinv;
        probs[2*256 + tid] = x2*sinv; probs[3*256 + tid] = x3*sinv;
    }
    for (int lin = tid; lin < 256*33; lin += 256) accs[lin] = 0.f;
    __syncthreads();

    for (int h = 0; h < 4; h++) {
        for (int lin = tid; lin < 256*32; lin += 256) {
            int cc = lin >> 5, e = lin & 31;
            float v = g_ret[((size_t)(n*4 + h)*kL + q*256 + cc)*kCh + e0 + e];
            accs[cc*33 + e] += probs[h*256 + cc] * v;
        }
    }
    __syncthreads();

    for (int lin = tid; lin < 32*256; lin += 256) {
        int e = lin >> 8, c = lin & 255;
        int p = (e0 + e)*36 + q;
        size_t oi = ((size_t)n*kL + p)*kCh + c;
        out[oi] = 0.1f*accs[c*33 + e] + in[oi];
    }
}

// ---------------- launch ----------------
extern "C" void kernel_launch(void* const* d_in, const int* in_sizes, int n_in,
                              void* d_out, int out_size)
{
    const float* input     = (const float*)d_in[0];
    const float* w_match   = (const float*)d_in[1];
    const float* b_match   = (const float*)d_in[2];
    const float* w_asm     = (const float*)d_in[3];
    const float* b_asm     = (const float*)d_in[4];
    const float* rotations = (const float*)d_in[5];
    float* out = (float*)d_out;

    const int CONVX_SMEM = 12384 * 16;                                  // 198144
    const int CONVY_SMEM = (2592 + 4752) * 16;                          // 117504
    const int ATT_SMEM   = (144*QRS + 64*KCS + 72*VSTR + 144*PSTR + 144*3 + 432) * 4;

    cudaFuncSetAttribute(convx_mma_kernel, cudaFuncAttributeMaxDynamicSharedMemorySize, CONVX_SMEM);
    cudaFuncSetAttribute(convy_mma_kernel, cudaFuncAttributeMaxDynamicSharedMemorySize, CONVY_SMEM);
    cudaFuncSetAttribute(attn_kernel,      cudaFuncAttributeMaxDynamicSharedMemorySize, ATT_SMEM);

    prep_in_kernel<<<kN*kL*64/256, 256>>>(input);
    prep_wx_kernel<<<144, 256>>>(w_match);
    prep_wy_kernel<<<576, 256>>>(w_asm);
    // convy in ncu capture slot 4
    convy_mma_kernel<<<dim3(kN*36, 4), 256, CONVY_SMEM>>>(input, b_asm);
    convx_mma_kernel<<<kN*72, 256, CONVX_SMEM>>>(b_match);
    hash_kernel<<<kN*kL/8, 256>>>(rotations);
    sortA_kernel<<<kN*144, 256>>>();
    sortBC_kernel<<<kN*144, 256>>>();
    attn_kernel<<<kN*256, ATHR, ATT_SMEM>>>();
    combine_kernel<<<dim3(kN*36, 8), 256>>>(input, out);
}

// round 9
// speedup vs baseline: 1.0024x; 1.0024x over previous
#include <cuda_runtime.h>
#include <math.h>

// Problem constants
#define kN 4
#define kH 96
#define kW 96
#define kCh 256
#define kC 64
#define kL 9216          // 96*96
#define kNH 4
#define kHB 64           // hash buckets
#define kCHK 144
#define kTOTJ 36864      // kNH*kL
#define kJW 432          // 3*kCHK

// smem strides (attn)
#define QRS 68
#define KCS 76
#define VSTR 260
#define PSTR 76
#define ATHR 576

// conv packed layouts
#define WNY 66           // float4 row stride for packed weights in smem

__device__ __forceinline__ float cvt_tf32(float f) {
    unsigned r; asm("cvt.rna.tf32.f32 %0,%1;" : "=r"(r) : "f"(f));
    return __uint_as_float(r);
}
__device__ __forceinline__ void mma_tf32(float* d, const unsigned* a, unsigned b0, unsigned b1) {
    asm("mma.sync.aligned.m16n8k8.row.col.f32.tf32.tf32.f32 "
        "{%0,%1,%2,%3},{%4,%5,%6,%7},{%8,%9},{%0,%1,%2,%3};"
        : "+f"(d[0]), "+f"(d[1]), "+f"(d[2]), "+f"(d[3])
        : "r"(a[0]), "r"(a[1]), "r"(a[2]), "r"(a[3]), "r"(b0), "r"(b1));
}
__device__ __forceinline__ void cp16(float4* dst, const float4* src) {
    unsigned s = (unsigned)__cvta_generic_to_shared(dst);
    asm volatile("cp.async.cg.shared.global [%0],[%1],16;" :: "r"(s), "l"(src));
}
__device__ __forceinline__ void cp_commit() { asm volatile("cp.async.commit_group;"); }
__device__ __forceinline__ void cp_wait1() { asm volatile("cp.async.wait_group 1;"); }
__device__ __forceinline__ void cp_wait0() { asm volatile("cp.async.wait_group 0;"); }

// -------- scratch (device globals; no allocation allowed) --------
__device__ float g_x[(size_t)kN*kL*kC];            // x_embed (n,t,f)
__device__ float g_y[(size_t)kN*kL*kCh];           // y_embed (n,t,e)
__device__ int   g_codes[kN*kTOTJ];
__device__ int   g_sorted[kN*kTOTJ];
__device__ int   g_hist[kN*144*256];
__device__ float g_ret[(size_t)kN*kNH*kL*kCh];     // attention out (n,h,t,e)
__device__ float g_bs[kN*kNH*kL];                  // lse (n,h,t)
// prepacked operands
__device__ float4 g_wyp[4*16*36*64];               // convy weights [cog][sl][r][nn]
__device__ float4 g_wxh[16*36*64];                 // convx weights hi
__device__ float4 g_wxl[16*36*64];                 // convx weights lo
__device__ float  g_xih[(size_t)kN*kL*kCh];        // input hi (NHWC)
__device__ float  g_xil[(size_t)kN*kL*kCh];        // input lo

// ---------------- prepack kernels ----------------
__global__ __launch_bounds__(256) void prep_in_kernel(const float* __restrict__ in)
{
    size_t i = (size_t)blockIdx.x*256 + threadIdx.x;   // f4 index
    float4 v = ((const float4*)in)[i];
    float4 vh, vl;
    vh.x = cvt_tf32(v.x); vl.x = cvt_tf32(v.x - vh.x);
    vh.y = cvt_tf32(v.y); vl.y = cvt_tf32(v.y - vh.y);
    vh.z = cvt_tf32(v.z); vl.z = cvt_tf32(v.z - vh.z);
    vh.w = cvt_tf32(v.w); vl.w = cvt_tf32(v.w - vh.w);
    ((float4*)g_xih)[i] = vh;
    ((float4*)g_xil)[i] = vl;
}

__global__ __launch_bounds__(256) void prep_wx_kernel(const float* __restrict__ w)
{
    int i = blockIdx.x*256 + threadIdx.x;              // < 36864
    int nn = i & 63;
    int r  = (i >> 6) % 36;
    int sl = i / 2304;
    int tap = r >> 2, kq4 = r & 3;
    int cin = sl*16 + 4*kq4;
    const float* wp = &w[(tap*kCh + cin)*kC + nn];
    float f0 = wp[0], f1 = wp[kC], f2 = wp[2*kC], f3 = wp[3*kC];
    float4 vh, vl;
    vh.x = cvt_tf32(f0); vl.x = cvt_tf32(f0 - vh.x);
    vh.y = cvt_tf32(f1); vl.y = cvt_tf32(f1 - vh.y);
    vh.z = cvt_tf32(f2); vl.z = cvt_tf32(f2 - vh.z);
    vh.w = cvt_tf32(f3); vl.w = cvt_tf32(f3 - vh.w);
    g_wxh[i] = vh; g_wxl[i] = vl;
}

__global__ __launch_bounds__(256) void prep_wy_kernel(const float* __restrict__ w)
{
    int i = blockIdx.x*256 + threadIdx.x;              // < 4*36864
    int j = i % 36864;
    int cog = i / 36864;
    int nn = j & 63;
    int r  = (j >> 6) % 36;
    int sl = j / 2304;
    int tap = r >> 2, kq4 = r & 3;
    int cin = sl*16 + 4*kq4;
    const float* wp = &w[(size_t)(tap*kCh + cin)*kCh + cog*64 + nn];
    float4 v;
    v.x = wp[0]; v.y = wp[kCh]; v.z = wp[2*kCh]; v.w = wp[3*kCh];
    g_wyp[i] = v;
}

// ---------------- match conv (x path), 3xTF32 MMA, 512 thr, single buffer --
// block tile: 256 pixels (16x16) x 64 cout. 16 warps, warp M=32, N=32.
__global__ __launch_bounds__(512, 1) void convx_mma_kernel(const float* __restrict__ bias)
{
    extern __shared__ float4 smx[];
    float4* pH = smx;                // 1296
    float4* pL = smx + 1296;         // 1296
    float4* wH = smx + 2592;         // 2376
    float4* wL = smx + 4968;         // 2376

    int n    = blockIdx.x / 36;
    int tile = blockIdx.x % 36;
    int by = (tile / 6) * 16, bx = (tile % 6) * 16;
    int tid = threadIdx.x;
    int wid = tid >> 5, lane = tid & 31;
    int m0w = (wid >> 1) * 32;
    int n0w = (wid & 1) * 32;
    int kq = lane & 3, nq = lane >> 2;

    // hoisted staging offsets (patch: 1296 f4, 3 strides of 512)
    int p_goff[3];
#pragma unroll
    for (int i = 0; i < 3; i++) {
        int lin = tid + i*512;
        p_goff[i] = -1;
        if (lin < 1296) {
            int pos = lin >> 2, kq4 = lin & 3;
            int yy = pos / 18, xx = pos % 18;
            int hh = by + yy - 1, ww = bx + xx - 1;
            if (hh >= 0 && hh < kH && ww >= 0 && ww < kW)
                p_goff[i] = (((n*kH + hh)*kW + ww) << 8) + 4*kq4;
        }
    }
#pragma unroll
    for (int i = 0; i < 3; i++) {
        int lin = tid + i*512;
        if (lin < 1296 && p_goff[i] < 0) {
            float4 z = {0.f,0.f,0.f,0.f};
            pH[lin] = z; pL[lin] = z;
        }
    }

    float acc[8][4];
#pragma unroll
    for (int i = 0; i < 8; i++)
#pragma unroll
        for (int j = 0; j < 4; j++) acc[i][j] = 0.f;

    int pb[4];
#pragma unroll
    for (int t = 0; t < 4; t++) {
        int m = m0w + t*8 + nq;
        pb[t] = (m >> 4)*18 + (m & 15);
    }

    for (int sl = 0; sl < 16; sl++) {
        // stage slice (cp.async, single buffer)
#pragma unroll
        for (int i = 0; i < 3; i++) {
            int lin = tid + i*512;
            if (lin < 1296 && p_goff[i] >= 0) {
                cp16(&pH[lin], (const float4*)&g_xih[p_goff[i] + sl*16]);
                cp16(&pL[lin], (const float4*)&g_xil[p_goff[i] + sl*16]);
            }
        }
#pragma unroll
        for (int i = 0; i < 5; i++) {
            int lin = tid + i*512;
            if (lin < 2304) {
                int didx = (lin >> 6)*WNY + (lin & 63);
                cp16(&wH[didx], &g_wxh[sl*2304 + lin]);
                cp16(&wL[didx], &g_wxl[sl*2304 + lin]);
            }
        }
        cp_commit(); cp_wait0();
        __syncthreads();

#pragma unroll
        for (int tap = 0; tap < 9; tap++) {
            int posoff = (tap/3)*18 + (tap%3);
            float4 ah[4], al[4];
#pragma unroll
            for (int t = 0; t < 4; t++) {
                int o = (pb[t] + posoff)*4 + kq;
                ah[t] = pH[o]; al[t] = pL[o];
            }
            unsigned Ah0[2][4], Ah1[2][4], Al0[2][4], Al1[2][4];
#pragma unroll
            for (int mt = 0; mt < 2; mt++) {
                Ah0[mt][0] = __float_as_uint(ah[2*mt].x);
                Ah0[mt][1] = __float_as_uint(ah[2*mt+1].x);
                Ah0[mt][2] = __float_as_uint(ah[2*mt].y);
                Ah0[mt][3] = __float_as_uint(ah[2*mt+1].y);
                Ah1[mt][0] = __float_as_uint(ah[2*mt].z);
                Ah1[mt][1] = __float_as_uint(ah[2*mt+1].z);
                Ah1[mt][2] = __float_as_uint(ah[2*mt].w);
                Ah1[mt][3] = __float_as_uint(ah[2*mt+1].w);
                Al0[mt][0] = __float_as_uint(al[2*mt].x);
                Al0[mt][1] = __float_as_uint(al[2*mt+1].x);
                Al0[mt][2] = __float_as_uint(al[2*mt].y);
                Al0[mt][3] = __float_as_uint(al[2*mt+1].y);
                Al1[mt][0] = __float_as_uint(al[2*mt].z);
                Al1[mt][1] = __float_as_uint(al[2*mt+1].z);
                Al1[mt][2] = __float_as_uint(al[2*mt].w);
                Al1[mt][3] = __float_as_uint(al[2*mt+1].w);
            }
            int wr = (tap*4 + kq)*WNY + n0w + nq;
#pragma unroll
            for (int nt = 0; nt < 4; nt++) {
                float4 bh = wH[wr + nt*8];
                float4 bl = wL[wr + nt*8];
                unsigned bhx = __float_as_uint(bh.x), bhy = __float_as_uint(bh.y);
                unsigned bhz = __float_as_uint(bh.z), bhw = __float_as_uint(bh.w);
                unsigned blx = __float_as_uint(bl.x), bly = __float_as_uint(bl.y);
                unsigned blz = __float_as_uint(bl.z), blw = __float_as_uint(bl.w);
#pragma unroll
                for (int mt = 0; mt < 2; mt++) {
                    float* a = acc[mt*4 + nt];
                    mma_tf32(a, Ah0[mt], bhx, bhy);
                    mma_tf32(a, Ah1[mt], bhz, bhw);
                    mma_tf32(a, Ah0[mt], blx, bly);
                    mma_tf32(a, Ah1[mt], blz, blw);
                    mma_tf32(a, Al0[mt], bhx, bhy);
                    mma_tf32(a, Al1[mt], bhz, bhw);
                }
            }
        }
        __syncthreads();
    }

    // epilogue: scatter to g_x embed layout (p = f*144 + t/64, c = t%64)
#pragma unroll
    for (int mt = 0; mt < 2; mt++) {
#pragma unroll
        for (int half = 0; half < 2; half++) {
            int m = m0w + mt*16 + half*8 + nq;
            int py = by + (m >> 4), px = bx + (m & 15);
            int p = py*kW + px;
            int f = p / 144, pm = p % 144;
#pragma unroll
            for (int nt = 0; nt < 4; nt++) {
                int c = n0w + nt*8 + 2*kq;
                float v0 = acc[mt*4 + nt][half*2]     + bias[c];
                float v1 = acc[mt*4 + nt][half*2 + 1] + bias[c+1];
                g_x[((size_t)n*kL + pm*64 + c    )*kC + f] = v0;
                g_x[((size_t)n*kL + pm*64 + c + 1)*kC + f] = v1;
            }
        }
    }
}

// ---------------- asm conv (y path), tf32 MMA, 512 thr, double buffer ------
// block tile: 256 pixels (16x16) x 64 cout. 16 warps, warp M=32, N=32.
__global__ __launch_bounds__(512, 1) void convy_mma_kernel(
    const float* __restrict__ in, const float* __restrict__ bias)
{
    extern __shared__ float4 smy[];
    float4* pB[2] = {smy,        smy + 1296};
    float4* wB[2] = {smy + 2592, smy + 2592 + 2376};

    int n    = blockIdx.x / 36;
    int tile = blockIdx.x % 36;
    int by = (tile / 6) * 16, bx = (tile % 6) * 16;
    int cog = blockIdx.y;
    int co0 = cog * 64;
    int tid = threadIdx.x;
    int wid = tid >> 5, lane = tid & 31;
    int m0w = (wid >> 1) * 32;
    int n0w = (wid & 1) * 32;
    int kq = lane & 3;
    int nq = lane >> 2;

    int p_goff[3];
#pragma unroll
    for (int i = 0; i < 3; i++) {
        int lin = tid + i*512;
        p_goff[i] = -1;
        if (lin < 1296) {
            int pos = lin >> 2, kq4 = lin & 3;
            int yy = pos / 18, xx = pos % 18;
            int hh = by + yy - 1, ww = bx + xx - 1;
            if (hh >= 0 && hh < kH && ww >= 0 && ww < kW)
                p_goff[i] = (((n*kH + hh)*kW + ww) << 8) + 4*kq4;
        }
    }
#pragma unroll
    for (int i = 0; i < 3; i++) {
        int lin = tid + i*512;
        if (lin < 1296 && p_goff[i] < 0) {
            float4 z = {0.f,0.f,0.f,0.f};
            pB[0][lin] = z; pB[1][lin] = z;
        }
    }

    float acc[8][4];
#pragma unroll
    for (int i = 0; i < 8; i++)
#pragma unroll
        for (int j = 0; j < 4; j++) acc[i][j] = 0.f;

    int pb[4];
#pragma unroll
    for (int t = 0; t < 4; t++) {
        int m = m0w + t*8 + nq;
        pb[t] = (m >> 4)*18 + (m & 15);
    }

    const float4* wsrc = &g_wyp[cog*36864];

    auto stage = [&](int sl, int buf) {
#pragma unroll
        for (int i = 0; i < 3; i++) {
            int lin = tid + i*512;
            if (lin < 1296 && p_goff[i] >= 0)
                cp16(&pB[buf][lin], (const float4*)&in[p_goff[i] + sl*16]);
        }
#pragma unroll
        for (int i = 0; i < 5; i++) {
            int lin = tid + i*512;
            if (lin < 2304)
                cp16(&wB[buf][(lin >> 6)*WNY + (lin & 63)], &wsrc[sl*2304 + lin]);
        }
    };

    stage(0, 0); cp_commit();
    for (int sl = 0; sl < 16; sl++) {
        int buf = sl & 1;
        if (sl < 15) { stage(sl + 1, buf ^ 1); cp_commit(); cp_wait1(); }
        else cp_wait0();
        __syncthreads();
        float4* patch4 = pB[buf];
        float4* wtp4   = wB[buf];

#pragma unroll
        for (int tap = 0; tap < 9; tap++) {
            int posoff = (tap/3)*18 + (tap%3);
            float4 a4[4];
#pragma unroll
            for (int t = 0; t < 4; t++)
                a4[t] = patch4[(pb[t] + posoff)*4 + kq];
            unsigned A0[2][4], A1[2][4];
#pragma unroll
            for (int mt = 0; mt < 2; mt++) {
                A0[mt][0] = __float_as_uint(a4[2*mt].x);
                A0[mt][1] = __float_as_uint(a4[2*mt+1].x);
                A0[mt][2] = __float_as_uint(a4[2*mt].y);
                A0[mt][3] = __float_as_uint(a4[2*mt+1].y);
                A1[mt][0] = __float_as_uint(a4[2*mt].z);
                A1[mt][1] = __float_as_uint(a4[2*mt+1].z);
                A1[mt][2] = __float_as_uint(a4[2*mt].w);
                A1[mt][3] = __float_as_uint(a4[2*mt+1].w);
            }
            int wr = (tap*4 + kq)*WNY + n0w + nq;
#pragma unroll
            for (int nt = 0; nt < 4; nt++) {
                float4 b4 = wtp4[wr + nt*8];
                unsigned bx0 = __float_as_uint(b4.x), by0 = __float_as_uint(b4.y);
                unsigned bz0 = __float_as_uint(b4.z), bw0 = __float_as_uint(b4.w);
#pragma unroll
                for (int mt = 0; mt < 2; mt++) {
                    mma_tf32(acc[mt*4 + nt], A0[mt], bx0, by0);
                    mma_tf32(acc[mt*4 + nt], A1[mt], bz0, bw0);
                }
            }
        }
        __syncthreads();
    }

#pragma unroll
    for (int mt = 0; mt < 2; mt++) {
#pragma unroll
        for (int half = 0; half < 2; half++) {
            int m = m0w + mt*16 + half*8 + nq;
            int py = by + (m >> 4), px = bx + (m & 15);
            int p = py*kW + px;
            int e = p / 36, pm = p % 36;
#pragma unroll
            for (int nt = 0; nt < 4; nt++) {
                int c = co0 + n0w + nt*8 + 2*kq;
                float v0 = acc[mt*4 + nt][half*2]     + bias[c];
                float v1 = acc[mt*4 + nt][half*2 + 1] + bias[c+1];
                g_y[((size_t)n*kL + pm*256 + c    )*kCh + e] = v0;
                g_y[((size_t)n*kL + pm*256 + c + 1)*kCh + e] = v1;
            }
        }
    }
}

// ---------------- LSH hashing ----------------
__global__ __launch_bounds__(256) void hash_kernel(const float* __restrict__ rot)
{
    __shared__ float Rsm[8192];
    __shared__ float xrow[8][64];
    int tid = threadIdx.x;
    for (int lin = tid; lin < 8192; lin += 256) Rsm[lin] = rot[lin];
    int wid = tid >> 5, lane = tid & 31;
    int idx = blockIdx.x*8 + wid;
    int n = idx / kL, t = idx % kL;
    const float* xr = &g_x[((size_t)n*kL + t)*kC];
    xrow[wid][lane]      = xr[lane];
    xrow[wid][lane + 32] = xr[lane + 32];
    __syncthreads();
#pragma unroll
    for (int h = 0; h < 4; h++) {
        float s = 0.f;
#pragma unroll
        for (int f = 0; f < 64; f++) s += xrow[wid][f] * Rsm[f*128 + h*32 + lane];
        float bv; int bi;
        if (s >= -s) { bv = s;  bi = lane; }
        else         { bv = -s; bi = lane + 32; }
#pragma unroll
        for (int off = 16; off > 0; off >>= 1) {
            float ov = __shfl_xor_sync(0xffffffffu, bv, off);
            int   oi = __shfl_xor_sync(0xffffffffu, bi, off);
            if (ov > bv || (ov == bv && oi < bi)) { bv = ov; bi = oi; }
        }
        if (lane == 0) g_codes[n*kTOTJ + h*kL + t] = bi + h*kHB;
    }
}

// ---------------- stable counting sort (argsort) ----------------
__global__ __launch_bounds__(256) void sortA_kernel()
{
    __shared__ int hist[256];
    int b = blockIdx.x; int n = b / 144, blk = b % 144; int tid = threadIdx.x;
    hist[tid] = 0; __syncthreads();
    int code = g_codes[n*kTOTJ + blk*256 + tid];
    atomicAdd(&hist[code], 1);
    __syncthreads();
    g_hist[(n*144 + blk)*256 + tid] = hist[tid];
}

__global__ __launch_bounds__(256) void sortBC_kernel()
{
    __shared__ int scanbuf[256];
    __shared__ int comb[256];
    __shared__ int cs[256];
    int b = blockIdx.x; int n = b / 144, blk = b % 144; int v = threadIdx.x;

    int tot = 0, off = 0;
    const int* hb = &g_hist[n*144*256 + v];
    for (int bb = 0; bb < 144; bb++) {
        int hv = hb[bb*256];
        tot += hv;
        if (bb < blk) off += hv;
    }
    scanbuf[v] = tot;
    __syncthreads();
    for (int d = 1; d < 256; d <<= 1) {
        int y = (v >= d) ? scanbuf[v - d] : 0;
        __syncthreads();
        scanbuf[v] += y;
        __syncthreads();
    }
    comb[v] = (scanbuf[v] - tot) + off;
    int c = g_codes[n*kTOTJ + blk*256 + v];
    cs[v] = c;
    __syncthreads();
    int rank = 0;
    for (int j = 0; j < v; j++) rank += (cs[j] == c);
    g_sorted[n*kTOTJ + comb[c] + rank] = blk*256 + v;
}

// ---------------- fused chunk attention (tf32 MMA, no global scratch) ------
__global__ __launch_bounds__(ATHR, 1) void attn_kernel()
{
    extern __shared__ float sm[];
    float* Qr  = sm;                      // 144*QRS
    float* Kc  = Qr + 144*QRS;            // 64*KCS
    float* Vsm = Kc + 64*KCS;             // 72*VSTR
    float* Psm = Vsm + 72*VSTR;           // 144*PSTR
    float* m_r = Psm + 144*PSTR;          // 144
    float* rowsumA = m_r + 144;           // 144
    float* rowsumB = rowsumA + 144;       // 144
    int* tIdx = (int*)(rowsumB + 144);    // 432

    int g = blockIdx.x;
    int n = g >> 8, k = g & 255;
    int h = k >> 6, kl = k & 63;
    int tid = threadIdx.x;
    int wid = tid >> 5, lane = tid & 31;
    int kq = lane & 3, nq = lane >> 2;

    for (int j = tid; j < kJW; j += ATHR) {
        int cchunk = j / kCHK, i = j % kCHK;
        int skl = (cchunk == 0) ? kl : (cchunk == 1) ? ((kl + 63) & 63) : ((kl + 1) & 63);
        int s = (h*64 + skl)*kCHK + i;
        tIdx[j] = g_sorted[n*kTOTJ + s] % kL;
    }
    for (int i = tid; i < kCHK; i += ATHR) { rowsumA[i] = 0.f; rowsumB[i] = 0.f; }
    __syncthreads();

    {
#pragma unroll
        for (int rr = 0; rr < 8; rr++) {
            int r = wid*8 + rr;
            const float* xr = &g_x[((size_t)n*kL + tIdx[r])*kC];
            float a = xr[lane], b = xr[lane + 32];
            Qr[r*QRS + lane] = a;
            Qr[r*QRS + lane + 32] = b;
            float ss = a*a + b*b;
#pragma unroll
            for (int off = 16; off > 0; off >>= 1)
                ss += __shfl_xor_sync(0xffffffffu, ss, off);
            if (lane == 0) m_r[r] = ss * rsqrtf(fmaxf(ss, 5e-5f));
        }
    }
    __syncthreads();

    int wq = wid % 9;
    int halfq = wid / 9;
    int m0 = wq * 16;
    float mA = m_r[m0 + nq], mB = m_r[m0 + 8 + nq];

    float Oacc[16][4];
#pragma unroll
    for (int i = 0; i < 16; i++)
#pragma unroll
        for (int j = 0; j < 4; j++) Oacc[i][j] = 0.f;

    for (int jc = 0; jc < 6; jc++) {
        int j0 = jc*72;
        if (wid < 9) {
            int col = wid*8 + (lane >> 2);
            int fs = (lane & 3) * 16;
            const float4* xr = (const float4*)&g_x[((size_t)n*kL + tIdx[j0 + col])*kC + fs];
            float4 v0 = xr[0], v1 = xr[1], v2 = xr[2], v3 = xr[3];
            float ss = v0.x*v0.x + v0.y*v0.y + v0.z*v0.z + v0.w*v0.w
                     + v1.x*v1.x + v1.y*v1.y + v1.z*v1.z + v1.w*v1.w
                     + v2.x*v2.x + v2.y*v2.y + v2.z*v2.z + v2.w*v2.w
                     + v3.x*v3.x + v3.y*v3.y + v3.z*v3.z + v3.w*v3.w;
            ss += __shfl_xor_sync(0xffffffffu, ss, 1);
            ss += __shfl_xor_sync(0xffffffffu, ss, 2);
            float r = rsqrtf(fmaxf(ss, 5e-5f));
            float* kcb = &Kc[fs*KCS + col];
            kcb[0*KCS] = v0.x*r; kcb[1*KCS] = v0.y*r;
            kcb[2*KCS] = v0.z*r; kcb[3*KCS] = v0.w*r;
            kcb[4*KCS] = v1.x*r; kcb[5*KCS] = v1.y*r;
            kcb[6*KCS] = v1.z*r; kcb[7*KCS] = v1.w*r;
            kcb[8*KCS] = v2.x*r; kcb[9*KCS] = v2.y*r;
            kcb[10*KCS] = v2.z*r; kcb[11*KCS] = v2.w*r;
            kcb[12*KCS] = v3.x*r; kcb[13*KCS] = v3.y*r;
            kcb[14*KCS] = v3.z*r; kcb[15*KCS] = v3.w*r;
        } else {
            int w2 = wid - 9;
#pragma unroll
            for (int rr = 0; rr < 8; rr++) {
                int row = w2*8 + rr;
                const float4* yr = (const float4*)&g_y[((size_t)n*kL + tIdx[j0 + row])*kCh];
                *(float4*)&Vsm[row*VSTR + lane*4]      = yr[lane];
                *(float4*)&Vsm[row*VSTR + (lane+32)*4] = yr[lane + 32];
            }
        }
        __syncthreads();

        {
            unsigned Af[8][4];
#pragma unroll
            for (int ks = 0; ks < 8; ks++) {
                const float* q0 = &Qr[(m0 + nq)*QRS + ks*8 + kq];
                const float* q1 = &Qr[(m0 + 8 + nq)*QRS + ks*8 + kq];
                Af[ks][0] = __float_as_uint(q0[0]);
                Af[ks][1] = __float_as_uint(q1[0]);
                Af[ks][2] = __float_as_uint(q0[4]);
                Af[ks][3] = __float_as_uint(q1[4]);
            }
            float s0 = 0.f, s1 = 0.f;
            int ntBeg = halfq ? 5 : 0;
            int ntEnd = halfq ? 9 : 5;
            for (int nt = ntBeg; nt < ntEnd; nt++) {
                float acc[4] = {0.f, 0.f, 0.f, 0.f};
#pragma unroll
                for (int ks = 0; ks < 8; ks++) {
                    unsigned b0 = __float_as_uint(Kc[(ks*8 + kq)*KCS + nt*8 + nq]);
                    unsigned b1 = __float_as_uint(Kc[(ks*8 + 4 + kq)*KCS + nt*8 + nq]);
                    mma_tf32(acc, Af[ks], b0, b1);
                }
                float e0 = __expf(acc[0] - mA), e1 = __expf(acc[1] - mA);
                float e2 = __expf(acc[2] - mB), e3 = __expf(acc[3] - mB);
                s0 += e0 + e1; s1 += e2 + e3;
                float2 pA; pA.x = e0; pA.y = e1;
                float2 pB2; pB2.x = e2; pB2.y = e3;
                *(float2*)&Psm[(m0 + nq)*PSTR + nt*8 + 2*kq] = pA;
                *(float2*)&Psm[(m0 + 8 + nq)*PSTR + nt*8 + 2*kq] = pB2;
            }
            s0 += __shfl_xor_sync(0xffffffffu, s0, 1);
            s0 += __shfl_xor_sync(0xffffffffu, s0, 2);
            s1 += __shfl_xor_sync(0xffffffffu, s1, 1);
            s1 += __shfl_xor_sync(0xffffffffu, s1, 2);
            if (kq == 0) {
                float* rs = halfq ? rowsumB : rowsumA;
                rs[m0 + nq] += s0;
                rs[m0 + 8 + nq] += s1;
            }
        }
        __syncthreads();

        {
            int n0 = halfq * 128;
#pragma unroll
            for (int ks = 0; ks < 9; ks++) {
                unsigned A[4];
                const float* p0 = &Psm[(m0 + nq)*PSTR + ks*8 + kq];
                const float* p1 = &Psm[(m0 + 8 + nq)*PSTR + ks*8 + kq];
                A[0] = __float_as_uint(p0[0]);
                A[1] = __float_as_uint(p1[0]);
                A[2] = __float_as_uint(p0[4]);
                A[3] = __float_as_uint(p1[4]);
                const float* vb0 = &Vsm[(ks*8 + kq)*VSTR + n0 + nq];
                const float* vb1 = &Vsm[(ks*8 + 4 + kq)*VSTR + n0 + nq];
#pragma unroll
                for (int nt = 0; nt < 16; nt++) {
                    unsigned b0 = __float_as_uint(vb0[nt*8]);
                    unsigned b1 = __float_as_uint(vb1[nt*8]);
                    mma_tf32(Oacc[nt], A, b0, b1);
                }
            }
        }
        __syncthreads();
    }

    {
        int n0 = halfq * 128;
        int rA = m0 + nq, rB = rA + 8;
        float sumA = rowsumA[rA] + rowsumB[rA];
        float sumB = rowsumA[rB] + rowsumB[rB];
        float invA = 1.f / sumA;
        float invB = 1.f / sumB;
        size_t baseA = ((size_t)(n*4 + h)*kL + tIdx[rA])*kCh;
        size_t baseB = ((size_t)(n*4 + h)*kL + tIdx[rB])*kCh;
#pragma unroll
        for (int nt = 0; nt < 16; nt++) {
            int cA = n0 + nt*8 + 2*kq;
            float2 oA; oA.x = Oacc[nt][0]*invA; oA.y = Oacc[nt][1]*invA;
            float2 oB; oB.x = Oacc[nt][2]*invB; oB.y = Oacc[nt][3]*invB;
            *(float2*)&g_ret[baseA + cA] = oA;
            *(float2*)&g_ret[baseB + cA] = oB;
        }
        if (wid < 9 && lane < 16) {
            int row = wid*16 + lane;
            float s = rowsumA[row] + rowsumB[row];
            g_bs[(size_t)(n*4 + h)*kL + tIdx[row]] = m_r[row] + __logf(s);
        }
    }
}

// ---------------- head combine + residual + output layout ----------------
__global__ __launch_bounds__(256) void combine_kernel(
    const float* __restrict__ in, float* __restrict__ out)
{
    __shared__ float accs[256*33];
    __shared__ float probs[4*256];
    int n = blockIdx.x / 36, q = blockIdx.x % 36;
    int e0 = blockIdx.y * 32;
    int tid = threadIdx.x;

    {
        int t = q*256 + tid;
        float b0 = g_bs[(size_t)(n*4 + 0)*kL + t];
        float b1 = g_bs[(size_t)(n*4 + 1)*kL + t];
        float b2 = g_bs[(size_t)(n*4 + 2)*kL + t];
        float b3 = g_bs[(size_t)(n*4 + 3)*kL + t];
        float m = fmaxf(fmaxf(b0, b1), fmaxf(b2, b3));
        float x0 = __expf(b0 - m), x1 = __expf(b1 - m);
        float x2 = __expf(b2 - m), x3 = __expf(b3 - m);
        float sinv = 1.f / (x0 + x1 + x2 + x3);
        probs[0*256 + tid] = x0*sinv; probs[1*256 + tid] = x1*sinv;
        probs[2*256 + tid] = x2*sinv; probs[3*256 + tid] = x3*sinv;
    }
    for (int lin = tid; lin < 256*33; lin += 256) accs[lin] = 0.f;
    __syncthreads();

    for (int h = 0; h < 4; h++) {
        for (int lin = tid; lin < 256*32; lin += 256) {
            int cc = lin >> 5, e = lin & 31;
            float v = g_ret[((size_t)(n*4 + h)*kL + q*256 + cc)*kCh + e0 + e];
            accs[cc*33 + e] += probs[h*256 + cc] * v;
        }
    }
    __syncthreads();

    for (int lin = tid; lin < 32*256; lin += 256) {
        int e = lin >> 8, c = lin & 255;
        int p = (e0 + e)*36 + q;
        size_t oi = ((size_t)n*kL + p)*kCh + c;
        out[oi] = 0.1f*accs[c*33 + e] + in[oi];
    }
}

// ---------------- launch ----------------
extern "C" void kernel_launch(void* const* d_in, const int* in_sizes, int n_in,
                              void* d_out, int out_size)
{
    const float* input     = (const float*)d_in[0];
    const float* w_match   = (const float*)d_in[1];
    const float* b_match   = (const float*)d_in[2];
    const float* w_asm     = (const float*)d_in[3];
    const float* b_asm     = (const float*)d_in[4];
    const float* rotations = (const float*)d_in[5];
    float* out = (float*)d_out;

    const int CONVX_SMEM = 7344 * 16;                                   // 117504
    const int CONVY_SMEM = (2592 + 4752) * 16;                          // 117504
    const int ATT_SMEM   = (144*QRS + 64*KCS + 72*VSTR + 144*PSTR + 144*3 + 432) * 4;

    cudaFuncSetAttribute(convx_mma_kernel, cudaFuncAttributeMaxDynamicSharedMemorySize, CONVX_SMEM);
    cudaFuncSetAttribute(convy_mma_kernel, cudaFuncAttributeMaxDynamicSharedMemorySize, CONVY_SMEM);
    cudaFuncSetAttribute(attn_kernel,      cudaFuncAttributeMaxDynamicSharedMemorySize, ATT_SMEM);

    prep_in_kernel<<<kN*kL*64/256, 256>>>(input);
    prep_wx_kernel<<<144, 256>>>(w_match);
    prep_wy_kernel<<<576, 256>>>(w_asm);
    // convy in ncu capture slot 4
    convy_mma_kernel<<<dim3(kN*36, 4), 512, CONVY_SMEM>>>(input, b_asm);
    convx_mma_kernel<<<kN*36, 512, CONVX_SMEM>>>(b_match);
    hash_kernel<<<kN*kL/8, 256>>>(rotations);
    sortA_kernel<<<kN*144, 256>>>();
    sortBC_kernel<<<kN*144, 256>>>();
    attn_kernel<<<kN*256, ATHR, ATT_SMEM>>>();
    combine_kernel<<<dim3(kN*36, 8), 256>>>(input, out);
}

// round 10
// speedup vs baseline: 1.0031x; 1.0007x over previous
#include <cuda_runtime.h>
#include <math.h>

// Problem constants
#define kN 4
#define kH 96
#define kW 96
#define kCh 256
#define kC 64
#define kL 9216          // 96*96
#define kNH 4
#define kHB 64           // hash buckets
#define kCHK 144
#define kTOTJ 36864      // kNH*kL
#define kJW 432          // 3*kCHK

// smem strides (attn)
#define QRS 68
#define KCS 76
#define VSTR 260
#define PSTR 76
#define ATHR 576

// conv packed layouts
#define WNY 66           // float4 row stride for packed weights in smem

__device__ __forceinline__ float cvt_tf32(float f) {
    unsigned r; asm("cvt.rna.tf32.f32 %0,%1;" : "=r"(r) : "f"(f));
    return __uint_as_float(r);
}
__device__ __forceinline__ float trunc13(float f) {
    return __uint_as_float(__float_as_uint(f) & 0xFFFFE000u);
}
__device__ __forceinline__ void mma_tf32(float* d, const unsigned* a, unsigned b0, unsigned b1) {
    asm("mma.sync.aligned.m16n8k8.row.col.f32.tf32.tf32.f32 "
        "{%0,%1,%2,%3},{%4,%5,%6,%7},{%8,%9},{%0,%1,%2,%3};"
        : "+f"(d[0]), "+f"(d[1]), "+f"(d[2]), "+f"(d[3])
        : "r"(a[0]), "r"(a[1]), "r"(a[2]), "r"(a[3]), "r"(b0), "r"(b1));
}
__device__ __forceinline__ void cp16(float4* dst, const float4* src) {
    unsigned s = (unsigned)__cvta_generic_to_shared(dst);
    asm volatile("cp.async.cg.shared.global [%0],[%1],16;" :: "r"(s), "l"(src));
}
__device__ __forceinline__ void cp_commit() { asm volatile("cp.async.commit_group;"); }
__device__ __forceinline__ void cp_wait1() { asm volatile("cp.async.wait_group 1;"); }
__device__ __forceinline__ void cp_wait0() { asm volatile("cp.async.wait_group 0;"); }

// -------- scratch (device globals; no allocation allowed) --------
__device__ float g_x[(size_t)kN*kL*kC];            // x_embed (n,t,f)
__device__ float g_y[(size_t)kN*kL*kCh];           // y_embed (n,t,e)
__device__ int   g_codes[kN*kTOTJ];
__device__ int   g_sorted[kN*kTOTJ];
__device__ int   g_hist[kN*144*256];
__device__ float g_ret[(size_t)kN*kNH*kL*kCh];     // attention out (n,h,t,e)
__device__ float g_bs[kN*kNH*kL];                  // lse (n,h,t)
// prepacked operands
__device__ float4 g_wyp[4*16*36*64];               // convy weights [cog][sl][r][nn]
__device__ float4 g_wxh[16*36*64];                 // convx weights hi
__device__ float4 g_wxl[16*36*64];                 // convx weights lo
__device__ float  g_xil[(size_t)kN*kL*kCh];        // input lo = v - trunc13(v)

// ---------------- prepack kernels ----------------
__global__ __launch_bounds__(256) void prep_in_kernel(const float* __restrict__ in)
{
    size_t i = (size_t)blockIdx.x*256 + threadIdx.x;   // f4 index
    float4 v = ((const float4*)in)[i];
    float4 vl;
    vl.x = v.x - trunc13(v.x);
    vl.y = v.y - trunc13(v.y);
    vl.z = v.z - trunc13(v.z);
    vl.w = v.w - trunc13(v.w);
    ((float4*)g_xil)[i] = vl;
}

__global__ __launch_bounds__(256) void prep_wx_kernel(const float* __restrict__ w)
{
    int i = blockIdx.x*256 + threadIdx.x;              // < 36864
    int nn = i & 63;
    int r  = (i >> 6) % 36;
    int sl = i / 2304;
    int tap = r >> 2, kq4 = r & 3;
    int cin = sl*16 + 4*kq4;
    const float* wp = &w[(tap*kCh + cin)*kC + nn];
    float f0 = wp[0], f1 = wp[kC], f2 = wp[2*kC], f3 = wp[3*kC];
    float4 vh, vl;
    vh.x = cvt_tf32(f0); vl.x = f0 - vh.x;
    vh.y = cvt_tf32(f1); vl.y = f1 - vh.y;
    vh.z = cvt_tf32(f2); vl.z = f2 - vh.z;
    vh.w = cvt_tf32(f3); vl.w = f3 - vh.w;
    g_wxh[i] = vh; g_wxl[i] = vl;
}

__global__ __launch_bounds__(256) void prep_wy_kernel(const float* __restrict__ w)
{
    int i = blockIdx.x*256 + threadIdx.x;              // < 4*36864
    int j = i % 36864;
    int cog = i / 36864;
    int nn = j & 63;
    int r  = (j >> 6) % 36;
    int sl = j / 2304;
    int tap = r >> 2, kq4 = r & 3;
    int cin = sl*16 + 4*kq4;
    const float* wp = &w[(size_t)(tap*kCh + cin)*kCh + cog*64 + nn];
    float4 v;
    v.x = wp[0]; v.y = wp[kCh]; v.z = wp[2*kCh]; v.w = wp[3*kCh];
    g_wyp[i] = v;
}

// ---------------- match conv (x path), 3xTF32 MMA, cp.async double-buffer --
// block tile: 128 pixels (8x16) x 64 cout. warps 4(M)x2(N). K sliced 16 cin.
// hi operand staged raw from `in` (tensor core truncates low 13 bits);
// lo operand from g_xil (exact residual).
__global__ __launch_bounds__(256, 1) void convx_mma_kernel(
    const float* __restrict__ in, const float* __restrict__ bias)
{
    extern __shared__ float4 smx[];
    float4* pH[2] = {smx,        smx + 720};
    float4* pL[2] = {smx + 1440, smx + 2160};
    float4* wH[2] = {smx + 2880, smx + 2880 + 2376};
    float4* wL[2] = {smx + 7632, smx + 7632 + 2376};

    int n    = blockIdx.x / 72;
    int tile = blockIdx.x % 72;
    int by = (tile / 6) * 8, bx = (tile % 6) * 16;
    int tid = threadIdx.x;
    int wid = tid >> 5, lane = tid & 31;
    int m0w = (wid >> 1) * 32;
    int n0w = (wid & 1) * 32;
    int kq = lane & 3, nq = lane >> 2;

    int p_goff[3];
#pragma unroll
    for (int i = 0; i < 3; i++) {
        int lin = tid + i*256;
        p_goff[i] = -1;
        if (lin < 720) {
            int pos = lin >> 2, kq4 = lin & 3;
            int yy = pos / 18, xx = pos % 18;
            int hh = by + yy - 1, ww = bx + xx - 1;
            if (hh >= 0 && hh < kH && ww >= 0 && ww < kW)
                p_goff[i] = (((n*kH + hh)*kW + ww) << 8) + 4*kq4;
        }
    }
#pragma unroll
    for (int i = 0; i < 3; i++) {
        int lin = tid + i*256;
        if (lin < 720 && p_goff[i] < 0) {
            float4 z = {0.f,0.f,0.f,0.f};
            pH[0][lin] = z; pH[1][lin] = z;
            pL[0][lin] = z; pL[1][lin] = z;
        }
    }

    float acc[8][4];
#pragma unroll
    for (int i = 0; i < 8; i++)
#pragma unroll
        for (int j = 0; j < 4; j++) acc[i][j] = 0.f;

    int pb[4];
#pragma unroll
    for (int t = 0; t < 4; t++) {
        int m = m0w + t*8 + nq;
        pb[t] = (m >> 4)*18 + (m & 15);
    }

    auto stage = [&](int sl, int buf) {
#pragma unroll
        for (int i = 0; i < 3; i++) {
            int lin = tid + i*256;
            if (lin < 720 && p_goff[i] >= 0) {
                cp16(&pH[buf][lin], (const float4*)&in[p_goff[i] + sl*16]);
                cp16(&pL[buf][lin], (const float4*)&g_xil[p_goff[i] + sl*16]);
            }
        }
#pragma unroll
        for (int i = 0; i < 9; i++) {
            int lin = tid + i*256;
            int r = lin >> 6, nn = lin & 63;
            int didx = r*WNY + nn;
            int sidx = sl*2304 + lin;
            cp16(&wH[buf][didx], &g_wxh[sidx]);
            cp16(&wL[buf][didx], &g_wxl[sidx]);
        }
    };

    stage(0, 0); cp_commit();
    for (int sl = 0; sl < 16; sl++) {
        int buf = sl & 1;
        if (sl < 15) { stage(sl + 1, buf ^ 1); cp_commit(); cp_wait1(); }
        else cp_wait0();
        __syncthreads();
        float4* p4h = pH[buf]; float4* p4l = pL[buf];
        float4* w4h = wH[buf]; float4* w4l = wL[buf];

#pragma unroll
        for (int tap = 0; tap < 9; tap++) {
            int posoff = (tap/3)*18 + (tap%3);
            float4 ah[4], al[4];
#pragma unroll
            for (int t = 0; t < 4; t++) {
                int o = (pb[t] + posoff)*4 + kq;
                ah[t] = p4h[o]; al[t] = p4l[o];
            }
            unsigned Ah00[4] = {__float_as_uint(ah[0].x), __float_as_uint(ah[1].x),
                                __float_as_uint(ah[0].y), __float_as_uint(ah[1].y)};
            unsigned Ah01[4] = {__float_as_uint(ah[0].z), __float_as_uint(ah[1].z),
                                __float_as_uint(ah[0].w), __float_as_uint(ah[1].w)};
            unsigned Ah10[4] = {__float_as_uint(ah[2].x), __float_as_uint(ah[3].x),
                                __float_as_uint(ah[2].y), __float_as_uint(ah[3].y)};
            unsigned Ah11[4] = {__float_as_uint(ah[2].z), __float_as_uint(ah[3].z),
                                __float_as_uint(ah[2].w), __float_as_uint(ah[3].w)};
            unsigned Al00[4] = {__float_as_uint(al[0].x), __float_as_uint(al[1].x),
                                __float_as_uint(al[0].y), __float_as_uint(al[1].y)};
            unsigned Al01[4] = {__float_as_uint(al[0].z), __float_as_uint(al[1].z),
                                __float_as_uint(al[0].w), __float_as_uint(al[1].w)};
            unsigned Al10[4] = {__float_as_uint(al[2].x), __float_as_uint(al[3].x),
                                __float_as_uint(al[2].y), __float_as_uint(al[3].y)};
            unsigned Al11[4] = {__float_as_uint(al[2].z), __float_as_uint(al[3].z),
                                __float_as_uint(al[2].w), __float_as_uint(al[3].w)};
            int wr = (tap*4 + kq)*WNY + n0w + nq;
#pragma unroll
            for (int nt = 0; nt < 4; nt++) {
                float4 bh = w4h[wr + nt*8];
                float4 bl = w4l[wr + nt*8];
                unsigned bhx = __float_as_uint(bh.x), bhy = __float_as_uint(bh.y);
                unsigned bhz = __float_as_uint(bh.z), bhw = __float_as_uint(bh.w);
                unsigned blx = __float_as_uint(bl.x), bly = __float_as_uint(bl.y);
                unsigned blz = __float_as_uint(bl.z), blw = __float_as_uint(bl.w);
                mma_tf32(acc[nt], Ah00, bhx, bhy);
                mma_tf32(acc[nt], Ah01, bhz, bhw);
                mma_tf32(acc[nt], Ah00, blx, bly);
                mma_tf32(acc[nt], Ah01, blz, blw);
                mma_tf32(acc[nt], Al00, bhx, bhy);
                mma_tf32(acc[nt], Al01, bhz, bhw);
                mma_tf32(acc[4+nt], Ah10, bhx, bhy);
                mma_tf32(acc[4+nt], Ah11, bhz, bhw);
                mma_tf32(acc[4+nt], Ah10, blx, bly);
                mma_tf32(acc[4+nt], Ah11, blz, blw);
                mma_tf32(acc[4+nt], Al10, bhx, bhy);
                mma_tf32(acc[4+nt], Al11, bhz, bhw);
            }
        }
        __syncthreads();
    }

    // epilogue: scatter to g_x embed layout (p = f*144 + t/64, c = t%64)
#pragma unroll
    for (int mt = 0; mt < 2; mt++) {
#pragma unroll
        for (int half = 0; half < 2; half++) {
            int m = m0w + mt*16 + half*8 + nq;
            int py = by + (m >> 4), px = bx + (m & 15);
            int p = py*kW + px;
            int f = p / 144, pm = p % 144;
#pragma unroll
            for (int nt = 0; nt < 4; nt++) {
                int c = n0w + nt*8 + 2*kq;
                float v0 = acc[mt*4 + nt][half*2]     + bias[c];
                float v1 = acc[mt*4 + nt][half*2 + 1] + bias[c+1];
                g_x[((size_t)n*kL + pm*64 + c    )*kC + f] = v0;
                g_x[((size_t)n*kL + pm*64 + c + 1)*kC + f] = v1;
            }
        }
    }
}

// ---------------- asm conv (y path), tf32 MMA, 512 thr, double buffer ------
__global__ __launch_bounds__(512, 1) void convy_mma_kernel(
    const float* __restrict__ in, const float* __restrict__ bias)
{
    extern __shared__ float4 smy[];
    float4* pB[2] = {smy,        smy + 1296};
    float4* wB[2] = {smy + 2592, smy + 2592 + 2376};

    int n    = blockIdx.x / 36;
    int tile = blockIdx.x % 36;
    int by = (tile / 6) * 16, bx = (tile % 6) * 16;
    int cog = blockIdx.y;
    int co0 = cog * 64;
    int tid = threadIdx.x;
    int wid = tid >> 5, lane = tid & 31;
    int m0w = (wid >> 1) * 32;
    int n0w = (wid & 1) * 32;
    int kq = lane & 3;
    int nq = lane >> 2;

    int p_goff[3];
#pragma unroll
    for (int i = 0; i < 3; i++) {
        int lin = tid + i*512;
        p_goff[i] = -1;
        if (lin < 1296) {
            int pos = lin >> 2, kq4 = lin & 3;
            int yy = pos / 18, xx = pos % 18;
            int hh = by + yy - 1, ww = bx + xx - 1;
            if (hh >= 0 && hh < kH && ww >= 0 && ww < kW)
                p_goff[i] = (((n*kH + hh)*kW + ww) << 8) + 4*kq4;
        }
    }
#pragma unroll
    for (int i = 0; i < 3; i++) {
        int lin = tid + i*512;
        if (lin < 1296 && p_goff[i] < 0) {
            float4 z = {0.f,0.f,0.f,0.f};
            pB[0][lin] = z; pB[1][lin] = z;
        }
    }

    float acc[8][4];
#pragma unroll
    for (int i = 0; i < 8; i++)
#pragma unroll
        for (int j = 0; j < 4; j++) acc[i][j] = 0.f;

    int pb[4];
#pragma unroll
    for (int t = 0; t < 4; t++) {
        int m = m0w + t*8 + nq;
        pb[t] = (m >> 4)*18 + (m & 15);
    }

    const float4* wsrc = &g_wyp[cog*36864];

    auto stage = [&](int sl, int buf) {
#pragma unroll
        for (int i = 0; i < 3; i++) {
            int lin = tid + i*512;
            if (lin < 1296 && p_goff[i] >= 0)
                cp16(&pB[buf][lin], (const float4*)&in[p_goff[i] + sl*16]);
        }
#pragma unroll
        for (int i = 0; i < 5; i++) {
            int lin = tid + i*512;
            if (lin < 2304)
                cp16(&wB[buf][(lin >> 6)*WNY + (lin & 63)], &wsrc[sl*2304 + lin]);
        }
    };

    stage(0, 0); cp_commit();
    for (int sl = 0; sl < 16; sl++) {
        int buf = sl & 1;
        if (sl < 15) { stage(sl + 1, buf ^ 1); cp_commit(); cp_wait1(); }
        else cp_wait0();
        __syncthreads();
        float4* patch4 = pB[buf];
        float4* wtp4   = wB[buf];

#pragma unroll
        for (int tap = 0; tap < 9; tap++) {
            int posoff = (tap/3)*18 + (tap%3);
            float4 a4[4];
#pragma unroll
            for (int t = 0; t < 4; t++)
                a4[t] = patch4[(pb[t] + posoff)*4 + kq];
            unsigned A0[2][4], A1[2][4];
#pragma unroll
            for (int mt = 0; mt < 2; mt++) {
                A0[mt][0] = __float_as_uint(a4[2*mt].x);
                A0[mt][1] = __float_as_uint(a4[2*mt+1].x);
                A0[mt][2] = __float_as_uint(a4[2*mt].y);
                A0[mt][3] = __float_as_uint(a4[2*mt+1].y);
                A1[mt][0] = __float_as_uint(a4[2*mt].z);
                A1[mt][1] = __float_as_uint(a4[2*mt+1].z);
                A1[mt][2] = __float_as_uint(a4[2*mt].w);
                A1[mt][3] = __float_as_uint(a4[2*mt+1].w);
            }
            int wr = (tap*4 + kq)*WNY + n0w + nq;
#pragma unroll
            for (int nt = 0; nt < 4; nt++) {
                float4 b4 = wtp4[wr + nt*8];
                unsigned bx0 = __float_as_uint(b4.x), by0 = __float_as_uint(b4.y);
                unsigned bz0 = __float_as_uint(b4.z), bw0 = __float_as_uint(b4.w);
#pragma unroll
                for (int mt = 0; mt < 2; mt++) {
                    mma_tf32(acc[mt*4 + nt], A0[mt], bx0, by0);
                    mma_tf32(acc[mt*4 + nt], A1[mt], bz0, bw0);
                }
            }
        }
        __syncthreads();
    }

#pragma unroll
    for (int mt = 0; mt < 2; mt++) {
#pragma unroll
        for (int half = 0; half < 2; half++) {
            int m = m0w + mt*16 + half*8 + nq;
            int py = by + (m >> 4), px = bx + (m & 15);
            int p = py*kW + px;
            int e = p / 36, pm = p % 36;
#pragma unroll
            for (int nt = 0; nt < 4; nt++) {
                int c = co0 + n0w + nt*8 + 2*kq;
                float v0 = acc[mt*4 + nt][half*2]     + bias[c];
                float v1 = acc[mt*4 + nt][half*2 + 1] + bias[c+1];
                g_y[((size_t)n*kL + pm*256 + c    )*kCh + e] = v0;
                g_y[((size_t)n*kL + pm*256 + c + 1)*kCh + e] = v1;
            }
        }
    }
}

// ---------------- LSH hashing ----------------
__global__ __launch_bounds__(256) void hash_kernel(const float* __restrict__ rot)
{
    __shared__ float Rsm[8192];
    __shared__ float xrow[8][64];
    int tid = threadIdx.x;
    for (int lin = tid; lin < 8192; lin += 256) Rsm[lin] = rot[lin];
    int wid = tid >> 5, lane = tid & 31;
    int idx = blockIdx.x*8 + wid;
    int n = idx / kL, t = idx % kL;
    const float* xr = &g_x[((size_t)n*kL + t)*kC];
    xrow[wid][lane]      = xr[lane];
    xrow[wid][lane + 32] = xr[lane + 32];
    __syncthreads();
#pragma unroll
    for (int h = 0; h < 4; h++) {
        float s = 0.f;
#pragma unroll
        for (int f = 0; f < 64; f++) s += xrow[wid][f] * Rsm[f*128 + h*32 + lane];
        float bv; int bi;
        if (s >= -s) { bv = s;  bi = lane; }
        else         { bv = -s; bi = lane + 32; }
#pragma unroll
        for (int off = 16; off > 0; off >>= 1) {
            float ov = __shfl_xor_sync(0xffffffffu, bv, off);
            int   oi = __shfl_xor_sync(0xffffffffu, bi, off);
            if (ov > bv || (ov == bv && oi < bi)) { bv = ov; bi = oi; }
        }
        if (lane == 0) g_codes[n*kTOTJ + h*kL + t] = bi + h*kHB;
    }
}

// ---------------- stable counting sort (argsort) ----------------
__global__ __launch_bounds__(256) void sortA_kernel()
{
    __shared__ int hist[256];
    int b = blockIdx.x; int n = b / 144, blk = b % 144; int tid = threadIdx.x;
    hist[tid] = 0; __syncthreads();
    int code = g_codes[n*kTOTJ + blk*256 + tid];
    atomicAdd(&hist[code], 1);
    __syncthreads();
    g_hist[(n*144 + blk)*256 + tid] = hist[tid];
}

__global__ __launch_bounds__(256) void sortBC_kernel()
{
    __shared__ int scanbuf[256];
    __shared__ int comb[256];
    __shared__ int cs[256];
    int b = blockIdx.x; int n = b / 144, blk = b % 144; int v = threadIdx.x;

    int tot = 0, off = 0;
    const int* hb = &g_hist[n*144*256 + v];
    for (int bb = 0; bb < 144; bb++) {
        int hv = hb[bb*256];
        tot += hv;
        if (bb < blk) off += hv;
    }
    scanbuf[v] = tot;
    __syncthreads();
    for (int d = 1; d < 256; d <<= 1) {
        int y = (v >= d) ? scanbuf[v - d] : 0;
        __syncthreads();
        scanbuf[v] += y;
        __syncthreads();
    }
    comb[v] = (scanbuf[v] - tot) + off;
    int c = g_codes[n*kTOTJ + blk*256 + v];
    cs[v] = c;
    __syncthreads();
    int rank = 0;
    for (int j = 0; j < v; j++) rank += (cs[j] == c);
    g_sorted[n*kTOTJ + comb[c] + rank] = blk*256 + v;
}

// ---------------- fused chunk attention (tf32 MMA, no global scratch) ------
__global__ __launch_bounds__(ATHR, 1) void attn_kernel()
{
    extern __shared__ float sm[];
    float* Qr  = sm;                      // 144*QRS
    float* Kc  = Qr + 144*QRS;            // 64*KCS
    float* Vsm = Kc + 64*KCS;             // 72*VSTR
    float* Psm = Vsm + 72*VSTR;           // 144*PSTR
    float* m_r = Psm + 144*PSTR;          // 144
    float* rowsumA = m_r + 144;           // 144
    float* rowsumB = rowsumA + 144;       // 144
    int* tIdx = (int*)(rowsumB + 144);    // 432

    int g = blockIdx.x;
    int n = g >> 8, k = g & 255;
    int h = k >> 6, kl = k & 63;
    int tid = threadIdx.x;
    int wid = tid >> 5, lane = tid & 31;
    int kq = lane & 3, nq = lane >> 2;

    for (int j = tid; j < kJW; j += ATHR) {
        int cchunk = j / kCHK, i = j % kCHK;
        int skl = (cchunk == 0) ? kl : (cchunk == 1) ? ((kl + 63) & 63) : ((kl + 1) & 63);
        int s = (h*64 + skl)*kCHK + i;
        tIdx[j] = g_sorted[n*kTOTJ + s] % kL;
    }
    for (int i = tid; i < kCHK; i += ATHR) { rowsumA[i] = 0.f; rowsumB[i] = 0.f; }
    __syncthreads();

    {
#pragma unroll
        for (int rr = 0; rr < 8; rr++) {
            int r = wid*8 + rr;
            const float* xr = &g_x[((size_t)n*kL + tIdx[r])*kC];
            float a = xr[lane], b = xr[lane + 32];
            Qr[r*QRS + lane] = a;
            Qr[r*QRS + lane + 32] = b;
            float ss = a*a + b*b;
#pragma unroll
            for (int off = 16; off > 0; off >>= 1)
                ss += __shfl_xor_sync(0xffffffffu, ss, off);
            if (lane == 0) m_r[r] = ss * rsqrtf(fmaxf(ss, 5e-5f));
        }
    }
    __syncthreads();

    int wq = wid % 9;
    int halfq = wid / 9;
    int m0 = wq * 16;
    float mA = m_r[m0 + nq], mB = m_r[m0 + 8 + nq];

    float Oacc[16][4];
#pragma unroll
    for (int i = 0; i < 16; i++)
#pragma unroll
        for (int j = 0; j < 4; j++) Oacc[i][j] = 0.f;

    for (int jc = 0; jc < 6; jc++) {
        int j0 = jc*72;
        if (wid < 9) {
            int col = wid*8 + (lane >> 2);
            int fs = (lane & 3) * 16;
            const float4* xr = (const float4*)&g_x[((size_t)n*kL + tIdx[j0 + col])*kC + fs];
            float4 v0 = xr[0], v1 = xr[1], v2 = xr[2], v3 = xr[3];
            float ss = v0.x*v0.x + v0.y*v0.y + v0.z*v0.z + v0.w*v0.w
                     + v1.x*v1.x + v1.y*v1.y + v1.z*v1.z + v1.w*v1.w
                     + v2.x*v2.x + v2.y*v2.y + v2.z*v2.z + v2.w*v2.w
                     + v3.x*v3.x + v3.y*v3.y + v3.z*v3.z + v3.w*v3.w;
            ss += __shfl_xor_sync(0xffffffffu, ss, 1);
            ss += __shfl_xor_sync(0xffffffffu, ss, 2);
            float r = rsqrtf(fmaxf(ss, 5e-5f));
            float* kcb = &Kc[fs*KCS + col];
            kcb[0*KCS] = v0.x*r; kcb[1*KCS] = v0.y*r;
            kcb[2*KCS] = v0.z*r; kcb[3*KCS] = v0.w*r;
            kcb[4*KCS] = v1.x*r; kcb[5*KCS] = v1.y*r;
            kcb[6*KCS] = v1.z*r; kcb[7*KCS] = v1.w*r;
            kcb[8*KCS] = v2.x*r; kcb[9*KCS] = v2.y*r;
            kcb[10*KCS] = v2.z*r; kcb[11*KCS] = v2.w*r;
            kcb[12*KCS] = v3.x*r; kcb[13*KCS] = v3.y*r;
            kcb[14*KCS] = v3.z*r; kcb[15*KCS] = v3.w*r;
        } else {
            int w2 = wid - 9;
#pragma unroll
            for (int rr = 0; rr < 8; rr++) {
                int row = w2*8 + rr;
                const float4* yr = (const float4*)&g_y[((size_t)n*kL + tIdx[j0 + row])*kCh];
                *(float4*)&Vsm[row*VSTR + lane*4]      = yr[lane];
                *(float4*)&Vsm[row*VSTR + (lane+32)*4] = yr[lane + 32];
            }
        }
        __syncthreads();

        {
            unsigned Af[8][4];
#pragma unroll
            for (int ks = 0; ks < 8; ks++) {
                const float* q0 = &Qr[(m0 + nq)*QRS + ks*8 + kq];
                const float* q1 = &Qr[(m0 + 8 + nq)*QRS + ks*8 + kq];
                Af[ks][0] = __float_as_uint(q0[0]);
                Af[ks][1] = __float_as_uint(q1[0]);
                Af[ks][2] = __float_as_uint(q0[4]);
                Af[ks][3] = __float_as_uint(q1[4]);
            }
            float s0 = 0.f, s1 = 0.f;
            int ntBeg = halfq ? 5 : 0;
            int ntEnd = halfq ? 9 : 5;
            for (int nt = ntBeg; nt < ntEnd; nt++) {
                float acc[4] = {0.f, 0.f, 0.f, 0.f};
#pragma unroll
                for (int ks = 0; ks < 8; ks++) {
                    unsigned b0 = __float_as_uint(Kc[(ks*8 + kq)*KCS + nt*8 + nq]);
                    unsigned b1 = __float_as_uint(Kc[(ks*8 + 4 + kq)*KCS + nt*8 + nq]);
                    mma_tf32(acc, Af[ks], b0, b1);
                }
                float e0 = __expf(acc[0] - mA), e1 = __expf(acc[1] - mA);
                float e2 = __expf(acc[2] - mB), e3 = __expf(acc[3] - mB);
                s0 += e0 + e1; s1 += e2 + e3;
                float2 pA; pA.x = e0; pA.y = e1;
                float2 pB2; pB2.x = e2; pB2.y = e3;
                *(float2*)&Psm[(m0 + nq)*PSTR + nt*8 + 2*kq] = pA;
                *(float2*)&Psm[(m0 + 8 + nq)*PSTR + nt*8 + 2*kq] = pB2;
            }
            s0 += __shfl_xor_sync(0xffffffffu, s0, 1);
            s0 += __shfl_xor_sync(0xffffffffu, s0, 2);
            s1 += __shfl_xor_sync(0xffffffffu, s1, 1);
            s1 += __shfl_xor_sync(0xffffffffu, s1, 2);
            if (kq == 0) {
                float* rs = halfq ? rowsumB : rowsumA;
                rs[m0 + nq] += s0;
                rs[m0 + 8 + nq] += s1;
            }
        }
        __syncthreads();

        {
            int n0 = halfq * 128;
#pragma unroll
            for (int ks = 0; ks < 9; ks++) {
                unsigned A[4];
                const float* p0 = &Psm[(m0 + nq)*PSTR + ks*8 + kq];
                const float* p1 = &Psm[(m0 + 8 + nq)*PSTR + ks*8 + kq];
                A[0] = __float_as_uint(p0[0]);
                A[1] = __float_as_uint(p1[0]);
                A[2] = __float_as_uint(p0[4]);
                A[3] = __float_as_uint(p1[4]);
                const float* vb0 = &Vsm[(ks*8 + kq)*VSTR + n0 + nq];
                const float* vb1 = &Vsm[(ks*8 + 4 + kq)*VSTR + n0 + nq];
#pragma unroll
                for (int nt = 0; nt < 16; nt++) {
                    unsigned b0 = __float_as_uint(vb0[nt*8]);
                    unsigned b1 = __float_as_uint(vb1[nt*8]);
                    mma_tf32(Oacc[nt], A, b0, b1);
                }
            }
        }
        __syncthreads();
    }

    {
        int n0 = halfq * 128;
        int rA = m0 + nq, rB = rA + 8;
        float sumA = rowsumA[rA] + rowsumB[rA];
        float sumB = rowsumA[rB] + rowsumB[rB];
        float invA = 1.f / sumA;
        float invB = 1.f / sumB;
        size_t baseA = ((size_t)(n*4 + h)*kL + tIdx[rA])*kCh;
        size_t baseB = ((size_t)(n*4 + h)*kL + tIdx[rB])*kCh;
#pragma unroll
        for (int nt = 0; nt < 16; nt++) {
            int cA = n0 + nt*8 + 2*kq;
            float2 oA; oA.x = Oacc[nt][0]*invA; oA.y = Oacc[nt][1]*invA;
            float2 oB; oB.x = Oacc[nt][2]*invB; oB.y = Oacc[nt][3]*invB;
            *(float2*)&g_ret[baseA + cA] = oA;
            *(float2*)&g_ret[baseB + cA] = oB;
        }
        if (wid < 9 && lane < 16) {
            int row = wid*16 + lane;
            float s = rowsumA[row] + rowsumB[row];
            g_bs[(size_t)(n*4 + h)*kL + tIdx[row]] = m_r[row] + __logf(s);
        }
    }
}

// ---------------- head combine + residual + output layout ----------------
__global__ __launch_bounds__(256) void combine_kernel(
    const float* __restrict__ in, float* __restrict__ out)
{
    __shared__ float accs[256*33];
    __shared__ float probs[4*256];
    int n = blockIdx.x / 36, q = blockIdx.x % 36;
    int e0 = blockIdx.y * 32;
    int tid = threadIdx.x;

    {
        int t = q*256 + tid;
        float b0 = g_bs[(size_t)(n*4 + 0)*kL + t];
        float b1 = g_bs[(size_t)(n*4 + 1)*kL + t];
        float b2 = g_bs[(size_t)(n*4 + 2)*kL + t];
        float b3 = g_bs[(size_t)(n*4 + 3)*kL + t];
        float m = fmaxf(fmaxf(b0, b1), fmaxf(b2, b3));
        float x0 = __expf(b0 - m), x1 = __expf(b1 - m);
        float x2 = __expf(b2 - m), x3 = __expf(b3 - m);
        float sinv = 1.f / (x0 + x1 + x2 + x3);
        probs[0*256 + tid] = x0*sinv; probs[1*256 + tid] = x1*sinv;
        probs[2*256 + tid] = x2*sinv; probs[3*256 + tid] = x3*sinv;
    }
    for (int lin = tid; lin < 256*33; lin += 256) accs[lin] = 0.f;
    __syncthreads();

    for (int h = 0; h < 4; h++) {
        for (int lin = tid; lin < 256*32; lin += 256) {
            int cc = lin >> 5, e = lin & 31;
            float v = g_ret[((size_t)(n*4 + h)*kL + q*256 + cc)*kCh + e0 + e];
            accs[cc*33 + e] += probs[h*256 + cc] * v;
        }
    }
    __syncthreads();

    for (int lin = tid; lin < 32*256; lin += 256) {
        int e = lin >> 8, c = lin & 255;
        int p = (e0 + e)*36 + q;
        size_t oi = ((size_t)n*kL + p)*kCh + c;
        out[oi] = 0.1f*accs[c*33 + e] + in[oi];
    }
}

// ---------------- launch ----------------
extern "C" void kernel_launch(void* const* d_in, const int* in_sizes, int n_in,
                              void* d_out, int out_size)
{
    const float* input     = (const float*)d_in[0];
    const float* w_match   = (const float*)d_in[1];
    const float* b_match   = (const float*)d_in[2];
    const float* w_asm     = (const float*)d_in[3];
    const float* b_asm     = (const float*)d_in[4];
    const float* rotations = (const float*)d_in[5];
    float* out = (float*)d_out;

    const int CONVX_SMEM = 12384 * 16;                                  // 198144
    const int CONVY_SMEM = (2592 + 4752) * 16;                          // 117504
    const int ATT_SMEM   = (144*QRS + 64*KCS + 72*VSTR + 144*PSTR + 144*3 + 432) * 4;

    cudaFuncSetAttribute(convx_mma_kernel, cudaFuncAttributeMaxDynamicSharedMemorySize, CONVX_SMEM);
    cudaFuncSetAttribute(convy_mma_kernel, cudaFuncAttributeMaxDynamicSharedMemorySize, CONVY_SMEM);
    cudaFuncSetAttribute(attn_kernel,      cudaFuncAttributeMaxDynamicSharedMemorySize, ATT_SMEM);

    prep_in_kernel<<<kN*kL*64/256, 256>>>(input);
    prep_wx_kernel<<<144, 256>>>(w_match);
    prep_wy_kernel<<<576, 256>>>(w_asm);
    // convy in ncu capture slot 4
    convy_mma_kernel<<<dim3(kN*36, 4), 512, CONVY_SMEM>>>(input, b_asm);
    convx_mma_kernel<<<kN*72, 256, CONVX_SMEM>>>(input, b_match);
    hash_kernel<<<kN*kL/8, 256>>>(rotations);
    sortA_kernel<<<kN*144, 256>>>();
    sortBC_kernel<<<kN*144, 256>>>();
    attn_kernel<<<kN*256, ATHR, ATT_SMEM>>>();
    combine_kernel<<<dim3(kN*36, 8), 256>>>(input, out);
}

// round 11
// speedup vs baseline: 1.0044x; 1.0013x over previous
#include <cuda_runtime.h>
#include <math.h>

// Problem constants
#define kN 4
#define kH 96
#define kW 96
#define kCh 256
#define kC 64
#define kL 9216          // 96*96
#define kNH 4
#define kHB 64           // hash buckets
#define kCHK 144
#define kTOTJ 36864      // kNH*kL
#define kJW 432          // 3*kCHK

// smem strides (attn)
#define QRS 68
#define KCS 76
#define VSTR 260
#define PSTR 76
#define ATHR 576

// conv packed layouts
#define WNY 66           // float4 row stride for packed weights in smem

__device__ __forceinline__ float cvt_tf32(float f) {
    unsigned r; asm("cvt.rna.tf32.f32 %0,%1;" : "=r"(r) : "f"(f));
    return __uint_as_float(r);
}
__device__ __forceinline__ float trunc13(float f) {
    return __uint_as_float(__float_as_uint(f) & 0xFFFFE000u);
}
__device__ __forceinline__ void mma_tf32(float* d, const unsigned* a, unsigned b0, unsigned b1) {
    asm("mma.sync.aligned.m16n8k8.row.col.f32.tf32.tf32.f32 "
        "{%0,%1,%2,%3},{%4,%5,%6,%7},{%8,%9},{%0,%1,%2,%3};"
        : "+f"(d[0]), "+f"(d[1]), "+f"(d[2]), "+f"(d[3])
        : "r"(a[0]), "r"(a[1]), "r"(a[2]), "r"(a[3]), "r"(b0), "r"(b1));
}
__device__ __forceinline__ void cp16(float4* dst, const float4* src) {
    unsigned s = (unsigned)__cvta_generic_to_shared(dst);
    asm volatile("cp.async.cg.shared.global [%0],[%1],16;" :: "r"(s), "l"(src));
}
__device__ __forceinline__ void cp_commit() { asm volatile("cp.async.commit_group;"); }
__device__ __forceinline__ void cp_wait1() { asm volatile("cp.async.wait_group 1;"); }
__device__ __forceinline__ void cp_wait0() { asm volatile("cp.async.wait_group 0;"); }

// -------- scratch (device globals; no allocation allowed) --------
__device__ float g_x[(size_t)kN*kL*kC];            // x_embed (n,t,f)
__device__ float g_y[(size_t)kN*kL*kCh];           // y_embed (n,t,e)
__device__ int   g_codes[kN*kTOTJ];
__device__ int   g_sorted[kN*kTOTJ];
__device__ int   g_hist[kN*144*256];
__device__ float g_ret[(size_t)kN*kNH*kL*kCh];     // attention out (n,h,t,e)
__device__ float g_bs[kN*kNH*kL];                  // lse (n,h,t)
// prepacked operands
__device__ float4 g_wyp[4*16*36*64];               // convy weights [cog][sl][r][nn]
__device__ float4 g_wxh[16*36*64];                 // convx weights hi
__device__ float4 g_wxl[16*36*64];                 // convx weights lo
__device__ float  g_xil[(size_t)kN*kL*kCh];        // input lo = v - trunc13(v)

// ---------------- prepack kernels ----------------
__global__ __launch_bounds__(256) void prep_in_kernel(const float* __restrict__ in)
{
    size_t i = (size_t)blockIdx.x*256 + threadIdx.x;   // f4 index
    float4 v = ((const float4*)in)[i];
    float4 vl;
    vl.x = v.x - trunc13(v.x);
    vl.y = v.y - trunc13(v.y);
    vl.z = v.z - trunc13(v.z);
    vl.w = v.w - trunc13(v.w);
    ((float4*)g_xil)[i] = vl;
}

__global__ __launch_bounds__(256) void prep_wx_kernel(const float* __restrict__ w)
{
    int i = blockIdx.x*256 + threadIdx.x;              // < 36864
    int nn = i & 63;
    int r  = (i >> 6) % 36;
    int sl = i / 2304;
    int tap = r >> 2, kq4 = r & 3;
    int cin = sl*16 + 4*kq4;
    const float* wp = &w[(tap*kCh + cin)*kC + nn];
    float f0 = wp[0], f1 = wp[kC], f2 = wp[2*kC], f3 = wp[3*kC];
    float4 vh, vl;
    vh.x = cvt_tf32(f0); vl.x = f0 - vh.x;
    vh.y = cvt_tf32(f1); vl.y = f1 - vh.y;
    vh.z = cvt_tf32(f2); vl.z = f2 - vh.z;
    vh.w = cvt_tf32(f3); vl.w = f3 - vh.w;
    g_wxh[i] = vh; g_wxl[i] = vl;
}

__global__ __launch_bounds__(256) void prep_wy_kernel(const float* __restrict__ w)
{
    int i = blockIdx.x*256 + threadIdx.x;              // < 4*36864
    int j = i % 36864;
    int cog = i / 36864;
    int nn = j & 63;
    int r  = (j >> 6) % 36;
    int sl = j / 2304;
    int tap = r >> 2, kq4 = r & 3;
    int cin = sl*16 + 4*kq4;
    const float* wp = &w[(size_t)(tap*kCh + cin)*kCh + cog*64 + nn];
    float4 v;
    v.x = wp[0]; v.y = wp[kCh]; v.z = wp[2*kCh]; v.w = wp[3*kCh];
    g_wyp[i] = v;
}

// ---------------- match conv (x path), 3xTF32 MMA, cp.async double-buffer --
__global__ __launch_bounds__(256, 1) void convx_mma_kernel(
    const float* __restrict__ in, const float* __restrict__ bias)
{
    extern __shared__ float4 smx[];
    float4* pH[2] = {smx,        smx + 720};
    float4* pL[2] = {smx + 1440, smx + 2160};
    float4* wH[2] = {smx + 2880, smx + 2880 + 2376};
    float4* wL[2] = {smx + 7632, smx + 7632 + 2376};

    int n    = blockIdx.x / 72;
    int tile = blockIdx.x % 72;
    int by = (tile / 6) * 8, bx = (tile % 6) * 16;
    int tid = threadIdx.x;
    int wid = tid >> 5, lane = tid & 31;
    int m0w = (wid >> 1) * 32;
    int n0w = (wid & 1) * 32;
    int kq = lane & 3, nq = lane >> 2;

    int p_goff[3];
#pragma unroll
    for (int i = 0; i < 3; i++) {
        int lin = tid + i*256;
        p_goff[i] = -1;
        if (lin < 720) {
            int pos = lin >> 2, kq4 = lin & 3;
            int yy = pos / 18, xx = pos % 18;
            int hh = by + yy - 1, ww = bx + xx - 1;
            if (hh >= 0 && hh < kH && ww >= 0 && ww < kW)
                p_goff[i] = (((n*kH + hh)*kW + ww) << 8) + 4*kq4;
        }
    }
#pragma unroll
    for (int i = 0; i < 3; i++) {
        int lin = tid + i*256;
        if (lin < 720 && p_goff[i] < 0) {
            float4 z = {0.f,0.f,0.f,0.f};
            pH[0][lin] = z; pH[1][lin] = z;
            pL[0][lin] = z; pL[1][lin] = z;
        }
    }

    float acc[8][4];
#pragma unroll
    for (int i = 0; i < 8; i++)
#pragma unroll
        for (int j = 0; j < 4; j++) acc[i][j] = 0.f;

    int pb[4];
#pragma unroll
    for (int t = 0; t < 4; t++) {
        int m = m0w + t*8 + nq;
        pb[t] = (m >> 4)*18 + (m & 15);
    }

    auto stage = [&](int sl, int buf) {
#pragma unroll
        for (int i = 0; i < 3; i++) {
            int lin = tid + i*256;
            if (lin < 720 && p_goff[i] >= 0) {
                cp16(&pH[buf][lin], (const float4*)&in[p_goff[i] + sl*16]);
                cp16(&pL[buf][lin], (const float4*)&g_xil[p_goff[i] + sl*16]);
            }
        }
#pragma unroll
        for (int i = 0; i < 9; i++) {
            int lin = tid + i*256;
            int r = lin >> 6, nn = lin & 63;
            int didx = r*WNY + nn;
            int sidx = sl*2304 + lin;
            cp16(&wH[buf][didx], &g_wxh[sidx]);
            cp16(&wL[buf][didx], &g_wxl[sidx]);
        }
    };

    stage(0, 0); cp_commit();
    for (int sl = 0; sl < 16; sl++) {
        int buf = sl & 1;
        if (sl < 15) { stage(sl + 1, buf ^ 1); cp_commit(); cp_wait1(); }
        else cp_wait0();
        __syncthreads();
        float4* p4h = pH[buf]; float4* p4l = pL[buf];
        float4* w4h = wH[buf]; float4* w4l = wL[buf];

#pragma unroll
        for (int tap = 0; tap < 9; tap++) {
            int posoff = (tap/3)*18 + (tap%3);
            float4 ah[4], al[4];
#pragma unroll
            for (int t = 0; t < 4; t++) {
                int o = (pb[t] + posoff)*4 + kq;
                ah[t] = p4h[o]; al[t] = p4l[o];
            }
            unsigned Ah00[4] = {__float_as_uint(ah[0].x), __float_as_uint(ah[1].x),
                                __float_as_uint(ah[0].y), __float_as_uint(ah[1].y)};
            unsigned Ah01[4] = {__float_as_uint(ah[0].z), __float_as_uint(ah[1].z),
                                __float_as_uint(ah[0].w), __float_as_uint(ah[1].w)};
            unsigned Ah10[4] = {__float_as_uint(ah[2].x), __float_as_uint(ah[3].x),
                                __float_as_uint(ah[2].y), __float_as_uint(ah[3].y)};
            unsigned Ah11[4] = {__float_as_uint(ah[2].z), __float_as_uint(ah[3].z),
                                __float_as_uint(ah[2].w), __float_as_uint(ah[3].w)};
            unsigned Al00[4] = {__float_as_uint(al[0].x), __float_as_uint(al[1].x),
                                __float_as_uint(al[0].y), __float_as_uint(al[1].y)};
            unsigned Al01[4] = {__float_as_uint(al[0].z), __float_as_uint(al[1].z),
                                __float_as_uint(al[0].w), __float_as_uint(al[1].w)};
            unsigned Al10[4] = {__float_as_uint(al[2].x), __float_as_uint(al[3].x),
                                __float_as_uint(al[2].y), __float_as_uint(al[3].y)};
            unsigned Al11[4] = {__float_as_uint(al[2].z), __float_as_uint(al[3].z),
                                __float_as_uint(al[2].w), __float_as_uint(al[3].w)};
            int wr = (tap*4 + kq)*WNY + n0w + nq;
#pragma unroll
            for (int nt = 0; nt < 4; nt++) {
                float4 bh = w4h[wr + nt*8];
                float4 bl = w4l[wr + nt*8];
                unsigned bhx = __float_as_uint(bh.x), bhy = __float_as_uint(bh.y);
                unsigned bhz = __float_as_uint(bh.z), bhw = __float_as_uint(bh.w);
                unsigned blx = __float_as_uint(bl.x), bly = __float_as_uint(bl.y);
                unsigned blz = __float_as_uint(bl.z), blw = __float_as_uint(bl.w);
                mma_tf32(acc[nt], Ah00, bhx, bhy);
                mma_tf32(acc[nt], Ah01, bhz, bhw);
                mma_tf32(acc[nt], Ah00, blx, bly);
                mma_tf32(acc[nt], Ah01, blz, blw);
                mma_tf32(acc[nt], Al00, bhx, bhy);
                mma_tf32(acc[nt], Al01, bhz, bhw);
                mma_tf32(acc[4+nt], Ah10, bhx, bhy);
                mma_tf32(acc[4+nt], Ah11, bhz, bhw);
                mma_tf32(acc[4+nt], Ah10, blx, bly);
                mma_tf32(acc[4+nt], Ah11, blz, blw);
                mma_tf32(acc[4+nt], Al10, bhx, bhy);
                mma_tf32(acc[4+nt], Al11, bhz, bhw);
            }
        }
        __syncthreads();
    }

#pragma unroll
    for (int mt = 0; mt < 2; mt++) {
#pragma unroll
        for (int half = 0; half < 2; half++) {
            int m = m0w + mt*16 + half*8 + nq;
            int py = by + (m >> 4), px = bx + (m & 15);
            int p = py*kW + px;
            int f = p / 144, pm = p % 144;
#pragma unroll
            for (int nt = 0; nt < 4; nt++) {
                int c = n0w + nt*8 + 2*kq;
                float v0 = acc[mt*4 + nt][half*2]     + bias[c];
                float v1 = acc[mt*4 + nt][half*2 + 1] + bias[c+1];
                g_x[((size_t)n*kL + pm*64 + c    )*kC + f] = v0;
                g_x[((size_t)n*kL + pm*64 + c + 1)*kC + f] = v1;
            }
        }
    }
}

// ---------------- asm conv (y path), tf32 MMA, 512 thr, double buffer ------
__global__ __launch_bounds__(512, 1) void convy_mma_kernel(
    const float* __restrict__ in, const float* __restrict__ bias)
{
    extern __shared__ float4 smy[];
    float4* pB[2] = {smy,        smy + 1296};
    float4* wB[2] = {smy + 2592, smy + 2592 + 2376};

    int n    = blockIdx.x / 36;
    int tile = blockIdx.x % 36;
    int by = (tile / 6) * 16, bx = (tile % 6) * 16;
    int cog = blockIdx.y;
    int co0 = cog * 64;
    int tid = threadIdx.x;
    int wid = tid >> 5, lane = tid & 31;
    int m0w = (wid >> 1) * 32;
    int n0w = (wid & 1) * 32;
    int kq = lane & 3;
    int nq = lane >> 2;

    int p_goff[3];
#pragma unroll
    for (int i = 0; i < 3; i++) {
        int lin = tid + i*512;
        p_goff[i] = -1;
        if (lin < 1296) {
            int pos = lin >> 2, kq4 = lin & 3;
            int yy = pos / 18, xx = pos % 18;
            int hh = by + yy - 1, ww = bx + xx - 1;
            if (hh >= 0 && hh < kH && ww >= 0 && ww < kW)
                p_goff[i] = (((n*kH + hh)*kW + ww) << 8) + 4*kq4;
        }
    }
#pragma unroll
    for (int i = 0; i < 3; i++) {
        int lin = tid + i*512;
        if (lin < 1296 && p_goff[i] < 0) {
            float4 z = {0.f,0.f,0.f,0.f};
            pB[0][lin] = z; pB[1][lin] = z;
        }
    }

    float acc[8][4];
#pragma unroll
    for (int i = 0; i < 8; i++)
#pragma unroll
        for (int j = 0; j < 4; j++) acc[i][j] = 0.f;

    int pb[4];
#pragma unroll
    for (int t = 0; t < 4; t++) {
        int m = m0w + t*8 + nq;
        pb[t] = (m >> 4)*18 + (m & 15);
    }

    const float4* wsrc = &g_wyp[cog*36864];

    auto stage = [&](int sl, int buf) {
#pragma unroll
        for (int i = 0; i < 3; i++) {
            int lin = tid + i*512;
            if (lin < 1296 && p_goff[i] >= 0)
                cp16(&pB[buf][lin], (const float4*)&in[p_goff[i] + sl*16]);
        }
#pragma unroll
        for (int i = 0; i < 5; i++) {
            int lin = tid + i*512;
            if (lin < 2304)
                cp16(&wB[buf][(lin >> 6)*WNY + (lin & 63)], &wsrc[sl*2304 + lin]);
        }
    };

    stage(0, 0); cp_commit();
    for (int sl = 0; sl < 16; sl++) {
        int buf = sl & 1;
        if (sl < 15) { stage(sl + 1, buf ^ 1); cp_commit(); cp_wait1(); }
        else cp_wait0();
        __syncthreads();
        float4* patch4 = pB[buf];
        float4* wtp4   = wB[buf];

#pragma unroll
        for (int tap = 0; tap < 9; tap++) {
            int posoff = (tap/3)*18 + (tap%3);
            float4 a4[4];
#pragma unroll
            for (int t = 0; t < 4; t++)
                a4[t] = patch4[(pb[t] + posoff)*4 + kq];
            unsigned A0[2][4], A1[2][4];
#pragma unroll
            for (int mt = 0; mt < 2; mt++) {
                A0[mt][0] = __float_as_uint(a4[2*mt].x);
                A0[mt][1] = __float_as_uint(a4[2*mt+1].x);
                A0[mt][2] = __float_as_uint(a4[2*mt].y);
                A0[mt][3] = __float_as_uint(a4[2*mt+1].y);
                A1[mt][0] = __float_as_uint(a4[2*mt].z);
                A1[mt][1] = __float_as_uint(a4[2*mt+1].z);
                A1[mt][2] = __float_as_uint(a4[2*mt].w);
                A1[mt][3] = __float_as_uint(a4[2*mt+1].w);
            }
            int wr = (tap*4 + kq)*WNY + n0w + nq;
#pragma unroll
            for (int nt = 0; nt < 4; nt++) {
                float4 b4 = wtp4[wr + nt*8];
                unsigned bx0 = __float_as_uint(b4.x), by0 = __float_as_uint(b4.y);
                unsigned bz0 = __float_as_uint(b4.z), bw0 = __float_as_uint(b4.w);
#pragma unroll
                for (int mt = 0; mt < 2; mt++) {
                    mma_tf32(acc[mt*4 + nt], A0[mt], bx0, by0);
                    mma_tf32(acc[mt*4 + nt], A1[mt], bz0, bw0);
                }
            }
        }
        __syncthreads();
    }

#pragma unroll
    for (int mt = 0; mt < 2; mt++) {
#pragma unroll
        for (int half = 0; half < 2; half++) {
            int m = m0w + mt*16 + half*8 + nq;
            int py = by + (m >> 4), px = bx + (m & 15);
            int p = py*kW + px;
            int e = p / 36, pm = p % 36;
#pragma unroll
            for (int nt = 0; nt < 4; nt++) {
                int c = co0 + n0w + nt*8 + 2*kq;
                float v0 = acc[mt*4 + nt][half*2]     + bias[c];
                float v1 = acc[mt*4 + nt][half*2 + 1] + bias[c+1];
                g_y[((size_t)n*kL + pm*256 + c    )*kCh + e] = v0;
                g_y[((size_t)n*kL + pm*256 + c + 1)*kCh + e] = v1;
            }
        }
    }
}

// ---------------- LSH hashing ----------------
__global__ __launch_bounds__(256) void hash_kernel(const float* __restrict__ rot)
{
    __shared__ float Rsm[8192];
    __shared__ float xrow[8][64];
    int tid = threadIdx.x;
    for (int lin = tid; lin < 8192; lin += 256) Rsm[lin] = rot[lin];
    int wid = tid >> 5, lane = tid & 31;
    int idx = blockIdx.x*8 + wid;
    int n = idx / kL, t = idx % kL;
    const float* xr = &g_x[((size_t)n*kL + t)*kC];
    xrow[wid][lane]      = xr[lane];
    xrow[wid][lane + 32] = xr[lane + 32];
    __syncthreads();
#pragma unroll
    for (int h = 0; h < 4; h++) {
        float s = 0.f;
#pragma unroll
        for (int f = 0; f < 64; f++) s += xrow[wid][f] * Rsm[f*128 + h*32 + lane];
        float bv; int bi;
        if (s >= -s) { bv = s;  bi = lane; }
        else         { bv = -s; bi = lane + 32; }
#pragma unroll
        for (int off = 16; off > 0; off >>= 1) {
            float ov = __shfl_xor_sync(0xffffffffu, bv, off);
            int   oi = __shfl_xor_sync(0xffffffffu, bi, off);
            if (ov > bv || (ov == bv && oi < bi)) { bv = ov; bi = oi; }
        }
        if (lane == 0) g_codes[n*kTOTJ + h*kL + t] = bi + h*kHB;
    }
}

// ---------------- stable counting sort (argsort) ----------------
__global__ __launch_bounds__(256) void sortA_kernel()
{
    __shared__ int hist[256];
    int b = blockIdx.x; int n = b / 144, blk = b % 144; int tid = threadIdx.x;
    hist[tid] = 0; __syncthreads();
    int code = g_codes[n*kTOTJ + blk*256 + tid];
    atomicAdd(&hist[code], 1);
    __syncthreads();
    g_hist[(n*144 + blk)*256 + tid] = hist[tid];
}

__global__ __launch_bounds__(256) void sortBC_kernel()
{
    __shared__ int scanbuf[256];
    __shared__ int comb[256];
    __shared__ int cs[256];
    int b = blockIdx.x; int n = b / 144, blk = b % 144; int v = threadIdx.x;

    int tot = 0, off = 0;
    const int* hb = &g_hist[n*144*256 + v];
    for (int bb = 0; bb < 144; bb++) {
        int hv = hb[bb*256];
        tot += hv;
        if (bb < blk) off += hv;
    }
    scanbuf[v] = tot;
    __syncthreads();
    for (int d = 1; d < 256; d <<= 1) {
        int y = (v >= d) ? scanbuf[v - d] : 0;
        __syncthreads();
        scanbuf[v] += y;
        __syncthreads();
    }
    comb[v] = (scanbuf[v] - tot) + off;
    int c = g_codes[n*kTOTJ + blk*256 + v];
    cs[v] = c;
    __syncthreads();
    int rank = 0;
    for (int j = 0; j < v; j++) rank += (cs[j] == c);
    g_sorted[n*kTOTJ + comb[c] + rank] = blk*256 + v;
}

// ---------------- fused chunk attention (tf32 MMA, no global scratch) ------
__global__ __launch_bounds__(ATHR, 1) void attn_kernel()
{
    extern __shared__ float sm[];
    float* Qr  = sm;                      // 144*QRS
    float* Kc  = Qr + 144*QRS;            // 64*KCS
    float* Vsm = Kc + 64*KCS;             // 72*VSTR
    float* Psm = Vsm + 72*VSTR;           // 144*PSTR
    float* m_r = Psm + 144*PSTR;          // 144
    float* rowsumA = m_r + 144;           // 144
    float* rowsumB = rowsumA + 144;       // 144
    int* tIdx = (int*)(rowsumB + 144);    // 432

    int g = blockIdx.x;
    int n = g >> 8, k = g & 255;
    int h = k >> 6, kl = k & 63;
    int tid = threadIdx.x;
    int wid = tid >> 5, lane = tid & 31;
    int kq = lane & 3, nq = lane >> 2;

    for (int j = tid; j < kJW; j += ATHR) {
        int cchunk = j / kCHK, i = j % kCHK;
        int skl = (cchunk == 0) ? kl : (cchunk == 1) ? ((kl + 63) & 63) : ((kl + 1) & 63);
        int s = (h*64 + skl)*kCHK + i;
        tIdx[j] = g_sorted[n*kTOTJ + s] % kL;
    }
    for (int i = tid; i < kCHK; i += ATHR) { rowsumA[i] = 0.f; rowsumB[i] = 0.f; }
    __syncthreads();

    {
#pragma unroll
        for (int rr = 0; rr < 8; rr++) {
            int r = wid*8 + rr;
            const float* xr = &g_x[((size_t)n*kL + tIdx[r])*kC];
            float a = xr[lane], b = xr[lane + 32];
            Qr[r*QRS + lane] = a;
            Qr[r*QRS + lane + 32] = b;
            float ss = a*a + b*b;
#pragma unroll
            for (int off = 16; off > 0; off >>= 1)
                ss += __shfl_xor_sync(0xffffffffu, ss, off);
            if (lane == 0) m_r[r] = ss * rsqrtf(fmaxf(ss, 5e-5f));
        }
    }
    __syncthreads();

    int wq = wid % 9;
    int halfq = wid / 9;
    int m0 = wq * 16;
    float mA = m_r[m0 + nq], mB = m_r[m0 + 8 + nq];

    float Oacc[16][4];
#pragma unroll
    for (int i = 0; i < 16; i++)
#pragma unroll
        for (int j = 0; j < 4; j++) Oacc[i][j] = 0.f;

    for (int jc = 0; jc < 6; jc++) {
        int j0 = jc*72;
        if (wid < 9) {
            int col = wid*8 + (lane >> 2);
            int fs = (lane & 3) * 16;
            const float4* xr = (const float4*)&g_x[((size_t)n*kL + tIdx[j0 + col])*kC + fs];
            float4 v0 = xr[0], v1 = xr[1], v2 = xr[2], v3 = xr[3];
            float ss = v0.x*v0.x + v0.y*v0.y + v0.z*v0.z + v0.w*v0.w
                     + v1.x*v1.x + v1.y*v1.y + v1.z*v1.z + v1.w*v1.w
                     + v2.x*v2.x + v2.y*v2.y + v2.z*v2.z + v2.w*v2.w
                     + v3.x*v3.x + v3.y*v3.y + v3.z*v3.z + v3.w*v3.w;
            ss += __shfl_xor_sync(0xffffffffu, ss, 1);
            ss += __shfl_xor_sync(0xffffffffu, ss, 2);
            float r = rsqrtf(fmaxf(ss, 5e-5f));
            float* kcb = &Kc[fs*KCS + col];
            kcb[0*KCS] = v0.x*r; kcb[1*KCS] = v0.y*r;
            kcb[2*KCS] = v0.z*r; kcb[3*KCS] = v0.w*r;
            kcb[4*KCS] = v1.x*r; kcb[5*KCS] = v1.y*r;
            kcb[6*KCS] = v1.z*r; kcb[7*KCS] = v1.w*r;
            kcb[8*KCS] = v2.x*r; kcb[9*KCS] = v2.y*r;
            kcb[10*KCS] = v2.z*r; kcb[11*KCS] = v2.w*r;
            kcb[12*KCS] = v3.x*r; kcb[13*KCS] = v3.y*r;
            kcb[14*KCS] = v3.z*r; kcb[15*KCS] = v3.w*r;
        } else {
            int w2 = wid - 9;
#pragma unroll
            for (int rr = 0; rr < 8; rr++) {
                int row = w2*8 + rr;
                const float4* yr = (const float4*)&g_y[((size_t)n*kL + tIdx[j0 + row])*kCh];
                *(float4*)&Vsm[row*VSTR + lane*4]      = yr[lane];
                *(float4*)&Vsm[row*VSTR + (lane+32)*4] = yr[lane + 32];
            }
        }
        __syncthreads();

        {
            unsigned Af[8][4];
#pragma unroll
            for (int ks = 0; ks < 8; ks++) {
                const float* q0 = &Qr[(m0 + nq)*QRS + ks*8 + kq];
                const float* q1 = &Qr[(m0 + 8 + nq)*QRS + ks*8 + kq];
                Af[ks][0] = __float_as_uint(q0[0]);
                Af[ks][1] = __float_as_uint(q1[0]);
                Af[ks][2] = __float_as_uint(q0[4]);
                Af[ks][3] = __float_as_uint(q1[4]);
            }
            float s0 = 0.f, s1 = 0.f;
            int ntBeg = halfq ? 5 : 0;
            int ntEnd = halfq ? 9 : 5;
            for (int nt = ntBeg; nt < ntEnd; nt++) {
                float acc[4] = {0.f, 0.f, 0.f, 0.f};
#pragma unroll
                for (int ks = 0; ks < 8; ks++) {
                    unsigned b0 = __float_as_uint(Kc[(ks*8 + kq)*KCS + nt*8 + nq]);
                    unsigned b1 = __float_as_uint(Kc[(ks*8 + 4 + kq)*KCS + nt*8 + nq]);
                    mma_tf32(acc, Af[ks], b0, b1);
                }
                float e0 = __expf(acc[0] - mA), e1 = __expf(acc[1] - mA);
                float e2 = __expf(acc[2] - mB), e3 = __expf(acc[3] - mB);
                s0 += e0 + e1; s1 += e2 + e3;
                float2 pA; pA.x = e0; pA.y = e1;
                float2 pB2; pB2.x = e2; pB2.y = e3;
                *(float2*)&Psm[(m0 + nq)*PSTR + nt*8 + 2*kq] = pA;
                *(float2*)&Psm[(m0 + 8 + nq)*PSTR + nt*8 + 2*kq] = pB2;
            }
            s0 += __shfl_xor_sync(0xffffffffu, s0, 1);
            s0 += __shfl_xor_sync(0xffffffffu, s0, 2);
            s1 += __shfl_xor_sync(0xffffffffu, s1, 1);
            s1 += __shfl_xor_sync(0xffffffffu, s1, 2);
            if (kq == 0) {
                float* rs = halfq ? rowsumB : rowsumA;
                rs[m0 + nq] += s0;
                rs[m0 + 8 + nq] += s1;
            }
        }
        __syncthreads();

        {
            int n0 = halfq * 128;
#pragma unroll
            for (int ks = 0; ks < 9; ks++) {
                unsigned A[4];
                const float* p0 = &Psm[(m0 + nq)*PSTR + ks*8 + kq];
                const float* p1 = &Psm[(m0 + 8 + nq)*PSTR + ks*8 + kq];
                A[0] = __float_as_uint(p0[0]);
                A[1] = __float_as_uint(p1[0]);
                A[2] = __float_as_uint(p0[4]);
                A[3] = __float_as_uint(p1[4]);
                const float* vb0 = &Vsm[(ks*8 + kq)*VSTR + n0 + nq];
                const float* vb1 = &Vsm[(ks*8 + 4 + kq)*VSTR + n0 + nq];
#pragma unroll
                for (int nt = 0; nt < 16; nt++) {
                    unsigned b0 = __float_as_uint(vb0[nt*8]);
                    unsigned b1 = __float_as_uint(vb1[nt*8]);
                    mma_tf32(Oacc[nt], A, b0, b1);
                }
            }
        }
        __syncthreads();
    }

    {
        int n0 = halfq * 128;
        int rA = m0 + nq, rB = rA + 8;
        float sumA = rowsumA[rA] + rowsumB[rA];
        float sumB = rowsumA[rB] + rowsumB[rB];
        float invA = 1.f / sumA;
        float invB = 1.f / sumB;
        size_t baseA = ((size_t)(n*4 + h)*kL + tIdx[rA])*kCh;
        size_t baseB = ((size_t)(n*4 + h)*kL + tIdx[rB])*kCh;
#pragma unroll
        for (int nt = 0; nt < 16; nt++) {
            int cA = n0 + nt*8 + 2*kq;
            float2 oA; oA.x = Oacc[nt][0]*invA; oA.y = Oacc[nt][1]*invA;
            float2 oB; oB.x = Oacc[nt][2]*invB; oB.y = Oacc[nt][3]*invB;
            *(float2*)&g_ret[baseA + cA] = oA;
            *(float2*)&g_ret[baseB + cA] = oB;
        }
        if (wid < 9 && lane < 16) {
            int row = wid*16 + lane;
            float s = rowsumA[row] + rowsumB[row];
            g_bs[(size_t)(n*4 + h)*kL + tIdx[row]] = m_r[row] + __logf(s);
        }
    }
}

// ---------------- head combine + residual + output layout ----------------
__global__ __launch_bounds__(256) void combine_kernel(
    const float* __restrict__ in, float* __restrict__ out)
{
    __shared__ float accs[256*33];
    __shared__ float probs[4*256];
    int n = blockIdx.x / 36, q = blockIdx.x % 36;
    int e0 = blockIdx.y * 32;
    int tid = threadIdx.x;

    {
        int t = q*256 + tid;
        float b0 = g_bs[(size_t)(n*4 + 0)*kL + t];
        float b1 = g_bs[(size_t)(n*4 + 1)*kL + t];
        float b2 = g_bs[(size_t)(n*4 + 2)*kL + t];
        float b3 = g_bs[(size_t)(n*4 + 3)*kL + t];
        float m = fmaxf(fmaxf(b0, b1), fmaxf(b2, b3));
        float x0 = __expf(b0 - m), x1 = __expf(b1 - m);
        float x2 = __expf(b2 - m), x3 = __expf(b3 - m);
        float sinv = 1.f / (x0 + x1 + x2 + x3);
        probs[0*256 + tid] = x0*sinv; probs[1*256 + tid] = x1*sinv;
        probs[2*256 + tid] = x2*sinv; probs[3*256 + tid] = x3*sinv;
    }
    for (int lin = tid; lin < 256*33; lin += 256) accs[lin] = 0.f;
    __syncthreads();

    for (int h = 0; h < 4; h++) {
        for (int lin = tid; lin < 256*32; lin += 256) {
            int cc = lin >> 5, e = lin & 31;
            float v = g_ret[((size_t)(n*4 + h)*kL + q*256 + cc)*kCh + e0 + e];
            accs[cc*33 + e] += probs[h*256 + cc] * v;
        }
    }
    __syncthreads();

    for (int lin = tid; lin < 32*256; lin += 256) {
        int e = lin >> 8, c = lin & 255;
        int p = (e0 + e)*36 + q;
        size_t oi = ((size_t)n*kL + p)*kCh + c;
        out[oi] = 0.1f*accs[c*33 + e] + in[oi];
    }
}

// ---------------- launch: stream-forked (capture-safe fork/join) ----------
extern "C" void kernel_launch(void* const* d_in, const int* in_sizes, int n_in,
                              void* d_out, int out_size)
{
    const float* input     = (const float*)d_in[0];
    const float* w_match   = (const float*)d_in[1];
    const float* b_match   = (const float*)d_in[2];
    const float* w_asm     = (const float*)d_in[3];
    const float* b_asm     = (const float*)d_in[4];
    const float* rotations = (const float*)d_in[5];
    float* out = (float*)d_out;

    const int CONVX_SMEM = 12384 * 16;                                  // 198144
    const int CONVY_SMEM = (2592 + 4752) * 16;                          // 117504
    const int ATT_SMEM   = (144*QRS + 64*KCS + 72*VSTR + 144*PSTR + 144*3 + 432) * 4;

    static cudaStream_t sY = nullptr;
    static cudaEvent_t evFork = nullptr, evJoin = nullptr;
    if (sY == nullptr) {
        cudaStreamCreateWithFlags(&sY, cudaStreamNonBlocking);
        cudaEventCreateWithFlags(&evFork, cudaEventDisableTiming);
        cudaEventCreateWithFlags(&evJoin, cudaEventDisableTiming);
        cudaFuncSetAttribute(convx_mma_kernel, cudaFuncAttributeMaxDynamicSharedMemorySize, CONVX_SMEM);
        cudaFuncSetAttribute(convy_mma_kernel, cudaFuncAttributeMaxDynamicSharedMemorySize, CONVY_SMEM);
        cudaFuncSetAttribute(attn_kernel,      cudaFuncAttributeMaxDynamicSharedMemorySize, ATT_SMEM);
    }

    // fork: y-arm (prep_wy -> convy) on sY, independent of x-arm until attn
    cudaEventRecord(evFork, 0);
    cudaStreamWaitEvent(sY, evFork, 0);

    // x-arm on stream 0
    prep_in_kernel<<<kN*kL*64/256, 256>>>(input);
    prep_wx_kernel<<<144, 256>>>(w_match);
    // y-arm on sY (submissions 3 & 4 -> convy stays in ncu capture slot 4)
    prep_wy_kernel<<<576, 256, 0, sY>>>(w_asm);
    convy_mma_kernel<<<dim3(kN*36, 4), 512, CONVY_SMEM, sY>>>(input, b_asm);
    cudaEventRecord(evJoin, sY);
    // x-arm continues
    convx_mma_kernel<<<kN*72, 256, CONVX_SMEM>>>(input, b_match);
    hash_kernel<<<kN*kL/8, 256>>>(rotations);
    sortA_kernel<<<kN*144, 256>>>();
    sortBC_kernel<<<kN*144, 256>>>();
    // join: attn needs g_y from the y-arm
    cudaStreamWaitEvent(0, evJoin, 0);
    attn_kernel<<<kN*256, ATHR, ATT_SMEM>>>();
    combine_kernel<<<dim3(kN*36, 8), 256>>>(input, out);
}

// round 12
// speedup vs baseline: 1.1214x; 1.1165x over previous
#include <cuda_runtime.h>
#include <math.h>

// Problem constants
#define kN 4
#define kH 96
#define kW 96
#define kCh 256
#define kC 64
#define kL 9216          // 96*96
#define kNH 4
#define kHB 64           // hash buckets
#define kCHK 144
#define kTOTJ 36864      // kNH*kL
#define kJW 432          // 3*kCHK

// smem strides (attn)
#define QRS 68
#define KP2S 76          // float2 col stride for K pair layout (76 mod 16 = 12, CF)
#define VP2S 260         // float2 e stride for V pair layout (260 mod 16 = 4, CF)
#define PSTR 76
#define ATHR 576

// conv packed layouts
#define WNY 66           // float4 row stride for packed weights in smem

__device__ __forceinline__ float cvt_tf32(float f) {
    unsigned r; asm("cvt.rna.tf32.f32 %0,%1;" : "=r"(r) : "f"(f));
    return __uint_as_float(r);
}
__device__ __forceinline__ float trunc13(float f) {
    return __uint_as_float(__float_as_uint(f) & 0xFFFFE000u);
}
__device__ __forceinline__ void mma_tf32(float* d, const unsigned* a, unsigned b0, unsigned b1) {
    asm("mma.sync.aligned.m16n8k8.row.col.f32.tf32.tf32.f32 "
        "{%0,%1,%2,%3},{%4,%5,%6,%7},{%8,%9},{%0,%1,%2,%3};"
        : "+f"(d[0]), "+f"(d[1]), "+f"(d[2]), "+f"(d[3])
        : "r"(a[0]), "r"(a[1]), "r"(a[2]), "r"(a[3]), "r"(b0), "r"(b1));
}
__device__ __forceinline__ void cp16(float4* dst, const float4* src) {
    unsigned s = (unsigned)__cvta_generic_to_shared(dst);
    asm volatile("cp.async.cg.shared.global [%0],[%1],16;" :: "r"(s), "l"(src));
}
__device__ __forceinline__ void cp_commit() { asm volatile("cp.async.commit_group;"); }
__device__ __forceinline__ void cp_wait1() { asm volatile("cp.async.wait_group 1;"); }
__device__ __forceinline__ void cp_wait0() { asm volatile("cp.async.wait_group 0;"); }

// -------- scratch (device globals; no allocation allowed) --------
__device__ float g_x[(size_t)kN*kL*kC];            // x_embed (n,t,f)
__device__ float g_y[(size_t)kN*kL*kCh];           // y_embed (n,t,e)
__device__ int   g_codes[kN*kTOTJ];
__device__ int   g_sorted[kN*kTOTJ];
__device__ int   g_hist[kN*144*256];
__device__ float g_ret[(size_t)kN*kNH*kL*kCh];     // attention out (n,h,t,e)
__device__ float g_bs[kN*kNH*kL];                  // lse (n,h,t)
// prepacked operands
__device__ float4 g_wyp[4*16*36*64];               // convy weights [cog][sl][r][nn]
__device__ float4 g_wxh[16*36*64];                 // convx weights hi
__device__ float4 g_wxl[16*36*64];                 // convx weights lo
__device__ float  g_xil[(size_t)kN*kL*kCh];        // input lo = v - trunc13(v)

// ---------------- prepack kernels ----------------
__global__ __launch_bounds__(256) void prep_in_kernel(const float* __restrict__ in)
{
    size_t i = (size_t)blockIdx.x*256 + threadIdx.x;   // f4 index
    float4 v = ((const float4*)in)[i];
    float4 vl;
    vl.x = v.x - trunc13(v.x);
    vl.y = v.y - trunc13(v.y);
    vl.z = v.z - trunc13(v.z);
    vl.w = v.w - trunc13(v.w);
    ((float4*)g_xil)[i] = vl;
}

__global__ __launch_bounds__(256) void prep_wx_kernel(const float* __restrict__ w)
{
    int i = blockIdx.x*256 + threadIdx.x;              // < 36864
    int nn = i & 63;
    int r  = (i >> 6) % 36;
    int sl = i / 2304;
    int tap = r >> 2, kq4 = r & 3;
    int cin = sl*16 + 4*kq4;
    const float* wp = &w[(tap*kCh + cin)*kC + nn];
    float f0 = wp[0], f1 = wp[kC], f2 = wp[2*kC], f3 = wp[3*kC];
    float4 vh, vl;
    vh.x = cvt_tf32(f0); vl.x = f0 - vh.x;
    vh.y = cvt_tf32(f1); vl.y = f1 - vh.y;
    vh.z = cvt_tf32(f2); vl.z = f2 - vh.z;
    vh.w = cvt_tf32(f3); vl.w = f3 - vh.w;
    g_wxh[i] = vh; g_wxl[i] = vl;
}

__global__ __launch_bounds__(256) void prep_wy_kernel(const float* __restrict__ w)
{
    int i = blockIdx.x*256 + threadIdx.x;              // < 4*36864
    int j = i % 36864;
    int cog = i / 36864;
    int nn = j & 63;
    int r  = (j >> 6) % 36;
    int sl = j / 2304;
    int tap = r >> 2, kq4 = r & 3;
    int cin = sl*16 + 4*kq4;
    const float* wp = &w[(size_t)(tap*kCh + cin)*kCh + cog*64 + nn];
    float4 v;
    v.x = wp[0]; v.y = wp[kCh]; v.z = wp[2*kCh]; v.w = wp[3*kCh];
    g_wyp[i] = v;
}

// ---------------- match conv (x path), 3xTF32 MMA, cp.async double-buffer --
__global__ __launch_bounds__(256, 1) void convx_mma_kernel(
    const float* __restrict__ in, const float* __restrict__ bias)
{
    extern __shared__ float4 smx[];
    float4* pH[2] = {smx,        smx + 720};
    float4* pL[2] = {smx + 1440, smx + 2160};
    float4* wH[2] = {smx + 2880, smx + 2880 + 2376};
    float4* wL[2] = {smx + 7632, smx + 7632 + 2376};

    int n    = blockIdx.x / 72;
    int tile = blockIdx.x % 72;
    int by = (tile / 6) * 8, bx = (tile % 6) * 16;
    int tid = threadIdx.x;
    int wid = tid >> 5, lane = tid & 31;
    int m0w = (wid >> 1) * 32;
    int n0w = (wid & 1) * 32;
    int kq = lane & 3, nq = lane >> 2;

    int p_goff[3];
#pragma unroll
    for (int i = 0; i < 3; i++) {
        int lin = tid + i*256;
        p_goff[i] = -1;
        if (lin < 720) {
            int pos = lin >> 2, kq4 = lin & 3;
            int yy = pos / 18, xx = pos % 18;
            int hh = by + yy - 1, ww = bx + xx - 1;
            if (hh >= 0 && hh < kH && ww >= 0 && ww < kW)
                p_goff[i] = (((n*kH + hh)*kW + ww) << 8) + 4*kq4;
        }
    }
#pragma unroll
    for (int i = 0; i < 3; i++) {
        int lin = tid + i*256;
        if (lin < 720 && p_goff[i] < 0) {
            float4 z = {0.f,0.f,0.f,0.f};
            pH[0][lin] = z; pH[1][lin] = z;
            pL[0][lin] = z; pL[1][lin] = z;
        }
    }

    float acc[8][4];
#pragma unroll
    for (int i = 0; i < 8; i++)
#pragma unroll
        for (int j = 0; j < 4; j++) acc[i][j] = 0.f;

    int pb[4];
#pragma unroll
    for (int t = 0; t < 4; t++) {
        int m = m0w + t*8 + nq;
        pb[t] = (m >> 4)*18 + (m & 15);
    }

    auto stage = [&](int sl, int buf) {
#pragma unroll
        for (int i = 0; i < 3; i++) {
            int lin = tid + i*256;
            if (lin < 720 && p_goff[i] >= 0) {
                cp16(&pH[buf][lin], (const float4*)&in[p_goff[i] + sl*16]);
                cp16(&pL[buf][lin], (const float4*)&g_xil[p_goff[i] + sl*16]);
            }
        }
#pragma unroll
        for (int i = 0; i < 9; i++) {
            int lin = tid + i*256;
            int r = lin >> 6, nn = lin & 63;
            int didx = r*WNY + nn;
            int sidx = sl*2304 + lin;
            cp16(&wH[buf][didx], &g_wxh[sidx]);
            cp16(&wL[buf][didx], &g_wxl[sidx]);
        }
    };

    stage(0, 0); cp_commit();
    for (int sl = 0; sl < 16; sl++) {
        int buf = sl & 1;
        if (sl < 15) { stage(sl + 1, buf ^ 1); cp_commit(); cp_wait1(); }
        else cp_wait0();
        __syncthreads();
        float4* p4h = pH[buf]; float4* p4l = pL[buf];
        float4* w4h = wH[buf]; float4* w4l = wL[buf];

#pragma unroll
        for (int tap = 0; tap < 9; tap++) {
            int posoff = (tap/3)*18 + (tap%3);
            float4 ah[4], al[4];
#pragma unroll
            for (int t = 0; t < 4; t++) {
                int o = (pb[t] + posoff)*4 + kq;
                ah[t] = p4h[o]; al[t] = p4l[o];
            }
            unsigned Ah00[4] = {__float_as_uint(ah[0].x), __float_as_uint(ah[1].x),
                                __float_as_uint(ah[0].y), __float_as_uint(ah[1].y)};
            unsigned Ah01[4] = {__float_as_uint(ah[0].z), __float_as_uint(ah[1].z),
                                __float_as_uint(ah[0].w), __float_as_uint(ah[1].w)};
            unsigned Ah10[4] = {__float_as_uint(ah[2].x), __float_as_uint(ah[3].x),
                                __float_as_uint(ah[2].y), __float_as_uint(ah[3].y)};
            unsigned Ah11[4] = {__float_as_uint(ah[2].z), __float_as_uint(ah[3].z),
                                __float_as_uint(ah[2].w), __float_as_uint(ah[3].w)};
            unsigned Al00[4] = {__float_as_uint(al[0].x), __float_as_uint(al[1].x),
                                __float_as_uint(al[0].y), __float_as_uint(al[1].y)};
            unsigned Al01[4] = {__float_as_uint(al[0].z), __float_as_uint(al[1].z),
                                __float_as_uint(al[0].w), __float_as_uint(al[1].w)};
            unsigned Al10[4] = {__float_as_uint(al[2].x), __float_as_uint(al[3].x),
                                __float_as_uint(al[2].y), __float_as_uint(al[3].y)};
            unsigned Al11[4] = {__float_as_uint(al[2].z), __float_as_uint(al[3].z),
                                __float_as_uint(al[2].w), __float_as_uint(al[3].w)};
            int wr = (tap*4 + kq)*WNY + n0w + nq;
#pragma unroll
            for (int nt = 0; nt < 4; nt++) {
                float4 bh = w4h[wr + nt*8];
                float4 bl = w4l[wr + nt*8];
                unsigned bhx = __float_as_uint(bh.x), bhy = __float_as_uint(bh.y);
                unsigned bhz = __float_as_uint(bh.z), bhw = __float_as_uint(bh.w);
                unsigned blx = __float_as_uint(bl.x), bly = __float_as_uint(bl.y);
                unsigned blz = __float_as_uint(bl.z), blw = __float_as_uint(bl.w);
                mma_tf32(acc[nt], Ah00, bhx, bhy);
                mma_tf32(acc[nt], Ah01, bhz, bhw);
                mma_tf32(acc[nt], Ah00, blx, bly);
                mma_tf32(acc[nt], Ah01, blz, blw);
                mma_tf32(acc[nt], Al00, bhx, bhy);
                mma_tf32(acc[nt], Al01, bhz, bhw);
                mma_tf32(acc[4+nt], Ah10, bhx, bhy);
                mma_tf32(acc[4+nt], Ah11, bhz, bhw);
                mma_tf32(acc[4+nt], Ah10, blx, bly);
                mma_tf32(acc[4+nt], Ah11, blz, blw);
                mma_tf32(acc[4+nt], Al10, bhx, bhy);
                mma_tf32(acc[4+nt], Al11, bhz, bhw);
            }
        }
        __syncthreads();
    }

#pragma unroll
    for (int mt = 0; mt < 2; mt++) {
#pragma unroll
        for (int half = 0; half < 2; half++) {
            int m = m0w + mt*16 + half*8 + nq;
            int py = by + (m >> 4), px = bx + (m & 15);
            int p = py*kW + px;
            int f = p / 144, pm = p % 144;
#pragma unroll
            for (int nt = 0; nt < 4; nt++) {
                int c = n0w + nt*8 + 2*kq;
                float v0 = acc[mt*4 + nt][half*2]     + bias[c];
                float v1 = acc[mt*4 + nt][half*2 + 1] + bias[c+1];
                g_x[((size_t)n*kL + pm*64 + c    )*kC + f] = v0;
                g_x[((size_t)n*kL + pm*64 + c + 1)*kC + f] = v1;
            }
        }
    }
}

// ---------------- asm conv (y path), tf32 MMA, 512 thr, double buffer ------
__global__ __launch_bounds__(512, 1) void convy_mma_kernel(
    const float* __restrict__ in, const float* __restrict__ bias)
{
    extern __shared__ float4 smy[];
    float4* pB[2] = {smy,        smy + 1296};
    float4* wB[2] = {smy + 2592, smy + 2592 + 2376};

    int n    = blockIdx.x / 36;
    int tile = blockIdx.x % 36;
    int by = (tile / 6) * 16, bx = (tile % 6) * 16;
    int cog = blockIdx.y;
    int co0 = cog * 64;
    int tid = threadIdx.x;
    int wid = tid >> 5, lane = tid & 31;
    int m0w = (wid >> 1) * 32;
    int n0w = (wid & 1) * 32;
    int kq = lane & 3;
    int nq = lane >> 2;

    int p_goff[3];
#pragma unroll
    for (int i = 0; i < 3; i++) {
        int lin = tid + i*512;
        p_goff[i] = -1;
        if (lin < 1296) {
            int pos = lin >> 2, kq4 = lin & 3;
            int yy = pos / 18, xx = pos % 18;
            int hh = by + yy - 1, ww = bx + xx - 1;
            if (hh >= 0 && hh < kH && ww >= 0 && ww < kW)
                p_goff[i] = (((n*kH + hh)*kW + ww) << 8) + 4*kq4;
        }
    }
#pragma unroll
    for (int i = 0; i < 3; i++) {
        int lin = tid + i*512;
        if (lin < 1296 && p_goff[i] < 0) {
            float4 z = {0.f,0.f,0.f,0.f};
            pB[0][lin] = z; pB[1][lin] = z;
        }
    }

    float acc[8][4];
#pragma unroll
    for (int i = 0; i < 8; i++)
#pragma unroll
        for (int j = 0; j < 4; j++) acc[i][j] = 0.f;

    int pb[4];
#pragma unroll
    for (int t = 0; t < 4; t++) {
        int m = m0w + t*8 + nq;
        pb[t] = (m >> 4)*18 + (m & 15);
    }

    const float4* wsrc = &g_wyp[cog*36864];

    auto stage = [&](int sl, int buf) {
#pragma unroll
        for (int i = 0; i < 3; i++) {
            int lin = tid + i*512;
            if (lin < 1296 && p_goff[i] >= 0)
                cp16(&pB[buf][lin], (const float4*)&in[p_goff[i] + sl*16]);
        }
#pragma unroll
        for (int i = 0; i < 5; i++) {
            int lin = tid + i*512;
            if (lin < 2304)
                cp16(&wB[buf][(lin >> 6)*WNY + (lin & 63)], &wsrc[sl*2304 + lin]);
        }
    };

    stage(0, 0); cp_commit();
    for (int sl = 0; sl < 16; sl++) {
        int buf = sl & 1;
        if (sl < 15) { stage(sl + 1, buf ^ 1); cp_commit(); cp_wait1(); }
        else cp_wait0();
        __syncthreads();
        float4* patch4 = pB[buf];
        float4* wtp4   = wB[buf];

#pragma unroll
        for (int tap = 0; tap < 9; tap++) {
            int posoff = (tap/3)*18 + (tap%3);
            float4 a4[4];
#pragma unroll
            for (int t = 0; t < 4; t++)
                a4[t] = patch4[(pb[t] + posoff)*4 + kq];
            unsigned A0[2][4], A1[2][4];
#pragma unroll
            for (int mt = 0; mt < 2; mt++) {
                A0[mt][0] = __float_as_uint(a4[2*mt].x);
                A0[mt][1] = __float_as_uint(a4[2*mt+1].x);
                A0[mt][2] = __float_as_uint(a4[2*mt].y);
                A0[mt][3] = __float_as_uint(a4[2*mt+1].y);
                A1[mt][0] = __float_as_uint(a4[2*mt].z);
                A1[mt][1] = __float_as_uint(a4[2*mt+1].z);
                A1[mt][2] = __float_as_uint(a4[2*mt].w);
                A1[mt][3] = __float_as_uint(a4[2*mt+1].w);
            }
            int wr = (tap*4 + kq)*WNY + n0w + nq;
#pragma unroll
            for (int nt = 0; nt < 4; nt++) {
                float4 b4 = wtp4[wr + nt*8];
                unsigned bx0 = __float_as_uint(b4.x), by0 = __float_as_uint(b4.y);
                unsigned bz0 = __float_as_uint(b4.z), bw0 = __float_as_uint(b4.w);
#pragma unroll
                for (int mt = 0; mt < 2; mt++) {
                    mma_tf32(acc[mt*4 + nt], A0[mt], bx0, by0);
                    mma_tf32(acc[mt*4 + nt], A1[mt], bz0, bw0);
                }
            }
        }
        __syncthreads();
    }

#pragma unroll
    for (int mt = 0; mt < 2; mt++) {
#pragma unroll
        for (int half = 0; half < 2; half++) {
            int m = m0w + mt*16 + half*8 + nq;
            int py = by + (m >> 4), px = bx + (m & 15);
            int p = py*kW + px;
            int e = p / 36, pm = p % 36;
#pragma unroll
            for (int nt = 0; nt < 4; nt++) {
                int c = co0 + n0w + nt*8 + 2*kq;
                float v0 = acc[mt*4 + nt][half*2]     + bias[c];
                float v1 = acc[mt*4 + nt][half*2 + 1] + bias[c+1];
                g_y[((size_t)n*kL + pm*256 + c    )*kCh + e] = v0;
                g_y[((size_t)n*kL + pm*256 + c + 1)*kCh + e] = v1;
            }
        }
    }
}

// ---------------- LSH hashing ----------------
__global__ __launch_bounds__(256) void hash_kernel(const float* __restrict__ rot)
{
    __shared__ float Rsm[8192];
    __shared__ float xrow[8][64];
    int tid = threadIdx.x;
    for (int lin = tid; lin < 8192; lin += 256) Rsm[lin] = rot[lin];
    int wid = tid >> 5, lane = tid & 31;
    int idx = blockIdx.x*8 + wid;
    int n = idx / kL, t = idx % kL;
    const float* xr = &g_x[((size_t)n*kL + t)*kC];
    xrow[wid][lane]      = xr[lane];
    xrow[wid][lane + 32] = xr[lane + 32];
    __syncthreads();
#pragma unroll
    for (int h = 0; h < 4; h++) {
        float s = 0.f;
#pragma unroll
        for (int f = 0; f < 64; f++) s += xrow[wid][f] * Rsm[f*128 + h*32 + lane];
        float bv; int bi;
        if (s >= -s) { bv = s;  bi = lane; }
        else         { bv = -s; bi = lane + 32; }
#pragma unroll
        for (int off = 16; off > 0; off >>= 1) {
            float ov = __shfl_xor_sync(0xffffffffu, bv, off);
            int   oi = __shfl_xor_sync(0xffffffffu, bi, off);
            if (ov > bv || (ov == bv && oi < bi)) { bv = ov; bi = oi; }
        }
        if (lane == 0) g_codes[n*kTOTJ + h*kL + t] = bi + h*kHB;
    }
}

// ---------------- stable counting sort (argsort) ----------------
__global__ __launch_bounds__(256) void sortA_kernel()
{
    __shared__ int hist[256];
    int b = blockIdx.x; int n = b / 144, blk = b % 144; int tid = threadIdx.x;
    hist[tid] = 0; __syncthreads();
    int code = g_codes[n*kTOTJ + blk*256 + tid];
    atomicAdd(&hist[code], 1);
    __syncthreads();
    g_hist[(n*144 + blk)*256 + tid] = hist[tid];
}

__global__ __launch_bounds__(256) void sortBC_kernel()
{
    __shared__ int scanbuf[256];
    __shared__ int comb[256];
    __shared__ int cs[256];
    int b = blockIdx.x; int n = b / 144, blk = b % 144; int v = threadIdx.x;

    int tot = 0, off = 0;
    const int* hb = &g_hist[n*144*256 + v];
    for (int bb = 0; bb < 144; bb++) {
        int hv = hb[bb*256];
        tot += hv;
        if (bb < blk) off += hv;
    }
    scanbuf[v] = tot;
    __syncthreads();
    for (int d = 1; d < 256; d <<= 1) {
        int y = (v >= d) ? scanbuf[v - d] : 0;
        __syncthreads();
        scanbuf[v] += y;
        __syncthreads();
    }
    comb[v] = (scanbuf[v] - tot) + off;
    int c = g_codes[n*kTOTJ + blk*256 + v];
    cs[v] = c;
    __syncthreads();
    int rank = 0;
    for (int j = 0; j < v; j++) rank += (cs[j] == c);
    g_sorted[n*kTOTJ + comb[c] + rank] = blk*256 + v;
}

// ---------------- fused chunk attention (tf32 MMA, pair-packed K/V) --------
__global__ __launch_bounds__(ATHR, 1) void attn_kernel()
{
    extern __shared__ float sm[];
    float* Qr  = sm;                      // 144*QRS floats
    float* Kp  = Qr + 144*QRS;            // 32*KP2S float2 = 4864 floats
    float* Vp  = Kp + 4864;               // 36*VP2S float2 = 18720 floats
    float* Psm = Vp + 18720;              // 144*PSTR floats
    float* m_r = Psm + 144*PSTR;          // 144
    float* rowsumA = m_r + 144;           // 144
    float* rowsumB = rowsumA + 144;       // 144
    int* tIdx = (int*)(rowsumB + 144);    // 432

    float2* kp2 = (float2*)Kp;
    float2* vp2 = (float2*)Vp;

    int g = blockIdx.x;
    int n = g >> 8, k = g & 255;
    int h = k >> 6, kl = k & 63;
    int tid = threadIdx.x;
    int wid = tid >> 5, lane = tid & 31;
    int kq = lane & 3, nq = lane >> 2;

    for (int j = tid; j < kJW; j += ATHR) {
        int cchunk = j / kCHK, i = j % kCHK;
        int skl = (cchunk == 0) ? kl : (cchunk == 1) ? ((kl + 63) & 63) : ((kl + 1) & 63);
        int s = (h*64 + skl)*kCHK + i;
        tIdx[j] = g_sorted[n*kTOTJ + s] % kL;
    }
    for (int i = tid; i < kCHK; i += ATHR) { rowsumA[i] = 0.f; rowsumB[i] = 0.f; }
    __syncthreads();

    {
#pragma unroll
        for (int rr = 0; rr < 8; rr++) {
            int r = wid*8 + rr;
            const float* xr = &g_x[((size_t)n*kL + tIdx[r])*kC];
            float a = xr[lane], b = xr[lane + 32];
            Qr[r*QRS + lane] = a;
            Qr[r*QRS + lane + 32] = b;
            float ss = a*a + b*b;
#pragma unroll
            for (int off = 16; off > 0; off >>= 1)
                ss += __shfl_xor_sync(0xffffffffu, ss, off);
            if (lane == 0) m_r[r] = ss * rsqrtf(fmaxf(ss, 5e-5f));
        }
    }
    __syncthreads();

    int wq = wid % 9;
    int halfq = wid / 9;
    int m0 = wq * 16;
    float mA = m_r[m0 + nq], mB = m_r[m0 + 8 + nq];

    float Oacc[16][4];
#pragma unroll
    for (int i = 0; i < 16; i++)
#pragma unroll
        for (int j = 0; j < 4; j++) Oacc[i][j] = 0.f;

    for (int jc = 0; jc < 6; jc++) {
        int j0 = jc*72;
        if (wid < 9) {
            // normalized K in pair layout: kp2[(ks*4+kq)*KP2S + col] = (K[8ks+kq][col], K[8ks+4+kq][col])
            int col = wid*8 + (lane >> 2);
            int fq = lane & 3;
            int fs = fq * 16;
            const float4* xr = (const float4*)&g_x[((size_t)n*kL + tIdx[j0 + col])*kC + fs];
            float4 v0 = xr[0], v1 = xr[1], v2 = xr[2], v3 = xr[3];
            float ss = v0.x*v0.x + v0.y*v0.y + v0.z*v0.z + v0.w*v0.w
                     + v1.x*v1.x + v1.y*v1.y + v1.z*v1.z + v1.w*v1.w
                     + v2.x*v2.x + v2.y*v2.y + v2.z*v2.z + v2.w*v2.w
                     + v3.x*v3.x + v3.y*v3.y + v3.z*v3.z + v3.w*v3.w;
            ss += __shfl_xor_sync(0xffffffffu, ss, 1);
            ss += __shfl_xor_sync(0xffffffffu, ss, 2);
            float r = rsqrtf(fmaxf(ss, 5e-5f));
            int ks0 = fq * 2;
            float2 t0; t0.x = v0.x*r; t0.y = v1.x*r; kp2[((ks0)*4 + 0)*KP2S + col] = t0;
            float2 t1; t1.x = v0.y*r; t1.y = v1.y*r; kp2[((ks0)*4 + 1)*KP2S + col] = t1;
            float2 t2; t2.x = v0.z*r; t2.y = v1.z*r; kp2[((ks0)*4 + 2)*KP2S + col] = t2;
            float2 t3; t3.x = v0.w*r; t3.y = v1.w*r; kp2[((ks0)*4 + 3)*KP2S + col] = t3;
            float2 t4; t4.x = v2.x*r; t4.y = v3.x*r; kp2[((ks0+1)*4 + 0)*KP2S + col] = t4;
            float2 t5; t5.x = v2.y*r; t5.y = v3.y*r; kp2[((ks0+1)*4 + 1)*KP2S + col] = t5;
            float2 t6; t6.x = v2.z*r; t6.y = v3.z*r; kp2[((ks0+1)*4 + 2)*KP2S + col] = t6;
            float2 t7; t7.x = v2.w*r; t7.y = v3.w*r; kp2[((ks0+1)*4 + 3)*KP2S + col] = t7;
        } else {
            // V in pair layout: vp2[(ks*4+kq)*VP2S + e] = (V[8ks+kq][e], V[8ks+4+kq][e])
            int w2 = wid - 9;     // = ks
#pragma unroll
            for (int rr = 0; rr < 4; rr++) {
                const float4* yA = (const float4*)&g_y[((size_t)n*kL + tIdx[j0 + w2*8 + rr])*kCh];
                const float4* yB = (const float4*)&g_y[((size_t)n*kL + tIdx[j0 + w2*8 + rr + 4])*kCh];
                float4 a1 = yA[lane], a2 = yA[lane + 32];
                float4 b1 = yB[lane], b2 = yB[lane + 32];
                int base = (w2*4 + rr)*VP2S;
                float2 p0; p0.x = a1.x; p0.y = b1.x; vp2[base + lane*4 + 0] = p0;
                float2 p1; p1.x = a1.y; p1.y = b1.y; vp2[base + lane*4 + 1] = p1;
                float2 p2; p2.x = a1.z; p2.y = b1.z; vp2[base + lane*4 + 2] = p2;
                float2 p3; p3.x = a1.w; p3.y = b1.w; vp2[base + lane*4 + 3] = p3;
                float2 p4; p4.x = a2.x; p4.y = b2.x; vp2[base + (lane+32)*4 + 0] = p4;
                float2 p5; p5.x = a2.y; p5.y = b2.y; vp2[base + (lane+32)*4 + 1] = p5;
                float2 p6; p6.x = a2.z; p6.y = b2.z; vp2[base + (lane+32)*4 + 2] = p6;
                float2 p7; p7.x = a2.w; p7.y = b2.w; vp2[base + (lane+32)*4 + 3] = p7;
            }
        }
        __syncthreads();

        // QK MMA + exp + Psm write
        {
            unsigned Af[8][4];
#pragma unroll
            for (int ks = 0; ks < 8; ks++) {
                const float* q0 = &Qr[(m0 + nq)*QRS + ks*8 + kq];
                const float* q1 = &Qr[(m0 + 8 + nq)*QRS + ks*8 + kq];
                Af[ks][0] = __float_as_uint(q0[0]);
                Af[ks][1] = __float_as_uint(q1[0]);
                Af[ks][2] = __float_as_uint(q0[4]);
                Af[ks][3] = __float_as_uint(q1[4]);
            }
            float s0 = 0.f, s1 = 0.f;
            int ntBeg = halfq ? 5 : 0;
            int ntEnd = halfq ? 9 : 5;
            for (int nt = ntBeg; nt < ntEnd; nt++) {
                float acc[4] = {0.f, 0.f, 0.f, 0.f};
#pragma unroll
                for (int ks = 0; ks < 8; ks++) {
                    float2 bp = kp2[(ks*4 + kq)*KP2S + nt*8 + nq];
                    mma_tf32(acc, Af[ks], __float_as_uint(bp.x), __float_as_uint(bp.y));
                }
                float e0 = __expf(acc[0] - mA), e1 = __expf(acc[1] - mA);
                float e2 = __expf(acc[2] - mB), e3 = __expf(acc[3] - mB);
                s0 += e0 + e1; s1 += e2 + e3;
                float2 pA; pA.x = e0; pA.y = e1;
                float2 pB2; pB2.x = e2; pB2.y = e3;
                *(float2*)&Psm[(m0 + nq)*PSTR + nt*8 + 2*kq] = pA;
                *(float2*)&Psm[(m0 + 8 + nq)*PSTR + nt*8 + 2*kq] = pB2;
            }
            s0 += __shfl_xor_sync(0xffffffffu, s0, 1);
            s0 += __shfl_xor_sync(0xffffffffu, s0, 2);
            s1 += __shfl_xor_sync(0xffffffffu, s1, 1);
            s1 += __shfl_xor_sync(0xffffffffu, s1, 2);
            if (kq == 0) {
                float* rs = halfq ? rowsumB : rowsumA;
                rs[m0 + nq] += s0;
                rs[m0 + 8 + nq] += s1;
            }
        }
        __syncthreads();

        // PV MMA
        {
            int n0 = halfq * 128;
#pragma unroll
            for (int ks = 0; ks < 9; ks++) {
                unsigned A[4];
                const float* p0 = &Psm[(m0 + nq)*PSTR + ks*8 + kq];
                const float* p1 = &Psm[(m0 + 8 + nq)*PSTR + ks*8 + kq];
                A[0] = __float_as_uint(p0[0]);
                A[1] = __float_as_uint(p1[0]);
                A[2] = __float_as_uint(p0[4]);
                A[3] = __float_as_uint(p1[4]);
                const float2* vb = &vp2[(ks*4 + kq)*VP2S + n0 + nq];
#pragma unroll
                for (int nt = 0; nt < 16; nt++) {
                    float2 bp = vb[nt*8];
                    mma_tf32(Oacc[nt], A, __float_as_uint(bp.x), __float_as_uint(bp.y));
                }
            }
        }
        __syncthreads();
    }

    {
        int n0 = halfq * 128;
        int rA = m0 + nq, rB = rA + 8;
        float sumA = rowsumA[rA] + rowsumB[rA];
        float sumB = rowsumA[rB] + rowsumB[rB];
        float invA = 1.f / sumA;
        float invB = 1.f / sumB;
        size_t baseA = ((size_t)(n*4 + h)*kL + tIdx[rA])*kCh;
        size_t baseB = ((size_t)(n*4 + h)*kL + tIdx[rB])*kCh;
#pragma unroll
        for (int nt = 0; nt < 16; nt++) {
            int cA = n0 + nt*8 + 2*kq;
            float2 oA; oA.x = Oacc[nt][0]*invA; oA.y = Oacc[nt][1]*invA;
            float2 oB; oB.x = Oacc[nt][2]*invB; oB.y = Oacc[nt][3]*invB;
            *(float2*)&g_ret[baseA + cA] = oA;
            *(float2*)&g_ret[baseB + cA] = oB;
        }
        if (wid < 9 && lane < 16) {
            int row = wid*16 + lane;
            float s = rowsumA[row] + rowsumB[row];
            g_bs[(size_t)(n*4 + h)*kL + tIdx[row]] = m_r[row] + __logf(s);
        }
    }
}

// ---------------- head combine + residual + output layout ----------------
__global__ __launch_bounds__(256) void combine_kernel(
    const float* __restrict__ in, float* __restrict__ out)
{
    __shared__ float accs[256*33];
    __shared__ float probs[4*256];
    int n = blockIdx.x / 36, q = blockIdx.x % 36;
    int e0 = blockIdx.y * 32;
    int tid = threadIdx.x;

    {
        int t = q*256 + tid;
        float b0 = g_bs[(size_t)(n*4 + 0)*kL + t];
        float b1 = g_bs[(size_t)(n*4 + 1)*kL + t];
        float b2 = g_bs[(size_t)(n*4 + 2)*kL + t];
        float b3 = g_bs[(size_t)(n*4 + 3)*kL + t];
        float m = fmaxf(fmaxf(b0, b1), fmaxf(b2, b3));
        float x0 = __expf(b0 - m), x1 = __expf(b1 - m);
        float x2 = __expf(b2 - m), x3 = __expf(b3 - m);
        float sinv = 1.f / (x0 + x1 + x2 + x3);
        probs[0*256 + tid] = x0*sinv; probs[1*256 + tid] = x1*sinv;
        probs[2*256 + tid] = x2*sinv; probs[3*256 + tid] = x3*sinv;
    }
    for (int lin = tid; lin < 256*33; lin += 256) accs[lin] = 0.f;
    __syncthreads();

    for (int h = 0; h < 4; h++) {
        for (int lin = tid; lin < 256*32; lin += 256) {
            int cc = lin >> 5, e = lin & 31;
            float v = g_ret[((size_t)(n*4 + h)*kL + q*256 + cc)*kCh + e0 + e];
            accs[cc*33 + e] += probs[h*256 + cc] * v;
        }
    }
    __syncthreads();

    for (int lin = tid; lin < 32*256; lin += 256) {
        int e = lin >> 8, c = lin & 255;
        int p = (e0 + e)*36 + q;
        size_t oi = ((size_t)n*kL + p)*kCh + c;
        out[oi] = 0.1f*accs[c*33 + e] + in[oi];
    }
}

// ---------------- launch: stream-forked (capture-safe fork/join) ----------
extern "C" void kernel_launch(void* const* d_in, const int* in_sizes, int n_in,
                              void* d_out, int out_size)
{
    const float* input     = (const float*)d_in[0];
    const float* w_match   = (const float*)d_in[1];
    const float* b_match   = (const float*)d_in[2];
    const float* w_asm     = (const float*)d_in[3];
    const float* b_asm     = (const float*)d_in[4];
    const float* rotations = (const float*)d_in[5];
    float* out = (float*)d_out;

    const int CONVX_SMEM = 12384 * 16;                                  // 198144
    const int CONVY_SMEM = (2592 + 4752) * 16;                          // 117504
    const int ATT_SMEM   = (144*QRS + 4864 + 18720 + 144*PSTR + 144*3 + 432) * 4;

    static cudaStream_t sY = nullptr;
    static cudaEvent_t evFork = nullptr, evJoin = nullptr;
    if (sY == nullptr) {
        cudaStreamCreateWithFlags(&sY, cudaStreamNonBlocking);
        cudaEventCreateWithFlags(&evFork, cudaEventDisableTiming);
        cudaEventCreateWithFlags(&evJoin, cudaEventDisableTiming);
        cudaFuncSetAttribute(convx_mma_kernel, cudaFuncAttributeMaxDynamicSharedMemorySize, CONVX_SMEM);
        cudaFuncSetAttribute(convy_mma_kernel, cudaFuncAttributeMaxDynamicSharedMemorySize, CONVY_SMEM);
        cudaFuncSetAttribute(attn_kernel,      cudaFuncAttributeMaxDynamicSharedMemorySize, ATT_SMEM);
    }

    cudaEventRecord(evFork, 0);
    cudaStreamWaitEvent(sY, evFork, 0);

    prep_in_kernel<<<kN*kL*64/256, 256>>>(input);
    prep_wx_kernel<<<144, 256>>>(w_match);
    prep_wy_kernel<<<576, 256, 0, sY>>>(w_asm);
    convy_mma_kernel<<<dim3(kN*36, 4), 512, CONVY_SMEM, sY>>>(input, b_asm);
    cudaEventRecord(evJoin, sY);
    convx_mma_kernel<<<kN*72, 256, CONVX_SMEM>>>(input, b_match);
    hash_kernel<<<kN*kL/8, 256>>>(rotations);
    sortA_kernel<<<kN*144, 256>>>();
    sortBC_kernel<<<kN*144, 256>>>();
    cudaStreamWaitEvent(0, evJoin, 0);
    attn_kernel<<<kN*256, ATHR, ATT_SMEM>>>();
    combine_kernel<<<dim3(kN*36, 8), 256>>>(input, out);
}

// round 13
// speedup vs baseline: 1.2682x; 1.1309x over previous
#include <cuda_runtime.h>
#include <cuda_bf16.h>
#include <math.h>

// Problem constants
#define kN 4
#define kH 96
#define kW 96
#define kCh 256
#define kC 64
#define kL 9216          // 96*96
#define kNH 4
#define kHB 64           // hash buckets
#define kCHK 144
#define kTOTJ 36864      // kNH*kL
#define kJW 432          // 3*kCHK

// smem strides (attn)
#define QRS 68
#define KP2S 76          // float2 col stride for K pair layout
#define VP2S 260         // float2 e stride for V pair layout
#define PSTR 76
#define ATHR 576

// conv packed layouts
#define WNY 66           // float4 row stride, convx weights
#define WYS 68           // uint2 row stride, convy bf16 weights (CF)

__device__ __forceinline__ float cvt_tf32(float f) {
    unsigned r; asm("cvt.rna.tf32.f32 %0,%1;" : "=r"(r) : "f"(f));
    return __uint_as_float(r);
}
__device__ __forceinline__ float trunc13(float f) {
    return __uint_as_float(__float_as_uint(f) & 0xFFFFE000u);
}
__device__ __forceinline__ unsigned pack_bf2(float lo, float hi) {
    __nv_bfloat162 t = __floats2bfloat162_rn(lo, hi);
    return *(unsigned*)&t;
}
__device__ __forceinline__ void mma_tf32(float* d, const unsigned* a, unsigned b0, unsigned b1) {
    asm("mma.sync.aligned.m16n8k8.row.col.f32.tf32.tf32.f32 "
        "{%0,%1,%2,%3},{%4,%5,%6,%7},{%8,%9},{%0,%1,%2,%3};"
        : "+f"(d[0]), "+f"(d[1]), "+f"(d[2]), "+f"(d[3])
        : "r"(a[0]), "r"(a[1]), "r"(a[2]), "r"(a[3]), "r"(b0), "r"(b1));
}
__device__ __forceinline__ void mma_bf16(float* d, const unsigned* a, unsigned b0, unsigned b1) {
    asm("mma.sync.aligned.m16n8k16.row.col.f32.bf16.bf16.f32 "
        "{%0,%1,%2,%3},{%4,%5,%6,%7},{%8,%9},{%0,%1,%2,%3};"
        : "+f"(d[0]), "+f"(d[1]), "+f"(d[2]), "+f"(d[3])
        : "r"(a[0]), "r"(a[1]), "r"(a[2]), "r"(a[3]), "r"(b0), "r"(b1));
}
__device__ __forceinline__ void cp16(void* dst, const void* src) {
    unsigned s = (unsigned)__cvta_generic_to_shared(dst);
    asm volatile("cp.async.cg.shared.global [%0],[%1],16;" :: "r"(s), "l"(src));
}
__device__ __forceinline__ void cp_commit() { asm volatile("cp.async.commit_group;"); }
__device__ __forceinline__ void cp_wait1() { asm volatile("cp.async.wait_group 1;"); }
__device__ __forceinline__ void cp_wait0() { asm volatile("cp.async.wait_group 0;"); }

// -------- scratch (device globals; no allocation allowed) --------
__device__ float g_x[(size_t)kN*kL*kC];            // x_embed (n,t,f)
__device__ float g_y[(size_t)kN*kL*kCh];           // y_embed (n,t,e)
__device__ int   g_codes[kN*kTOTJ];
__device__ int   g_sorted[kN*kTOTJ];
__device__ int   g_hist[kN*144*256];
__device__ float g_ret[(size_t)kN*kNH*kL*kCh];     // attention out (n,h,t,e)
__device__ float g_bs[kN*kNH*kL];                  // lse (n,h,t)
// prepacked operands
__device__ uint2  g_wybf[4*16*36*64];              // convy bf16 weights [cog][sl][r][nn]
__device__ uint2  g_inbf[(size_t)kN*kL*64];        // input bf16 pairs [pix][sl][kq]
__device__ float4 g_wxh[16*36*64];                 // convx weights hi
__device__ float4 g_wxl[16*36*64];                 // convx weights lo
__device__ float  g_xil[(size_t)kN*kL*kCh];        // input lo = v - trunc13(v)

// ---------------- prepack kernels ----------------
__global__ __launch_bounds__(256) void prep_in_kernel(const float* __restrict__ in)
{
    size_t i = (size_t)blockIdx.x*256 + threadIdx.x;   // f4 index
    float4 v = ((const float4*)in)[i];
    float4 vl;
    vl.x = v.x - trunc13(v.x);
    vl.y = v.y - trunc13(v.y);
    vl.z = v.z - trunc13(v.z);
    vl.w = v.w - trunc13(v.w);
    ((float4*)g_xil)[i] = vl;
}

// bf16 pair layout for m16n8k16 A: g_inbf[pix*64 + sl*4 + kq] = (cin cs+2kq,+1 | cs+2kq+8,+9)
__global__ __launch_bounds__(256) void prep_inbf_kernel(const float* __restrict__ in)
{
    size_t i = (size_t)blockIdx.x*256 + threadIdx.x;   // uint2 index
    int kq = (int)(i & 3);
    int sl = (int)((i >> 2) & 15);
    size_t pix = i >> 6;
    const float* p = &in[pix*256 + sl*16 + 2*kq];
    uint2 o;
    o.x = pack_bf2(p[0], p[1]);
    o.y = pack_bf2(p[8], p[9]);
    g_inbf[i] = o;
}

__global__ __launch_bounds__(256) void prep_wx_kernel(const float* __restrict__ w)
{
    int i = blockIdx.x*256 + threadIdx.x;              // < 36864
    int nn = i & 63;
    int r  = (i >> 6) % 36;
    int sl = i / 2304;
    int tap = r >> 2, kq4 = r & 3;
    int cin = sl*16 + 4*kq4;
    const float* wp = &w[(tap*kCh + cin)*kC + nn];
    float f0 = wp[0], f1 = wp[kC], f2 = wp[2*kC], f3 = wp[3*kC];
    float4 vh, vl;
    vh.x = cvt_tf32(f0); vl.x = f0 - vh.x;
    vh.y = cvt_tf32(f1); vl.y = f1 - vh.y;
    vh.z = cvt_tf32(f2); vl.z = f2 - vh.z;
    vh.w = cvt_tf32(f3); vl.w = f3 - vh.w;
    g_wxh[i] = vh; g_wxl[i] = vl;
}

// convy weights bf16: g_wybf[cog*36864 + sl*2304 + r*64 + nn], r = tap*4+kq
__global__ __launch_bounds__(256) void prep_wybf_kernel(const float* __restrict__ w)
{
    int i = blockIdx.x*256 + threadIdx.x;              // < 4*36864
    int nn = i & 63;
    int r  = (i >> 6) % 36;
    int sl = (i >> 6) / 36 % 16;
    int cog = i / 36864;
    int tap = r >> 2, kq = r & 3;
    int cin = sl*16 + 2*kq;
    const float* wp = &w[(size_t)(tap*kCh + cin)*kCh + cog*64 + nn];
    uint2 o;
    o.x = pack_bf2(wp[0], wp[kCh]);                    // k = 2kq, 2kq+1
    o.y = pack_bf2(wp[8*kCh], wp[9*kCh]);              // k = 2kq+8, 2kq+9
    g_wybf[i] = o;
}

// ---------------- match conv (x path), 3xTF32 MMA, cp.async double-buffer --
__global__ __launch_bounds__(256, 1) void convx_mma_kernel(
    const float* __restrict__ in, const float* __restrict__ bias)
{
    extern __shared__ float4 smx[];
    float4* pH[2] = {smx,        smx + 720};
    float4* pL[2] = {smx + 1440, smx + 2160};
    float4* wH[2] = {smx + 2880, smx + 2880 + 2376};
    float4* wL[2] = {smx + 7632, smx + 7632 + 2376};

    int n    = blockIdx.x / 72;
    int tile = blockIdx.x % 72;
    int by = (tile / 6) * 8, bx = (tile % 6) * 16;
    int tid = threadIdx.x;
    int wid = tid >> 5, lane = tid & 31;
    int m0w = (wid >> 1) * 32;
    int n0w = (wid & 1) * 32;
    int kq = lane & 3, nq = lane >> 2;

    int p_goff[3];
#pragma unroll
    for (int i = 0; i < 3; i++) {
        int lin = tid + i*256;
        p_goff[i] = -1;
        if (lin < 720) {
            int pos = lin >> 2, kq4 = lin & 3;
            int yy = pos / 18, xx = pos % 18;
            int hh = by + yy - 1, ww = bx + xx - 1;
            if (hh >= 0 && hh < kH && ww >= 0 && ww < kW)
                p_goff[i] = (((n*kH + hh)*kW + ww) << 8) + 4*kq4;
        }
    }
#pragma unroll
    for (int i = 0; i < 3; i++) {
        int lin = tid + i*256;
        if (lin < 720 && p_goff[i] < 0) {
            float4 z = {0.f,0.f,0.f,0.f};
            pH[0][lin] = z; pH[1][lin] = z;
            pL[0][lin] = z; pL[1][lin] = z;
        }
    }

    float acc[8][4];
#pragma unroll
    for (int i = 0; i < 8; i++)
#pragma unroll
        for (int j = 0; j < 4; j++) acc[i][j] = 0.f;

    int pb[4];
#pragma unroll
    for (int t = 0; t < 4; t++) {
        int m = m0w + t*8 + nq;
        pb[t] = (m >> 4)*18 + (m & 15);
    }

    auto stage = [&](int sl, int buf) {
#pragma unroll
        for (int i = 0; i < 3; i++) {
            int lin = tid + i*256;
            if (lin < 720 && p_goff[i] >= 0) {
                cp16(&pH[buf][lin], &in[p_goff[i] + sl*16]);
                cp16(&pL[buf][lin], &g_xil[p_goff[i] + sl*16]);
            }
        }
#pragma unroll
        for (int i = 0; i < 9; i++) {
            int lin = tid + i*256;
            int r = lin >> 6, nn = lin & 63;
            int didx = r*WNY + nn;
            int sidx = sl*2304 + lin;
            cp16(&wH[buf][didx], &g_wxh[sidx]);
            cp16(&wL[buf][didx], &g_wxl[sidx]);
        }
    };

    stage(0, 0); cp_commit();
    for (int sl = 0; sl < 16; sl++) {
        int buf = sl & 1;
        if (sl < 15) { stage(sl + 1, buf ^ 1); cp_commit(); cp_wait1(); }
        else cp_wait0();
        __syncthreads();
        float4* p4h = pH[buf]; float4* p4l = pL[buf];
        float4* w4h = wH[buf]; float4* w4l = wL[buf];

#pragma unroll
        for (int tap = 0; tap < 9; tap++) {
            int posoff = (tap/3)*18 + (tap%3);
            float4 ah[4], al[4];
#pragma unroll
            for (int t = 0; t < 4; t++) {
                int o = (pb[t] + posoff)*4 + kq;
                ah[t] = p4h[o]; al[t] = p4l[o];
            }
            unsigned Ah00[4] = {__float_as_uint(ah[0].x), __float_as_uint(ah[1].x),
                                __float_as_uint(ah[0].y), __float_as_uint(ah[1].y)};
            unsigned Ah01[4] = {__float_as_uint(ah[0].z), __float_as_uint(ah[1].z),
                                __float_as_uint(ah[0].w), __float_as_uint(ah[1].w)};
            unsigned Ah10[4] = {__float_as_uint(ah[2].x), __float_as_uint(ah[3].x),
                                __float_as_uint(ah[2].y), __float_as_uint(ah[3].y)};
            unsigned Ah11[4] = {__float_as_uint(ah[2].z), __float_as_uint(ah[3].z),
                                __float_as_uint(ah[2].w), __float_as_uint(ah[3].w)};
            unsigned Al00[4] = {__float_as_uint(al[0].x), __float_as_uint(al[1].x),
                                __float_as_uint(al[0].y), __float_as_uint(al[1].y)};
            unsigned Al01[4] = {__float_as_uint(al[0].z), __float_as_uint(al[1].z),
                                __float_as_uint(al[0].w), __float_as_uint(al[1].w)};
            unsigned Al10[4] = {__float_as_uint(al[2].x), __float_as_uint(al[3].x),
                                __float_as_uint(al[2].y), __float_as_uint(al[3].y)};
            unsigned Al11[4] = {__float_as_uint(al[2].z), __float_as_uint(al[3].z),
                                __float_as_uint(al[2].w), __float_as_uint(al[3].w)};
            int wr = (tap*4 + kq)*WNY + n0w + nq;
#pragma unroll
            for (int nt = 0; nt < 4; nt++) {
                float4 bh = w4h[wr + nt*8];
                float4 bl = w4l[wr + nt*8];
                unsigned bhx = __float_as_uint(bh.x), bhy = __float_as_uint(bh.y);
                unsigned bhz = __float_as_uint(bh.z), bhw = __float_as_uint(bh.w);
                unsigned blx = __float_as_uint(bl.x), bly = __float_as_uint(bl.y);
                unsigned blz = __float_as_uint(bl.z), blw = __float_as_uint(bl.w);
                mma_tf32(acc[nt], Ah00, bhx, bhy);
                mma_tf32(acc[nt], Ah01, bhz, bhw);
                mma_tf32(acc[nt], Ah00, blx, bly);
                mma_tf32(acc[nt], Ah01, blz, blw);
                mma_tf32(acc[nt], Al00, bhx, bhy);
                mma_tf32(acc[nt], Al01, bhz, bhw);
                mma_tf32(acc[4+nt], Ah10, bhx, bhy);
                mma_tf32(acc[4+nt], Ah11, bhz, bhw);
                mma_tf32(acc[4+nt], Ah10, blx, bly);
                mma_tf32(acc[4+nt], Ah11, blz, blw);
                mma_tf32(acc[4+nt], Al10, bhx, bhy);
                mma_tf32(acc[4+nt], Al11, bhz, bhw);
            }
        }
        __syncthreads();
    }

#pragma unroll
    for (int mt = 0; mt < 2; mt++) {
#pragma unroll
        for (int half = 0; half < 2; half++) {
            int m = m0w + mt*16 + half*8 + nq;
            int py = by + (m >> 4), px = bx + (m & 15);
            int p = py*kW + px;
            int f = p / 144, pm = p % 144;
#pragma unroll
            for (int nt = 0; nt < 4; nt++) {
                int c = n0w + nt*8 + 2*kq;
                float v0 = acc[mt*4 + nt][half*2]     + bias[c];
                float v1 = acc[mt*4 + nt][half*2 + 1] + bias[c+1];
                g_x[((size_t)n*kL + pm*64 + c    )*kC + f] = v0;
                g_x[((size_t)n*kL + pm*64 + c + 1)*kC + f] = v1;
            }
        }
    }
}

// ---------------- asm conv (y path), bf16 m16n8k16 MMA, double buffer ------
// block tile: 256 pixels (16x16) x 64 cout. 16 warps, warp M=32, N=32.
__global__ __launch_bounds__(512, 1) void convy_mma_kernel(const float* __restrict__ bias)
{
    extern __shared__ uint2 smy2[];
    uint2* pB[2] = {smy2,        smy2 + 1296};        // 324 pos x 4 kq
    uint2* wB[2] = {smy2 + 2592, smy2 + 2592 + 2448}; // 36 r x WYS

    int n    = blockIdx.x / 36;
    int tile = blockIdx.x % 36;
    int by = (tile / 6) * 16, bx = (tile % 6) * 16;
    int cog = blockIdx.y;
    int co0 = cog * 64;
    int tid = threadIdx.x;
    int wid = tid >> 5, lane = tid & 31;
    int m0w = (wid >> 1) * 32;
    int n0w = (wid & 1) * 32;
    int kq = lane & 3;
    int nq = lane >> 2;

    // patch staging offsets: 648 cp16 (pos, kq-half)
    long long p_gidx[2];
#pragma unroll
    for (int i = 0; i < 2; i++) {
        int lin = tid + i*512;
        p_gidx[i] = -1;
        if (lin < 648) {
            int pos = lin >> 1;
            int yy = pos / 18, xx = pos % 18;
            int hh = by + yy - 1, ww = bx + xx - 1;
            if (hh >= 0 && hh < kH && ww >= 0 && ww < kW)
                p_gidx[i] = ((long long)((n*kH + hh)*kW + ww))*64 + (lin & 1)*2;
        }
    }
#pragma unroll
    for (int i = 0; i < 2; i++) {
        int lin = tid + i*512;
        if (lin < 648 && p_gidx[i] < 0) {
            uint2 z = {0u, 0u};
            int d = (lin >> 1)*4 + (lin & 1)*2;
            pB[0][d] = z; pB[0][d+1] = z;
            pB[1][d] = z; pB[1][d+1] = z;
        }
    }

    float acc[8][4];
#pragma unroll
    for (int i = 0; i < 8; i++)
#pragma unroll
        for (int j = 0; j < 4; j++) acc[i][j] = 0.f;

    int pb[4];
#pragma unroll
    for (int t = 0; t < 4; t++) {
        int m = m0w + t*8 + nq;
        pb[t] = (m >> 4)*18 + (m & 15);
    }

    const uint2* wsrc = &g_wybf[cog*36864];

    auto stage = [&](int sl, int buf) {
#pragma unroll
        for (int i = 0; i < 2; i++) {
            int lin = tid + i*512;
            if (lin < 648 && p_gidx[i] >= 0)
                cp16(&pB[buf][(lin >> 1)*4 + (lin & 1)*2], &g_inbf[p_gidx[i] + sl*4]);
        }
#pragma unroll
        for (int i = 0; i < 3; i++) {
            int lin = tid + i*512;
            if (lin < 1152) {
                int idx = lin*2;
                int r = idx >> 6, nn = idx & 63;
                cp16(&wB[buf][r*WYS + nn], &wsrc[sl*2304 + idx]);
            }
        }
    };

    stage(0, 0); cp_commit();
    for (int sl = 0; sl < 16; sl++) {
        int buf = sl & 1;
        if (sl < 15) { stage(sl + 1, buf ^ 1); cp_commit(); cp_wait1(); }
        else cp_wait0();
        __syncthreads();
        uint2* up2 = pB[buf];
        uint2* w2  = wB[buf];

#pragma unroll
        for (int tap = 0; tap < 9; tap++) {
            int posoff = (tap/3)*18 + (tap%3);
            uint2 aL0 = up2[(pb[0] + posoff)*4 + kq];
            uint2 aH0 = up2[(pb[1] + posoff)*4 + kq];
            uint2 aL1 = up2[(pb[2] + posoff)*4 + kq];
            uint2 aH1 = up2[(pb[3] + posoff)*4 + kq];
            unsigned A0[4] = {aL0.x, aH0.x, aL0.y, aH0.y};
            unsigned A1[4] = {aL1.x, aH1.x, aL1.y, aH1.y};
            int wr = (tap*4 + kq)*WYS + n0w + nq;
#pragma unroll
            for (int nt = 0; nt < 4; nt++) {
                uint2 bw = w2[wr + nt*8];
                mma_bf16(acc[nt],     A0, bw.x, bw.y);
                mma_bf16(acc[4 + nt], A1, bw.x, bw.y);
            }
        }
        __syncthreads();
    }

#pragma unroll
    for (int mt = 0; mt < 2; mt++) {
#pragma unroll
        for (int half = 0; half < 2; half++) {
            int m = m0w + mt*16 + half*8 + nq;
            int py = by + (m >> 4), px = bx + (m & 15);
            int p = py*kW + px;
            int e = p / 36, pm = p % 36;
#pragma unroll
            for (int nt = 0; nt < 4; nt++) {
                int c = co0 + n0w + nt*8 + 2*kq;
                float v0 = acc[mt*4 + nt][half*2]     + bias[c];
                float v1 = acc[mt*4 + nt][half*2 + 1] + bias[c+1];
                g_y[((size_t)n*kL + pm*256 + c    )*kCh + e] = v0;
                g_y[((size_t)n*kL + pm*256 + c + 1)*kCh + e] = v1;
            }
        }
    }
}

// ---------------- LSH hashing ----------------
__global__ __launch_bounds__(256) void hash_kernel(const float* __restrict__ rot)
{
    __shared__ float Rsm[8192];
    __shared__ float xrow[8][64];
    int tid = threadIdx.x;
    for (int lin = tid; lin < 8192; lin += 256) Rsm[lin] = rot[lin];
    int wid = tid >> 5, lane = tid & 31;
    int idx = blockIdx.x*8 + wid;
    int n = idx / kL, t = idx % kL;
    const float* xr = &g_x[((size_t)n*kL + t)*kC];
    xrow[wid][lane]      = xr[lane];
    xrow[wid][lane + 32] = xr[lane + 32];
    __syncthreads();
#pragma unroll
    for (int h = 0; h < 4; h++) {
        float s = 0.f;
#pragma unroll
        for (int f = 0; f < 64; f++) s += xrow[wid][f] * Rsm[f*128 + h*32 + lane];
        float bv; int bi;
        if (s >= -s) { bv = s;  bi = lane; }
        else         { bv = -s; bi = lane + 32; }
#pragma unroll
        for (int off = 16; off > 0; off >>= 1) {
            float ov = __shfl_xor_sync(0xffffffffu, bv, off);
            int   oi = __shfl_xor_sync(0xffffffffu, bi, off);
            if (ov > bv || (ov == bv && oi < bi)) { bv = ov; bi = oi; }
        }
        if (lane == 0) g_codes[n*kTOTJ + h*kL + t] = bi + h*kHB;
    }
}

// ---------------- stable counting sort (argsort) ----------------
__global__ __launch_bounds__(256) void sortA_kernel()
{
    __shared__ int hist[256];
    int b = blockIdx.x; int n = b / 144, blk = b % 144; int tid = threadIdx.x;
    hist[tid] = 0; __syncthreads();
    int code = g_codes[n*kTOTJ + blk*256 + tid];
    atomicAdd(&hist[code], 1);
    __syncthreads();
    g_hist[(n*144 + blk)*256 + tid] = hist[tid];
}

__global__ __launch_bounds__(256) void sortBC_kernel()
{
    __shared__ int scanbuf[256];
    __shared__ int comb[256];
    __shared__ int cs[256];
    int b = blockIdx.x; int n = b / 144, blk = b % 144; int v = threadIdx.x;

    int tot = 0, off = 0;
    const int* hb = &g_hist[n*144*256 + v];
    for (int bb = 0; bb < 144; bb++) {
        int hv = hb[bb*256];
        tot += hv;
        if (bb < blk) off += hv;
    }
    scanbuf[v] = tot;
    __syncthreads();
    for (int d = 1; d < 256; d <<= 1) {
        int y = (v >= d) ? scanbuf[v - d] : 0;
        __syncthreads();
        scanbuf[v] += y;
        __syncthreads();
    }
    comb[v] = (scanbuf[v] - tot) + off;
    int c = g_codes[n*kTOTJ + blk*256 + v];
    cs[v] = c;
    __syncthreads();
    int rank = 0;
    for (int j = 0; j < v; j++) rank += (cs[j] == c);
    g_sorted[n*kTOTJ + comb[c] + rank] = blk*256 + v;
}

// ---------------- fused chunk attention (tf32 MMA, pair-packed K/V) --------
__global__ __launch_bounds__(ATHR, 1) void attn_kernel()
{
    extern __shared__ float sm[];
    float* Qr  = sm;                      // 144*QRS floats
    float* Kp  = Qr + 144*QRS;            // 32*KP2S float2 = 4864 floats
    float* Vp  = Kp + 4864;               // 36*VP2S float2 = 18720 floats
    float* Psm = Vp + 18720;              // 144*PSTR floats
    float* m_r = Psm + 144*PSTR;          // 144
    float* rowsumA = m_r + 144;           // 144
    float* rowsumB = rowsumA + 144;       // 144
    int* tIdx = (int*)(rowsumB + 144);    // 432

    float2* kp2 = (float2*)Kp;
    float2* vp2 = (float2*)Vp;

    int g = blockIdx.x;
    int n = g >> 8, k = g & 255;
    int h = k >> 6, kl = k & 63;
    int tid = threadIdx.x;
    int wid = tid >> 5, lane = tid & 31;
    int kq = lane & 3, nq = lane >> 2;

    for (int j = tid; j < kJW; j += ATHR) {
        int cchunk = j / kCHK, i = j % kCHK;
        int skl = (cchunk == 0) ? kl : (cchunk == 1) ? ((kl + 63) & 63) : ((kl + 1) & 63);
        int s = (h*64 + skl)*kCHK + i;
        tIdx[j] = g_sorted[n*kTOTJ + s] % kL;
    }
    for (int i = tid; i < kCHK; i += ATHR) { rowsumA[i] = 0.f; rowsumB[i] = 0.f; }
    __syncthreads();

    {
#pragma unroll
        for (int rr = 0; rr < 8; rr++) {
            int r = wid*8 + rr;
            const float* xr = &g_x[((size_t)n*kL + tIdx[r])*kC];
            float a = xr[lane], b = xr[lane + 32];
            Qr[r*QRS + lane] = a;
            Qr[r*QRS + lane + 32] = b;
            float ss = a*a + b*b;
#pragma unroll
            for (int off = 16; off > 0; off >>= 1)
                ss += __shfl_xor_sync(0xffffffffu, ss, off);
            if (lane == 0) m_r[r] = ss * rsqrtf(fmaxf(ss, 5e-5f));
        }
    }
    __syncthreads();

    int wq = wid % 9;
    int halfq = wid / 9;
    int m0 = wq * 16;
    float mA = m_r[m0 + nq], mB = m_r[m0 + 8 + nq];

    float Oacc[16][4];
#pragma unroll
    for (int i = 0; i < 16; i++)
#pragma unroll
        for (int j = 0; j < 4; j++) Oacc[i][j] = 0.f;

    for (int jc = 0; jc < 6; jc++) {
        int j0 = jc*72;
        if (wid < 9) {
            int col = wid*8 + (lane >> 2);
            int fq = lane & 3;
            int fs = fq * 16;
            const float4* xr = (const float4*)&g_x[((size_t)n*kL + tIdx[j0 + col])*kC + fs];
            float4 v0 = xr[0], v1 = xr[1], v2 = xr[2], v3 = xr[3];
            float ss = v0.x*v0.x + v0.y*v0.y + v0.z*v0.z + v0.w*v0.w
                     + v1.x*v1.x + v1.y*v1.y + v1.z*v1.z + v1.w*v1.w
                     + v2.x*v2.x + v2.y*v2.y + v2.z*v2.z + v2.w*v2.w
                     + v3.x*v3.x + v3.y*v3.y + v3.z*v3.z + v3.w*v3.w;
            ss += __shfl_xor_sync(0xffffffffu, ss, 1);
            ss += __shfl_xor_sync(0xffffffffu, ss, 2);
            float r = rsqrtf(fmaxf(ss, 5e-5f));
            int ks0 = fq * 2;
            float2 t0; t0.x = v0.x*r; t0.y = v1.x*r; kp2[((ks0)*4 + 0)*KP2S + col] = t0;
            float2 t1; t1.x = v0.y*r; t1.y = v1.y*r; kp2[((ks0)*4 + 1)*KP2S + col] = t1;
            float2 t2; t2.x = v0.z*r; t2.y = v1.z*r; kp2[((ks0)*4 + 2)*KP2S + col] = t2;
            float2 t3; t3.x = v0.w*r; t3.y = v1.w*r; kp2[((ks0)*4 + 3)*KP2S + col] = t3;
            float2 t4; t4.x = v2.x*r; t4.y = v3.x*r; kp2[((ks0+1)*4 + 0)*KP2S + col] = t4;
            float2 t5; t5.x = v2.y*r; t5.y = v3.y*r; kp2[((ks0+1)*4 + 1)*KP2S + col] = t5;
            float2 t6; t6.x = v2.z*r; t6.y = v3.z*r; kp2[((ks0+1)*4 + 2)*KP2S + col] = t6;
            float2 t7; t7.x = v2.w*r; t7.y = v3.w*r; kp2[((ks0+1)*4 + 3)*KP2S + col] = t7;
        } else {
            int w2 = wid - 9;
#pragma unroll
            for (int rr = 0; rr < 4; rr++) {
                const float4* yA = (const float4*)&g_y[((size_t)n*kL + tIdx[j0 + w2*8 + rr])*kCh];
                const float4* yB = (const float4*)&g_y[((size_t)n*kL + tIdx[j0 + w2*8 + rr + 4])*kCh];
                float4 a1 = yA[lane], a2 = yA[lane + 32];
                float4 b1 = yB[lane], b2 = yB[lane + 32];
                int base = (w2*4 + rr)*VP2S;
                float2 p0; p0.x = a1.x; p0.y = b1.x; vp2[base + lane*4 + 0] = p0;
                float2 p1; p1.x = a1.y; p1.y = b1.y; vp2[base + lane*4 + 1] = p1;
                float2 p2; p2.x = a1.z; p2.y = b1.z; vp2[base + lane*4 + 2] = p2;
                float2 p3; p3.x = a1.w; p3.y = b1.w; vp2[base + lane*4 + 3] = p3;
                float2 p4; p4.x = a2.x; p4.y = b2.x; vp2[base + (lane+32)*4 + 0] = p4;
                float2 p5; p5.x = a2.y; p5.y = b2.y; vp2[base + (lane+32)*4 + 1] = p5;
                float2 p6; p6.x = a2.z; p6.y = b2.z; vp2[base + (lane+32)*4 + 2] = p6;
                float2 p7; p7.x = a2.w; p7.y = b2.w; vp2[base + (lane+32)*4 + 3] = p7;
            }
        }
        __syncthreads();

        {
            unsigned Af[8][4];
#pragma unroll
            for (int ks = 0; ks < 8; ks++) {
                const float* q0 = &Qr[(m0 + nq)*QRS + ks*8 + kq];
                const float* q1 = &Qr[(m0 + 8 + nq)*QRS + ks*8 + kq];
                Af[ks][0] = __float_as_uint(q0[0]);
                Af[ks][1] = __float_as_uint(q1[0]);
                Af[ks][2] = __float_as_uint(q0[4]);
                Af[ks][3] = __float_as_uint(q1[4]);
            }
            float s0 = 0.f, s1 = 0.f;
            int ntBeg = halfq ? 5 : 0;
            int ntEnd = halfq ? 9 : 5;
            for (int nt = ntBeg; nt < ntEnd; nt++) {
                float acc[4] = {0.f, 0.f, 0.f, 0.f};
#pragma unroll
                for (int ks = 0; ks < 8; ks++) {
                    float2 bp = kp2[(ks*4 + kq)*KP2S + nt*8 + nq];
                    mma_tf32(acc, Af[ks], __float_as_uint(bp.x), __float_as_uint(bp.y));
                }
                float e0 = __expf(acc[0] - mA), e1 = __expf(acc[1] - mA);
                float e2 = __expf(acc[2] - mB), e3 = __expf(acc[3] - mB);
                s0 += e0 + e1; s1 += e2 + e3;
                float2 pA; pA.x = e0; pA.y = e1;
                float2 pB2; pB2.x = e2; pB2.y = e3;
                *(float2*)&Psm[(m0 + nq)*PSTR + nt*8 + 2*kq] = pA;
                *(float2*)&Psm[(m0 + 8 + nq)*PSTR + nt*8 + 2*kq] = pB2;
            }
            s0 += __shfl_xor_sync(0xffffffffu, s0, 1);
            s0 += __shfl_xor_sync(0xffffffffu, s0, 2);
            s1 += __shfl_xor_sync(0xffffffffu, s1, 1);
            s1 += __shfl_xor_sync(0xffffffffu, s1, 2);
            if (kq == 0) {
                float* rs = halfq ? rowsumB : rowsumA;
                rs[m0 + nq] += s0;
                rs[m0 + 8 + nq] += s1;
            }
        }
        __syncthreads();

        {
            int n0 = halfq * 128;
#pragma unroll
            for (int ks = 0; ks < 9; ks++) {
                unsigned A[4];
                const float* p0 = &Psm[(m0 + nq)*PSTR + ks*8 + kq];
                const float* p1 = &Psm[(m0 + 8 + nq)*PSTR + ks*8 + kq];
                A[0] = __float_as_uint(p0[0]);
                A[1] = __float_as_uint(p1[0]);
                A[2] = __float_as_uint(p0[4]);
                A[3] = __float_as_uint(p1[4]);
                const float2* vb = &vp2[(ks*4 + kq)*VP2S + n0 + nq];
#pragma unroll
                for (int nt = 0; nt < 16; nt++) {
                    float2 bp = vb[nt*8];
                    mma_tf32(Oacc[nt], A, __float_as_uint(bp.x), __float_as_uint(bp.y));
                }
            }
        }
        __syncthreads();
    }

    {
        int n0 = halfq * 128;
        int rA = m0 + nq, rB = rA + 8;
        float sumA = rowsumA[rA] + rowsumB[rA];
        float sumB = rowsumA[rB] + rowsumB[rB];
        float invA = 1.f / sumA;
        float invB = 1.f / sumB;
        size_t baseA = ((size_t)(n*4 + h)*kL + tIdx[rA])*kCh;
        size_t baseB = ((size_t)(n*4 + h)*kL + tIdx[rB])*kCh;
#pragma unroll
        for (int nt = 0; nt < 16; nt++) {
            int cA = n0 + nt*8 + 2*kq;
            float2 oA; oA.x = Oacc[nt][0]*invA; oA.y = Oacc[nt][1]*invA;
            float2 oB; oB.x = Oacc[nt][2]*invB; oB.y = Oacc[nt][3]*invB;
            *(float2*)&g_ret[baseA + cA] = oA;
            *(float2*)&g_ret[baseB + cA] = oB;
        }
        if (wid < 9 && lane < 16) {
            int row = wid*16 + lane;
            float s = rowsumA[row] + rowsumB[row];
            g_bs[(size_t)(n*4 + h)*kL + tIdx[row]] = m_r[row] + __logf(s);
        }
    }
}

// ---------------- head combine + residual + output layout ----------------
__global__ __launch_bounds__(256) void combine_kernel(
    const float* __restrict__ in, float* __restrict__ out)
{
    __shared__ float accs[256*33];
    __shared__ float probs[4*256];
    int n = blockIdx.x / 36, q = blockIdx.x % 36;
    int e0 = blockIdx.y * 32;
    int tid = threadIdx.x;

    {
        int t = q*256 + tid;
        float b0 = g_bs[(size_t)(n*4 + 0)*kL + t];
        float b1 = g_bs[(size_t)(n*4 + 1)*kL + t];
        float b2 = g_bs[(size_t)(n*4 + 2)*kL + t];
        float b3 = g_bs[(size_t)(n*4 + 3)*kL + t];
        float m = fmaxf(fmaxf(b0, b1), fmaxf(b2, b3));
        float x0 = __expf(b0 - m), x1 = __expf(b1 - m);
        float x2 = __expf(b2 - m), x3 = __expf(b3 - m);
        float sinv = 1.f / (x0 + x1 + x2 + x3);
        probs[0*256 + tid] = x0*sinv; probs[1*256 + tid] = x1*sinv;
        probs[2*256 + tid] = x2*sinv; probs[3*256 + tid] = x3*sinv;
    }
    for (int lin = tid; lin < 256*33; lin += 256) accs[lin] = 0.f;
    __syncthreads();

    for (int h = 0; h < 4; h++) {
        for (int lin = tid; lin < 256*32; lin += 256) {
            int cc = lin >> 5, e = lin & 31;
            float v = g_ret[((size_t)(n*4 + h)*kL + q*256 + cc)*kCh + e0 + e];
            accs[cc*33 + e] += probs[h*256 + cc] * v;
        }
    }
    __syncthreads();

    for (int lin = tid; lin < 32*256; lin += 256) {
        int e = lin >> 8, c = lin & 255;
        int p = (e0 + e)*36 + q;
        size_t oi = ((size_t)n*kL + p)*kCh + c;
        out[oi] = 0.1f*accs[c*33 + e] + in[oi];
    }
}

// ---------------- launch: stream-forked (capture-safe fork/join) ----------
extern "C" void kernel_launch(void* const* d_in, const int* in_sizes, int n_in,
                              void* d_out, int out_size)
{
    const float* input     = (const float*)d_in[0];
    const float* w_match   = (const float*)d_in[1];
    const float* b_match   = (const float*)d_in[2];
    const float* w_asm     = (const float*)d_in[3];
    const float* b_asm     = (const float*)d_in[4];
    const float* rotations = (const float*)d_in[5];
    float* out = (float*)d_out;

    const int CONVX_SMEM = 12384 * 16;                                  // 198144
    const int CONVY_SMEM = (2592 + 2448*2) * 8;                         // 59904
    const int ATT_SMEM   = (144*QRS + 4864 + 18720 + 144*PSTR + 144*3 + 432) * 4;

    static cudaStream_t sY = nullptr;
    static cudaEvent_t evFork = nullptr, evJoin = nullptr;
    if (sY == nullptr) {
        cudaStreamCreateWithFlags(&sY, cudaStreamNonBlocking);
        cudaEventCreateWithFlags(&evFork, cudaEventDisableTiming);
        cudaEventCreateWithFlags(&evJoin, cudaEventDisableTiming);
        cudaFuncSetAttribute(convx_mma_kernel, cudaFuncAttributeMaxDynamicSharedMemorySize, CONVX_SMEM);
        cudaFuncSetAttribute(convy_mma_kernel, cudaFuncAttributeMaxDynamicSharedMemorySize, CONVY_SMEM);
        cudaFuncSetAttribute(attn_kernel,      cudaFuncAttributeMaxDynamicSharedMemorySize, ATT_SMEM);
    }

    cudaEventRecord(evFork, 0);
    cudaStreamWaitEvent(sY, evFork, 0);

    prep_in_kernel<<<kN*kL*64/256, 256>>>(input);                       // s0 (#1)
    prep_inbf_kernel<<<kN*kL*64/256, 256, 0, sY>>>(input);              // sY (#2)
    prep_wybf_kernel<<<576, 256, 0, sY>>>(w_asm);                       // sY (#3)
    convy_mma_kernel<<<dim3(kN*36, 4), 512, CONVY_SMEM, sY>>>(b_asm);   // sY (#4, ncu slot)
    cudaEventRecord(evJoin, sY);
    prep_wx_kernel<<<144, 256>>>(w_match);                              // s0
    convx_mma_kernel<<<kN*72, 256, CONVX_SMEM>>>(input, b_match);
    hash_kernel<<<kN*kL/8, 256>>>(rotations);
    sortA_kernel<<<kN*144, 256>>>();
    sortBC_kernel<<<kN*144, 256>>>();
    cudaStreamWaitEvent(0, evJoin, 0);
    attn_kernel<<<kN*256, ATHR, ATT_SMEM>>>();
    combine_kernel<<<dim3(kN*36, 8), 256>>>(input, out);
}

// round 14
// speedup vs baseline: 1.3021x; 1.0267x over previous
#include <cuda_runtime.h>
#include <cuda_bf16.h>
#include <math.h>

// Problem constants
#define kN 4
#define kH 96
#define kW 96
#define kCh 256
#define kC 64
#define kL 9216          // 96*96
#define kNH 4
#define kHB 64           // hash buckets
#define kCHK 144
#define kTOTJ 36864      // kNH*kL
#define kJW 432          // 3*kCHK

// smem strides (attn)
#define QRS 68
#define KP2S 76          // float2 col stride for K pair layout
#define PU32S 44         // u32 stride for P bf16-pair rows (CF write + ldmatrix)
#define VSSU 132         // u32 stride for V bf16 rows (264 bf16; CF)
#define ATHR 576

// conv packed layouts
#define WNY 66           // float4 row stride, convx weights
#define WYS 68           // uint2 row stride, convy bf16 weights (CF)

__device__ __forceinline__ float cvt_tf32(float f) {
    unsigned r; asm("cvt.rna.tf32.f32 %0,%1;" : "=r"(r) : "f"(f));
    return __uint_as_float(r);
}
__device__ __forceinline__ float trunc13(float f) {
    return __uint_as_float(__float_as_uint(f) & 0xFFFFE000u);
}
__device__ __forceinline__ unsigned pack_bf2(float lo, float hi) {
    __nv_bfloat162 t = __floats2bfloat162_rn(lo, hi);
    return *(unsigned*)&t;
}
__device__ __forceinline__ void mma_tf32(float* d, const unsigned* a, unsigned b0, unsigned b1) {
    asm("mma.sync.aligned.m16n8k8.row.col.f32.tf32.tf32.f32 "
        "{%0,%1,%2,%3},{%4,%5,%6,%7},{%8,%9},{%0,%1,%2,%3};"
        : "+f"(d[0]), "+f"(d[1]), "+f"(d[2]), "+f"(d[3])
        : "r"(a[0]), "r"(a[1]), "r"(a[2]), "r"(a[3]), "r"(b0), "r"(b1));
}
__device__ __forceinline__ void mma_bf16(float* d, const unsigned* a, unsigned b0, unsigned b1) {
    asm("mma.sync.aligned.m16n8k16.row.col.f32.bf16.bf16.f32 "
        "{%0,%1,%2,%3},{%4,%5,%6,%7},{%8,%9},{%0,%1,%2,%3};"
        : "+f"(d[0]), "+f"(d[1]), "+f"(d[2]), "+f"(d[3])
        : "r"(a[0]), "r"(a[1]), "r"(a[2]), "r"(a[3]), "r"(b0), "r"(b1));
}
__device__ __forceinline__ void ldm_x4(unsigned* r, unsigned saddr) {
    asm volatile("ldmatrix.sync.aligned.m8n8.x4.shared.b16 {%0,%1,%2,%3},[%4];"
        : "=r"(r[0]), "=r"(r[1]), "=r"(r[2]), "=r"(r[3]) : "r"(saddr));
}
__device__ __forceinline__ void ldm_x4t(unsigned* r, unsigned saddr) {
    asm volatile("ldmatrix.sync.aligned.m8n8.x4.trans.shared.b16 {%0,%1,%2,%3},[%4];"
        : "=r"(r[0]), "=r"(r[1]), "=r"(r[2]), "=r"(r[3]) : "r"(saddr));
}
__device__ __forceinline__ void cp16(void* dst, const void* src) {
    unsigned s = (unsigned)__cvta_generic_to_shared(dst);
    asm volatile("cp.async.cg.shared.global [%0],[%1],16;" :: "r"(s), "l"(src));
}
__device__ __forceinline__ void cp_commit() { asm volatile("cp.async.commit_group;"); }
__device__ __forceinline__ void cp_wait1() { asm volatile("cp.async.wait_group 1;"); }
__device__ __forceinline__ void cp_wait0() { asm volatile("cp.async.wait_group 0;"); }

// -------- scratch (device globals; no allocation allowed) --------
__device__ float g_x[(size_t)kN*kL*kC];            // x_embed (n,t,f)
__device__ __nv_bfloat16 g_yb[(size_t)kN*kL*kCh];  // y_embed bf16 (n,t,e)
__device__ int   g_codes[kN*kTOTJ];
__device__ int   g_sorted[kN*kTOTJ];
__device__ int   g_hist[kN*144*256];
__device__ float g_ret[(size_t)kN*kNH*kL*kCh];     // attention out (n,h,t,e)
__device__ float g_bs[kN*kNH*kL];                  // lse (n,h,t)
// prepacked operands
__device__ uint2  g_wybf[4*16*36*64];              // convy bf16 weights [cog][sl][r][nn]
__device__ uint2  g_inbf[(size_t)kN*kL*64];        // input bf16 pairs [pix][sl][kq]
__device__ float4 g_wxh[16*36*64];                 // convx weights hi
__device__ float4 g_wxl[16*36*64];                 // convx weights lo
__device__ float  g_xil[(size_t)kN*kL*kCh];        // input lo = v - trunc13(v)

// ---------------- prepack kernels ----------------
__global__ __launch_bounds__(256) void prep_in_kernel(const float* __restrict__ in)
{
    size_t i = (size_t)blockIdx.x*256 + threadIdx.x;
    float4 v = ((const float4*)in)[i];
    float4 vl;
    vl.x = v.x - trunc13(v.x);
    vl.y = v.y - trunc13(v.y);
    vl.z = v.z - trunc13(v.z);
    vl.w = v.w - trunc13(v.w);
    ((float4*)g_xil)[i] = vl;
}

__global__ __launch_bounds__(256) void prep_inbf_kernel(const float* __restrict__ in)
{
    size_t i = (size_t)blockIdx.x*256 + threadIdx.x;
    int kq = (int)(i & 3);
    int sl = (int)((i >> 2) & 15);
    size_t pix = i >> 6;
    const float* p = &in[pix*256 + sl*16 + 2*kq];
    uint2 o;
    o.x = pack_bf2(p[0], p[1]);
    o.y = pack_bf2(p[8], p[9]);
    g_inbf[i] = o;
}

__global__ __launch_bounds__(256) void prep_wx_kernel(const float* __restrict__ w)
{
    int i = blockIdx.x*256 + threadIdx.x;
    int nn = i & 63;
    int r  = (i >> 6) % 36;
    int sl = i / 2304;
    int tap = r >> 2, kq4 = r & 3;
    int cin = sl*16 + 4*kq4;
    const float* wp = &w[(tap*kCh + cin)*kC + nn];
    float f0 = wp[0], f1 = wp[kC], f2 = wp[2*kC], f3 = wp[3*kC];
    float4 vh, vl;
    vh.x = cvt_tf32(f0); vl.x = f0 - vh.x;
    vh.y = cvt_tf32(f1); vl.y = f1 - vh.y;
    vh.z = cvt_tf32(f2); vl.z = f2 - vh.z;
    vh.w = cvt_tf32(f3); vl.w = f3 - vh.w;
    g_wxh[i] = vh; g_wxl[i] = vl;
}

__global__ __launch_bounds__(256) void prep_wybf_kernel(const float* __restrict__ w)
{
    int i = blockIdx.x*256 + threadIdx.x;
    int nn = i & 63;
    int r  = (i >> 6) % 36;
    int sl = (i >> 6) / 36 % 16;
    int cog = i / 36864;
    int tap = r >> 2, kq = r & 3;
    int cin = sl*16 + 2*kq;
    const float* wp = &w[(size_t)(tap*kCh + cin)*kCh + cog*64 + nn];
    uint2 o;
    o.x = pack_bf2(wp[0], wp[kCh]);
    o.y = pack_bf2(wp[8*kCh], wp[9*kCh]);
    g_wybf[i] = o;
}

// ---------------- match conv (x path), 3xTF32 MMA, cp.async double-buffer --
__global__ __launch_bounds__(256, 1) void convx_mma_kernel(
    const float* __restrict__ in, const float* __restrict__ bias)
{
    extern __shared__ float4 smx[];
    float4* pH[2] = {smx,        smx + 720};
    float4* pL[2] = {smx + 1440, smx + 2160};
    float4* wH[2] = {smx + 2880, smx + 2880 + 2376};
    float4* wL[2] = {smx + 7632, smx + 7632 + 2376};

    int n    = blockIdx.x / 72;
    int tile = blockIdx.x % 72;
    int by = (tile / 6) * 8, bx = (tile % 6) * 16;
    int tid = threadIdx.x;
    int wid = tid >> 5, lane = tid & 31;
    int m0w = (wid >> 1) * 32;
    int n0w = (wid & 1) * 32;
    int kq = lane & 3, nq = lane >> 2;

    int p_goff[3];
#pragma unroll
    for (int i = 0; i < 3; i++) {
        int lin = tid + i*256;
        p_goff[i] = -1;
        if (lin < 720) {
            int pos = lin >> 2, kq4 = lin & 3;
            int yy = pos / 18, xx = pos % 18;
            int hh = by + yy - 1, ww = bx + xx - 1;
            if (hh >= 0 && hh < kH && ww >= 0 && ww < kW)
                p_goff[i] = (((n*kH + hh)*kW + ww) << 8) + 4*kq4;
        }
    }
#pragma unroll
    for (int i = 0; i < 3; i++) {
        int lin = tid + i*256;
        if (lin < 720 && p_goff[i] < 0) {
            float4 z = {0.f,0.f,0.f,0.f};
            pH[0][lin] = z; pH[1][lin] = z;
            pL[0][lin] = z; pL[1][lin] = z;
        }
    }

    float acc[8][4];
#pragma unroll
    for (int i = 0; i < 8; i++)
#pragma unroll
        for (int j = 0; j < 4; j++) acc[i][j] = 0.f;

    int pb[4];
#pragma unroll
    for (int t = 0; t < 4; t++) {
        int m = m0w + t*8 + nq;
        pb[t] = (m >> 4)*18 + (m & 15);
    }

    auto stage = [&](int sl, int buf) {
#pragma unroll
        for (int i = 0; i < 3; i++) {
            int lin = tid + i*256;
            if (lin < 720 && p_goff[i] >= 0) {
                cp16(&pH[buf][lin], &in[p_goff[i] + sl*16]);
                cp16(&pL[buf][lin], &g_xil[p_goff[i] + sl*16]);
            }
        }
#pragma unroll
        for (int i = 0; i < 9; i++) {
            int lin = tid + i*256;
            int r = lin >> 6, nn = lin & 63;
            int didx = r*WNY + nn;
            int sidx = sl*2304 + lin;
            cp16(&wH[buf][didx], &g_wxh[sidx]);
            cp16(&wL[buf][didx], &g_wxl[sidx]);
        }
    };

    stage(0, 0); cp_commit();
    for (int sl = 0; sl < 16; sl++) {
        int buf = sl & 1;
        if (sl < 15) { stage(sl + 1, buf ^ 1); cp_commit(); cp_wait1(); }
        else cp_wait0();
        __syncthreads();
        float4* p4h = pH[buf]; float4* p4l = pL[buf];
        float4* w4h = wH[buf]; float4* w4l = wL[buf];

#pragma unroll
        for (int tap = 0; tap < 9; tap++) {
            int posoff = (tap/3)*18 + (tap%3);
            float4 ah[4], al[4];
#pragma unroll
            for (int t = 0; t < 4; t++) {
                int o = (pb[t] + posoff)*4 + kq;
                ah[t] = p4h[o]; al[t] = p4l[o];
            }
            unsigned Ah00[4] = {__float_as_uint(ah[0].x), __float_as_uint(ah[1].x),
                                __float_as_uint(ah[0].y), __float_as_uint(ah[1].y)};
            unsigned Ah01[4] = {__float_as_uint(ah[0].z), __float_as_uint(ah[1].z),
                                __float_as_uint(ah[0].w), __float_as_uint(ah[1].w)};
            unsigned Ah10[4] = {__float_as_uint(ah[2].x), __float_as_uint(ah[3].x),
                                __float_as_uint(ah[2].y), __float_as_uint(ah[3].y)};
            unsigned Ah11[4] = {__float_as_uint(ah[2].z), __float_as_uint(ah[3].z),
                                __float_as_uint(ah[2].w), __float_as_uint(ah[3].w)};
            unsigned Al00[4] = {__float_as_uint(al[0].x), __float_as_uint(al[1].x),
                                __float_as_uint(al[0].y), __float_as_uint(al[1].y)};
            unsigned Al01[4] = {__float_as_uint(al[0].z), __float_as_uint(al[1].z),
                                __float_as_uint(al[0].w), __float_as_uint(al[1].w)};
            unsigned Al10[4] = {__float_as_uint(al[2].x), __float_as_uint(al[3].x),
                                __float_as_uint(al[2].y), __float_as_uint(al[3].y)};
            unsigned Al11[4] = {__float_as_uint(al[2].z), __float_as_uint(al[3].z),
                                __float_as_uint(al[2].w), __float_as_uint(al[3].w)};
            int wr = (tap*4 + kq)*WNY + n0w + nq;
#pragma unroll
            for (int nt = 0; nt < 4; nt++) {
                float4 bh = w4h[wr + nt*8];
                float4 bl = w4l[wr + nt*8];
                unsigned bhx = __float_as_uint(bh.x), bhy = __float_as_uint(bh.y);
                unsigned bhz = __float_as_uint(bh.z), bhw = __float_as_uint(bh.w);
                unsigned blx = __float_as_uint(bl.x), bly = __float_as_uint(bl.y);
                unsigned blz = __float_as_uint(bl.z), blw = __float_as_uint(bl.w);
                mma_tf32(acc[nt], Ah00, bhx, bhy);
                mma_tf32(acc[nt], Ah01, bhz, bhw);
                mma_tf32(acc[nt], Ah00, blx, bly);
                mma_tf32(acc[nt], Ah01, blz, blw);
                mma_tf32(acc[nt], Al00, bhx, bhy);
                mma_tf32(acc[nt], Al01, bhz, bhw);
                mma_tf32(acc[4+nt], Ah10, bhx, bhy);
                mma_tf32(acc[4+nt], Ah11, bhz, bhw);
                mma_tf32(acc[4+nt], Ah10, blx, bly);
                mma_tf32(acc[4+nt], Ah11, blz, blw);
                mma_tf32(acc[4+nt], Al10, bhx, bhy);
                mma_tf32(acc[4+nt], Al11, bhz, bhw);
            }
        }
        __syncthreads();
    }

#pragma unroll
    for (int mt = 0; mt < 2; mt++) {
#pragma unroll
        for (int half = 0; half < 2; half++) {
            int m = m0w + mt*16 + half*8 + nq;
            int py = by + (m >> 4), px = bx + (m & 15);
            int p = py*kW + px;
            int f = p / 144, pm = p % 144;
#pragma unroll
            for (int nt = 0; nt < 4; nt++) {
                int c = n0w + nt*8 + 2*kq;
                float v0 = acc[mt*4 + nt][half*2]     + bias[c];
                float v1 = acc[mt*4 + nt][half*2 + 1] + bias[c+1];
                g_x[((size_t)n*kL + pm*64 + c    )*kC + f] = v0;
                g_x[((size_t)n*kL + pm*64 + c + 1)*kC + f] = v1;
            }
        }
    }
}

// ---------------- asm conv (y path), bf16 m16n8k16 MMA, double buffer ------
__global__ __launch_bounds__(512, 1) void convy_mma_kernel(const float* __restrict__ bias)
{
    extern __shared__ uint2 smy2[];
    uint2* pB[2] = {smy2,        smy2 + 1296};
    uint2* wB[2] = {smy2 + 2592, smy2 + 2592 + 2448};

    int n    = blockIdx.x / 36;
    int tile = blockIdx.x % 36;
    int by = (tile / 6) * 16, bx = (tile % 6) * 16;
    int cog = blockIdx.y;
    int co0 = cog * 64;
    int tid = threadIdx.x;
    int wid = tid >> 5, lane = tid & 31;
    int m0w = (wid >> 1) * 32;
    int n0w = (wid & 1) * 32;
    int kq = lane & 3;
    int nq = lane >> 2;

    long long p_gidx[2];
#pragma unroll
    for (int i = 0; i < 2; i++) {
        int lin = tid + i*512;
        p_gidx[i] = -1;
        if (lin < 648) {
            int pos = lin >> 1;
            int yy = pos / 18, xx = pos % 18;
            int hh = by + yy - 1, ww = bx + xx - 1;
            if (hh >= 0 && hh < kH && ww >= 0 && ww < kW)
                p_gidx[i] = ((long long)((n*kH + hh)*kW + ww))*64 + (lin & 1)*2;
        }
    }
#pragma unroll
    for (int i = 0; i < 2; i++) {
        int lin = tid + i*512;
        if (lin < 648 && p_gidx[i] < 0) {
            uint2 z = {0u, 0u};
            int d = (lin >> 1)*4 + (lin & 1)*2;
            pB[0][d] = z; pB[0][d+1] = z;
            pB[1][d] = z; pB[1][d+1] = z;
        }
    }

    float acc[8][4];
#pragma unroll
    for (int i = 0; i < 8; i++)
#pragma unroll
        for (int j = 0; j < 4; j++) acc[i][j] = 0.f;

    int pb[4];
#pragma unroll
    for (int t = 0; t < 4; t++) {
        int m = m0w + t*8 + nq;
        pb[t] = (m >> 4)*18 + (m & 15);
    }

    const uint2* wsrc = &g_wybf[cog*36864];

    auto stage = [&](int sl, int buf) {
#pragma unroll
        for (int i = 0; i < 2; i++) {
            int lin = tid + i*512;
            if (lin < 648 && p_gidx[i] >= 0)
                cp16(&pB[buf][(lin >> 1)*4 + (lin & 1)*2], &g_inbf[p_gidx[i] + sl*4]);
        }
#pragma unroll
        for (int i = 0; i < 3; i++) {
            int lin = tid + i*512;
            if (lin < 1152) {
                int idx = lin*2;
                int r = idx >> 6, nn = idx & 63;
                cp16(&wB[buf][r*WYS + nn], &wsrc[sl*2304 + idx]);
            }
        }
    };

    stage(0, 0); cp_commit();
    for (int sl = 0; sl < 16; sl++) {
        int buf = sl & 1;
        if (sl < 15) { stage(sl + 1, buf ^ 1); cp_commit(); cp_wait1(); }
        else cp_wait0();
        __syncthreads();
        uint2* up2 = pB[buf];
        uint2* w2  = wB[buf];

#pragma unroll
        for (int tap = 0; tap < 9; tap++) {
            int posoff = (tap/3)*18 + (tap%3);
            uint2 aL0 = up2[(pb[0] + posoff)*4 + kq];
            uint2 aH0 = up2[(pb[1] + posoff)*4 + kq];
            uint2 aL1 = up2[(pb[2] + posoff)*4 + kq];
            uint2 aH1 = up2[(pb[3] + posoff)*4 + kq];
            unsigned A0[4] = {aL0.x, aH0.x, aL0.y, aH0.y};
            unsigned A1[4] = {aL1.x, aH1.x, aL1.y, aH1.y};
            int wr = (tap*4 + kq)*WYS + n0w + nq;
#pragma unroll
            for (int nt = 0; nt < 4; nt++) {
                uint2 bw = w2[wr + nt*8];
                mma_bf16(acc[nt],     A0, bw.x, bw.y);
                mma_bf16(acc[4 + nt], A1, bw.x, bw.y);
            }
        }
        __syncthreads();
    }

#pragma unroll
    for (int mt = 0; mt < 2; mt++) {
#pragma unroll
        for (int half = 0; half < 2; half++) {
            int m = m0w + mt*16 + half*8 + nq;
            int py = by + (m >> 4), px = bx + (m & 15);
            int p = py*kW + px;
            int e = p / 36, pm = p % 36;
#pragma unroll
            for (int nt = 0; nt < 4; nt++) {
                int c = co0 + n0w + nt*8 + 2*kq;
                float v0 = acc[mt*4 + nt][half*2]     + bias[c];
                float v1 = acc[mt*4 + nt][half*2 + 1] + bias[c+1];
                g_yb[((size_t)n*kL + pm*256 + c    )*kCh + e] = __float2bfloat16_rn(v0);
                g_yb[((size_t)n*kL + pm*256 + c + 1)*kCh + e] = __float2bfloat16_rn(v1);
            }
        }
    }
}

// ---------------- LSH hashing ----------------
__global__ __launch_bounds__(256) void hash_kernel(const float* __restrict__ rot)
{
    __shared__ float Rsm[8192];
    __shared__ float xrow[8][64];
    int tid = threadIdx.x;
    for (int lin = tid; lin < 8192; lin += 256) Rsm[lin] = rot[lin];
    int wid = tid >> 5, lane = tid & 31;
    int idx = blockIdx.x*8 + wid;
    int n = idx / kL, t = idx % kL;
    const float* xr = &g_x[((size_t)n*kL + t)*kC];
    xrow[wid][lane]      = xr[lane];
    xrow[wid][lane + 32] = xr[lane + 32];
    __syncthreads();
#pragma unroll
    for (int h = 0; h < 4; h++) {
        float s = 0.f;
#pragma unroll
        for (int f = 0; f < 64; f++) s += xrow[wid][f] * Rsm[f*128 + h*32 + lane];
        float bv; int bi;
        if (s >= -s) { bv = s;  bi = lane; }
        else         { bv = -s; bi = lane + 32; }
#pragma unroll
        for (int off = 16; off > 0; off >>= 1) {
            float ov = __shfl_xor_sync(0xffffffffu, bv, off);
            int   oi = __shfl_xor_sync(0xffffffffu, bi, off);
            if (ov > bv || (ov == bv && oi < bi)) { bv = ov; bi = oi; }
        }
        if (lane == 0) g_codes[n*kTOTJ + h*kL + t] = bi + h*kHB;
    }
}

// ---------------- stable counting sort (argsort) ----------------
__global__ __launch_bounds__(256) void sortA_kernel()
{
    __shared__ int hist[256];
    int b = blockIdx.x; int n = b / 144, blk = b % 144; int tid = threadIdx.x;
    hist[tid] = 0; __syncthreads();
    int code = g_codes[n*kTOTJ + blk*256 + tid];
    atomicAdd(&hist[code], 1);
    __syncthreads();
    g_hist[(n*144 + blk)*256 + tid] = hist[tid];
}

__global__ __launch_bounds__(256) void sortBC_kernel()
{
    __shared__ int scanbuf[256];
    __shared__ int comb[256];
    __shared__ int cs[256];
    int b = blockIdx.x; int n = b / 144, blk = b % 144; int v = threadIdx.x;

    int tot = 0, off = 0;
    const int* hb = &g_hist[n*144*256 + v];
    for (int bb = 0; bb < 144; bb++) {
        int hv = hb[bb*256];
        tot += hv;
        if (bb < blk) off += hv;
    }
    scanbuf[v] = tot;
    __syncthreads();
    for (int d = 1; d < 256; d <<= 1) {
        int y = (v >= d) ? scanbuf[v - d] : 0;
        __syncthreads();
        scanbuf[v] += y;
        __syncthreads();
    }
    comb[v] = (scanbuf[v] - tot) + off;
    int c = g_codes[n*kTOTJ + blk*256 + v];
    cs[v] = c;
    __syncthreads();
    int rank = 0;
    for (int j = 0; j < v; j++) rank += (cs[j] == c);
    g_sorted[n*kTOTJ + comb[c] + rank] = blk*256 + v;
}

// ---------------- fused chunk attention: tf32 QK + bf16 ldmatrix PV --------
__global__ __launch_bounds__(ATHR, 1) void attn_kernel()
{
    extern __shared__ float sm[];
    float* Qr  = sm;                              // 9792 floats
    float* Kp  = Qr + 144*QRS;                    // 4864 floats (float2 pairs)
    unsigned* vs_u32  = (unsigned*)(sm + 14656);  // 80 rows x VSSU u32 (bf16 V)
    unsigned* psm_u32 = (unsigned*)(sm + 25216);  // 144 x PU32S u32 (bf16 P pairs)
    float* m_r = sm + 31552;                      // 144
    float* rowsumA = m_r + 144;                   // 144
    float* rowsumB = rowsumA + 144;               // 144
    int* tIdx = (int*)(rowsumB + 144);            // 432

    float2* kp2 = (float2*)Kp;

    int g = blockIdx.x;
    int n = g >> 8, k = g & 255;
    int h = k >> 6, kl = k & 63;
    int tid = threadIdx.x;
    int wid = tid >> 5, lane = tid & 31;
    int kq = lane & 3, nq = lane >> 2;

    for (int j = tid; j < kJW; j += ATHR) {
        int cchunk = j / kCHK, i = j % kCHK;
        int skl = (cchunk == 0) ? kl : (cchunk == 1) ? ((kl + 63) & 63) : ((kl + 1) & 63);
        int s = (h*64 + skl)*kCHK + i;
        tIdx[j] = g_sorted[n*kTOTJ + s] % kL;
    }
    for (int i = tid; i < kCHK; i += ATHR) { rowsumA[i] = 0.f; rowsumB[i] = 0.f; }
    // zero pads once: P pair cols 36..43 (all 144 rows), V rows 72..79
    for (int i = tid; i < 144*8; i += ATHR)
        psm_u32[(i >> 3)*PU32S + 36 + (i & 7)] = 0u;
    for (int i = tid; i < 8*VSSU; i += ATHR)
        vs_u32[72*VSSU + i] = 0u;
    __syncthreads();

    {
#pragma unroll
        for (int rr = 0; rr < 8; rr++) {
            int r = wid*8 + rr;
            const float* xr = &g_x[((size_t)n*kL + tIdx[r])*kC];
            float a = xr[lane], b = xr[lane + 32];
            Qr[r*QRS + lane] = a;
            Qr[r*QRS + lane + 32] = b;
            float ss = a*a + b*b;
#pragma unroll
            for (int off = 16; off > 0; off >>= 1)
                ss += __shfl_xor_sync(0xffffffffu, ss, off);
            if (lane == 0) m_r[r] = ss * rsqrtf(fmaxf(ss, 5e-5f));
        }
    }
    __syncthreads();

    int wq = wid % 9;
    int halfq = wid / 9;
    int m0 = wq * 16;
    float mA = m_r[m0 + nq], mB = m_r[m0 + 8 + nq];

    float Oacc[16][4];
#pragma unroll
    for (int i = 0; i < 16; i++)
#pragma unroll
        for (int j = 0; j < 4; j++) Oacc[i][j] = 0.f;

    // ldmatrix shared-space base addresses
    unsigned pbase = (unsigned)__cvta_generic_to_shared(psm_u32);
    unsigned vbase = (unsigned)__cvta_generic_to_shared(vs_u32);
    unsigned aaddr = pbase + (unsigned)((m0 + (lane & 15))*(PU32S*4) + (lane >> 4)*16);
    unsigned baddr = vbase + (unsigned)((lane & 15)*(VSSU*4) + ((halfq*128 + (lane >> 4)*8) << 1));

    for (int jc = 0; jc < 6; jc++) {
        int j0 = jc*72;
        if (wid < 9) {
            // normalized K in float2 pair layout (tf32 QK path)
            int col = wid*8 + (lane >> 2);
            int fq = lane & 3;
            int fs = fq * 16;
            const float4* xr = (const float4*)&g_x[((size_t)n*kL + tIdx[j0 + col])*kC + fs];
            float4 v0 = xr[0], v1 = xr[1], v2 = xr[2], v3 = xr[3];
            float ss = v0.x*v0.x + v0.y*v0.y + v0.z*v0.z + v0.w*v0.w
                     + v1.x*v1.x + v1.y*v1.y + v1.z*v1.z + v1.w*v1.w
                     + v2.x*v2.x + v2.y*v2.y + v2.z*v2.z + v2.w*v2.w
                     + v3.x*v3.x + v3.y*v3.y + v3.z*v3.z + v3.w*v3.w;
            ss += __shfl_xor_sync(0xffffffffu, ss, 1);
            ss += __shfl_xor_sync(0xffffffffu, ss, 2);
            float r = rsqrtf(fmaxf(ss, 5e-5f));
            int ks0 = fq * 2;
            float2 t0; t0.x = v0.x*r; t0.y = v1.x*r; kp2[((ks0)*4 + 0)*KP2S + col] = t0;
            float2 t1; t1.x = v0.y*r; t1.y = v1.y*r; kp2[((ks0)*4 + 1)*KP2S + col] = t1;
            float2 t2; t2.x = v0.z*r; t2.y = v1.z*r; kp2[((ks0)*4 + 2)*KP2S + col] = t2;
            float2 t3; t3.x = v0.w*r; t3.y = v1.w*r; kp2[((ks0)*4 + 3)*KP2S + col] = t3;
            float2 t4; t4.x = v2.x*r; t4.y = v3.x*r; kp2[((ks0+1)*4 + 0)*KP2S + col] = t4;
            float2 t5; t5.x = v2.y*r; t5.y = v3.y*r; kp2[((ks0+1)*4 + 1)*KP2S + col] = t5;
            float2 t6; t6.x = v2.z*r; t6.y = v3.z*r; kp2[((ks0+1)*4 + 2)*KP2S + col] = t6;
            float2 t7; t7.x = v2.w*r; t7.y = v3.w*r; kp2[((ks0+1)*4 + 3)*KP2S + col] = t7;
        } else {
            // V rows copied as bf16 (row = 512B = 32 x uint4)
            int w2 = wid - 9;
#pragma unroll
            for (int r = 0; r < 8; r++) {
                int row = w2*8 + r;
                uint4 v = ((const uint4*)&g_yb[((size_t)n*kL + tIdx[j0 + row])*kCh])[lane];
                ((uint4*)vs_u32)[row*(VSSU/4) + lane] = v;
            }
        }
        __syncthreads();

        // QK MMA (tf32) + exp + bf16 P pairs to smem
        {
            unsigned Af[8][4];
#pragma unroll
            for (int ks = 0; ks < 8; ks++) {
                const float* q0 = &Qr[(m0 + nq)*QRS + ks*8 + kq];
                const float* q1 = &Qr[(m0 + 8 + nq)*QRS + ks*8 + kq];
                Af[ks][0] = __float_as_uint(q0[0]);
                Af[ks][1] = __float_as_uint(q1[0]);
                Af[ks][2] = __float_as_uint(q0[4]);
                Af[ks][3] = __float_as_uint(q1[4]);
            }
            float s0 = 0.f, s1 = 0.f;
            int ntBeg = halfq ? 5 : 0;
            int ntEnd = halfq ? 9 : 5;
            for (int nt = ntBeg; nt < ntEnd; nt++) {
                float acc[4] = {0.f, 0.f, 0.f, 0.f};
#pragma unroll
                for (int ks = 0; ks < 8; ks++) {
                    float2 bp = kp2[(ks*4 + kq)*KP2S + nt*8 + nq];
                    mma_tf32(acc, Af[ks], __float_as_uint(bp.x), __float_as_uint(bp.y));
                }
                float e0 = __expf(acc[0] - mA), e1 = __expf(acc[1] - mA);
                float e2 = __expf(acc[2] - mB), e3 = __expf(acc[3] - mB);
                s0 += e0 + e1; s1 += e2 + e3;
                psm_u32[(m0 + nq)*PU32S + nt*4 + kq]     = pack_bf2(e0, e1);
                psm_u32[(m0 + 8 + nq)*PU32S + nt*4 + kq] = pack_bf2(e2, e3);
            }
            s0 += __shfl_xor_sync(0xffffffffu, s0, 1);
            s0 += __shfl_xor_sync(0xffffffffu, s0, 2);
            s1 += __shfl_xor_sync(0xffffffffu, s1, 1);
            s1 += __shfl_xor_sync(0xffffffffu, s1, 2);
            if (kq == 0) {
                float* rs = halfq ? rowsumB : rowsumA;
                rs[m0 + nq] += s0;
                rs[m0 + 8 + nq] += s1;
            }
        }
        __syncthreads();

        // PV MMA (bf16 m16n8k16 via ldmatrix), 5 uniform k16 groups (pads zeroed)
        {
#pragma unroll
            for (int gg = 0; gg < 5; gg++) {
                unsigned A[4];
                ldm_x4(A, aaddr + gg*32);
#pragma unroll
                for (int np = 0; np < 8; np++) {
                    unsigned B[4];
                    ldm_x4t(B, baddr + gg*16*(VSSU*4) + np*32);
                    mma_bf16(Oacc[2*np],     A, B[0], B[1]);
                    mma_bf16(Oacc[2*np + 1], A, B[2], B[3]);
                }
            }
        }
        __syncthreads();
    }

    {
        int n0 = halfq * 128;
        int rA = m0 + nq, rB = rA + 8;
        float sumA = rowsumA[rA] + rowsumB[rA];
        float sumB = rowsumA[rB] + rowsumB[rB];
        float invA = 1.f / sumA;
        float invB = 1.f / sumB;
        size_t baseA = ((size_t)(n*4 + h)*kL + tIdx[rA])*kCh;
        size_t baseB = ((size_t)(n*4 + h)*kL + tIdx[rB])*kCh;
#pragma unroll
        for (int nt = 0; nt < 16; nt++) {
            int cA = n0 + nt*8 + 2*kq;
            float2 oA; oA.x = Oacc[nt][0]*invA; oA.y = Oacc[nt][1]*invA;
            float2 oB; oB.x = Oacc[nt][2]*invB; oB.y = Oacc[nt][3]*invB;
            *(float2*)&g_ret[baseA + cA] = oA;
            *(float2*)&g_ret[baseB + cA] = oB;
        }
        if (wid < 9 && lane < 16) {
            int row = wid*16 + lane;
            float s = rowsumA[row] + rowsumB[row];
            g_bs[(size_t)(n*4 + h)*kL + tIdx[row]] = m_r[row] + __logf(s);
        }
    }
}

// ---------------- head combine + residual + output layout ----------------
__global__ __launch_bounds__(256) void combine_kernel(
    const float* __restrict__ in, float* __restrict__ out)
{
    __shared__ float accs[256*33];
    __shared__ float probs[4*256];
    int n = blockIdx.x / 36, q = blockIdx.x % 36;
    int e0 = blockIdx.y * 32;
    int tid = threadIdx.x;

    {
        int t = q*256 + tid;
        float b0 = g_bs[(size_t)(n*4 + 0)*kL + t];
        float b1 = g_bs[(size_t)(n*4 + 1)*kL + t];
        float b2 = g_bs[(size_t)(n*4 + 2)*kL + t];
        float b3 = g_bs[(size_t)(n*4 + 3)*kL + t];
        float m = fmaxf(fmaxf(b0, b1), fmaxf(b2, b3));
        float x0 = __expf(b0 - m), x1 = __expf(b1 - m);
        float x2 = __expf(b2 - m), x3 = __expf(b3 - m);
        float sinv = 1.f / (x0 + x1 + x2 + x3);
        probs[0*256 + tid] = x0*sinv; probs[1*256 + tid] = x1*sinv;
        probs[2*256 + tid] = x2*sinv; probs[3*256 + tid] = x3*sinv;
    }
    for (int lin = tid; lin < 256*33; lin += 256) accs[lin] = 0.f;
    __syncthreads();

    for (int h = 0; h < 4; h++) {
        for (int lin = tid; lin < 256*32; lin += 256) {
            int cc = lin >> 5, e = lin & 31;
            float v = g_ret[((size_t)(n*4 + h)*kL + q*256 + cc)*kCh + e0 + e];
            accs[cc*33 + e] += probs[h*256 + cc] * v;
        }
    }
    __syncthreads();

    for (int lin = tid; lin < 32*256; lin += 256) {
        int e = lin >> 8, c = lin & 255;
        int p = (e0 + e)*36 + q;
        size_t oi = ((size_t)n*kL + p)*kCh + c;
        out[oi] = 0.1f*accs[c*33 + e] + in[oi];
    }
}

// ---------------- launch: stream-forked (capture-safe fork/join) ----------
extern "C" void kernel_launch(void* const* d_in, const int* in_sizes, int n_in,
                              void* d_out, int out_size)
{
    const float* input     = (const float*)d_in[0];
    const float* w_match   = (const float*)d_in[1];
    const float* b_match   = (const float*)d_in[2];
    const float* w_asm     = (const float*)d_in[3];
    const float* b_asm     = (const float*)d_in[4];
    const float* rotations = (const float*)d_in[5];
    float* out = (float*)d_out;

    const int CONVX_SMEM = 12384 * 16;                                  // 198144
    const int CONVY_SMEM = (2592 + 2448*2) * 8;                         // 59904
    const int ATT_SMEM   = 32416 * 4;                                   // 129664

    static cudaStream_t sY = nullptr;
    static cudaEvent_t evFork = nullptr, evJoin = nullptr;
    if (sY == nullptr) {
        cudaStreamCreateWithFlags(&sY, cudaStreamNonBlocking);
        cudaEventCreateWithFlags(&evFork, cudaEventDisableTiming);
        cudaEventCreateWithFlags(&evJoin, cudaEventDisableTiming);
        cudaFuncSetAttribute(convx_mma_kernel, cudaFuncAttributeMaxDynamicSharedMemorySize, CONVX_SMEM);
        cudaFuncSetAttribute(convy_mma_kernel, cudaFuncAttributeMaxDynamicSharedMemorySize, CONVY_SMEM);
        cudaFuncSetAttribute(attn_kernel,      cudaFuncAttributeMaxDynamicSharedMemorySize, ATT_SMEM);
    }

    cudaEventRecord(evFork, 0);
    cudaStreamWaitEvent(sY, evFork, 0);

    prep_in_kernel<<<kN*kL*64/256, 256>>>(input);                       // s0 (#1)
    prep_inbf_kernel<<<kN*kL*64/256, 256, 0, sY>>>(input);              // sY (#2)
    prep_wybf_kernel<<<576, 256, 0, sY>>>(w_asm);                       // sY (#3)
    convy_mma_kernel<<<dim3(kN*36, 4), 512, CONVY_SMEM, sY>>>(b_asm);   // sY (#4, ncu slot)
    cudaEventRecord(evJoin, sY);
    prep_wx_kernel<<<144, 256>>>(w_match);                              // s0
    convx_mma_kernel<<<kN*72, 256, CONVX_SMEM>>>(input, b_match);
    hash_kernel<<<kN*kL/8, 256>>>(rotations);
    sortA_kernel<<<kN*144, 256>>>();
    sortBC_kernel<<<kN*144, 256>>>();
    cudaStreamWaitEvent(0, evJoin, 0);
    attn_kernel<<<kN*256, ATHR, ATT_SMEM>>>();
    combine_kernel<<<dim3(kN*36, 8), 256>>>(input, out);
}

// round 15
// speedup vs baseline: 1.4570x; 1.1190x over previous
#include <cuda_runtime.h>
#include <cuda_bf16.h>
#include <math.h>

// Problem constants
#define kN 4
#define kH 96
#define kW 96
#define kCh 256
#define kC 64
#define kL 9216          // 96*96
#define kNH 4
#define kHB 64           // hash buckets
#define kCHK 144
#define kTOTJ 36864      // kNH*kL
#define kJW 432          // 3*kCHK

// smem strides (attn)
#define QRS 68
#define KP2S 76          // float2 col stride for K pair layout
#define PU32S 44         // u32 stride for P bf16-pair rows (CF write + ldmatrix)
#define VSSU 132         // u32 stride for V bf16 rows (264 bf16; CF)
#define ATHR 576

// conv packed layouts
#define WNY 66           // float4 row stride, convx weights
#define WYS 68           // uint2 row stride, convy bf16 weights (CF)

__device__ __forceinline__ float cvt_tf32(float f) {
    unsigned r; asm("cvt.rna.tf32.f32 %0,%1;" : "=r"(r) : "f"(f));
    return __uint_as_float(r);
}
__device__ __forceinline__ float trunc13(float f) {
    return __uint_as_float(__float_as_uint(f) & 0xFFFFE000u);
}
__device__ __forceinline__ unsigned pack_bf2(float lo, float hi) {
    __nv_bfloat162 t = __floats2bfloat162_rn(lo, hi);
    return *(unsigned*)&t;
}
__device__ __forceinline__ void mma_tf32(float* d, const unsigned* a, unsigned b0, unsigned b1) {
    asm("mma.sync.aligned.m16n8k8.row.col.f32.tf32.tf32.f32 "
        "{%0,%1,%2,%3},{%4,%5,%6,%7},{%8,%9},{%0,%1,%2,%3};"
        : "+f"(d[0]), "+f"(d[1]), "+f"(d[2]), "+f"(d[3])
        : "r"(a[0]), "r"(a[1]), "r"(a[2]), "r"(a[3]), "r"(b0), "r"(b1));
}
__device__ __forceinline__ void mma_bf16(float* d, const unsigned* a, unsigned b0, unsigned b1) {
    asm("mma.sync.aligned.m16n8k16.row.col.f32.bf16.bf16.f32 "
        "{%0,%1,%2,%3},{%4,%5,%6,%7},{%8,%9},{%0,%1,%2,%3};"
        : "+f"(d[0]), "+f"(d[1]), "+f"(d[2]), "+f"(d[3])
        : "r"(a[0]), "r"(a[1]), "r"(a[2]), "r"(a[3]), "r"(b0), "r"(b1));
}
__device__ __forceinline__ void ldm_x4(unsigned* r, unsigned saddr) {
    asm volatile("ldmatrix.sync.aligned.m8n8.x4.shared.b16 {%0,%1,%2,%3},[%4];"
        : "=r"(r[0]), "=r"(r[1]), "=r"(r[2]), "=r"(r[3]) : "r"(saddr));
}
__device__ __forceinline__ void ldm_x4t(unsigned* r, unsigned saddr) {
    asm volatile("ldmatrix.sync.aligned.m8n8.x4.trans.shared.b16 {%0,%1,%2,%3},[%4];"
        : "=r"(r[0]), "=r"(r[1]), "=r"(r[2]), "=r"(r[3]) : "r"(saddr));
}
__device__ __forceinline__ void cp16(void* dst, const void* src) {
    unsigned s = (unsigned)__cvta_generic_to_shared(dst);
    asm volatile("cp.async.cg.shared.global [%0],[%1],16;" :: "r"(s), "l"(src));
}
__device__ __forceinline__ void cp_commit() { asm volatile("cp.async.commit_group;"); }
__device__ __forceinline__ void cp_wait1() { asm volatile("cp.async.wait_group 1;"); }
__device__ __forceinline__ void cp_wait0() { asm volatile("cp.async.wait_group 0;"); }

// -------- scratch (device globals; no allocation allowed) --------
__device__ float g_x[(size_t)kN*kL*kC];            // x_embed (n,t,f)
__device__ __nv_bfloat16 g_yb[(size_t)kN*kL*kCh];  // y_embed bf16 (n,t,e)
__device__ int   g_codes[kN*kTOTJ];
__device__ int   g_sorted[kN*kTOTJ];
__device__ int   g_hist[kN*144*256];
__device__ unsigned g_retb[(size_t)kN*kNH*kL*kCh/2]; // attention out bf16 pairs
__device__ float g_bs[kN*kNH*kL];                  // lse (n,h,t)
// prepacked operands
__device__ uint2  g_wybf[4*16*36*64];              // convy bf16 weights [cog][sl][r][nn]
__device__ uint2  g_inbf[(size_t)kN*kL*64];        // input bf16 pairs [pix][sl][kq]
__device__ float4 g_wxh[16*36*64];                 // convx weights hi
__device__ float4 g_wxl[16*36*64];                 // convx weights lo
__device__ float  g_xil[(size_t)kN*kL*kCh];        // input lo = v - trunc13(v)

// ---------------- prepack kernels ----------------
__global__ __launch_bounds__(256) void prep_in_kernel(const float* __restrict__ in)
{
    size_t i = (size_t)blockIdx.x*256 + threadIdx.x;
    float4 v = ((const float4*)in)[i];
    float4 vl;
    vl.x = v.x - trunc13(v.x);
    vl.y = v.y - trunc13(v.y);
    vl.z = v.z - trunc13(v.z);
    vl.w = v.w - trunc13(v.w);
    ((float4*)g_xil)[i] = vl;
}

__global__ __launch_bounds__(256) void prep_inbf_kernel(const float* __restrict__ in)
{
    size_t i = (size_t)blockIdx.x*256 + threadIdx.x;
    int kq = (int)(i & 3);
    int sl = (int)((i >> 2) & 15);
    size_t pix = i >> 6;
    const float* p = &in[pix*256 + sl*16 + 2*kq];
    uint2 o;
    o.x = pack_bf2(p[0], p[1]);
    o.y = pack_bf2(p[8], p[9]);
    g_inbf[i] = o;
}

__global__ __launch_bounds__(256) void prep_wx_kernel(const float* __restrict__ w)
{
    int i = blockIdx.x*256 + threadIdx.x;
    int nn = i & 63;
    int r  = (i >> 6) % 36;
    int sl = i / 2304;
    int tap = r >> 2, kq4 = r & 3;
    int cin = sl*16 + 4*kq4;
    const float* wp = &w[(tap*kCh + cin)*kC + nn];
    float f0 = wp[0], f1 = wp[kC], f2 = wp[2*kC], f3 = wp[3*kC];
    float4 vh, vl;
    vh.x = cvt_tf32(f0); vl.x = f0 - vh.x;
    vh.y = cvt_tf32(f1); vl.y = f1 - vh.y;
    vh.z = cvt_tf32(f2); vl.z = f2 - vh.z;
    vh.w = cvt_tf32(f3); vl.w = f3 - vh.w;
    g_wxh[i] = vh; g_wxl[i] = vl;
}

__global__ __launch_bounds__(256) void prep_wybf_kernel(const float* __restrict__ w)
{
    int i = blockIdx.x*256 + threadIdx.x;
    int nn = i & 63;
    int r  = (i >> 6) % 36;
    int sl = (i >> 6) / 36 % 16;
    int cog = i / 36864;
    int tap = r >> 2, kq = r & 3;
    int cin = sl*16 + 2*kq;
    const float* wp = &w[(size_t)(tap*kCh + cin)*kCh + cog*64 + nn];
    uint2 o;
    o.x = pack_bf2(wp[0], wp[kCh]);
    o.y = pack_bf2(wp[8*kCh], wp[9*kCh]);
    g_wybf[i] = o;
}

// ---------------- match conv (x path), 3xTF32 MMA, cp.async double-buffer --
__global__ __launch_bounds__(256, 1) void convx_mma_kernel(
    const float* __restrict__ in, const float* __restrict__ bias)
{
    extern __shared__ float4 smx[];
    float4* pH[2] = {smx,        smx + 720};
    float4* pL[2] = {smx + 1440, smx + 2160};
    float4* wH[2] = {smx + 2880, smx + 2880 + 2376};
    float4* wL[2] = {smx + 7632, smx + 7632 + 2376};

    int n    = blockIdx.x / 72;
    int tile = blockIdx.x % 72;
    int by = (tile / 6) * 8, bx = (tile % 6) * 16;
    int tid = threadIdx.x;
    int wid = tid >> 5, lane = tid & 31;
    int m0w = (wid >> 1) * 32;
    int n0w = (wid & 1) * 32;
    int kq = lane & 3, nq = lane >> 2;

    int p_goff[3];
#pragma unroll
    for (int i = 0; i < 3; i++) {
        int lin = tid + i*256;
        p_goff[i] = -1;
        if (lin < 720) {
            int pos = lin >> 2, kq4 = lin & 3;
            int yy = pos / 18, xx = pos % 18;
            int hh = by + yy - 1, ww = bx + xx - 1;
            if (hh >= 0 && hh < kH && ww >= 0 && ww < kW)
                p_goff[i] = (((n*kH + hh)*kW + ww) << 8) + 4*kq4;
        }
    }
#pragma unroll
    for (int i = 0; i < 3; i++) {
        int lin = tid + i*256;
        if (lin < 720 && p_goff[i] < 0) {
            float4 z = {0.f,0.f,0.f,0.f};
            pH[0][lin] = z; pH[1][lin] = z;
            pL[0][lin] = z; pL[1][lin] = z;
        }
    }

    float acc[8][4];
#pragma unroll
    for (int i = 0; i < 8; i++)
#pragma unroll
        for (int j = 0; j < 4; j++) acc[i][j] = 0.f;

    int pb[4];
#pragma unroll
    for (int t = 0; t < 4; t++) {
        int m = m0w + t*8 + nq;
        pb[t] = (m >> 4)*18 + (m & 15);
    }

    auto stage = [&](int sl, int buf) {
#pragma unroll
        for (int i = 0; i < 3; i++) {
            int lin = tid + i*256;
            if (lin < 720 && p_goff[i] >= 0) {
                cp16(&pH[buf][lin], &in[p_goff[i] + sl*16]);
                cp16(&pL[buf][lin], &g_xil[p_goff[i] + sl*16]);
            }
        }
#pragma unroll
        for (int i = 0; i < 9; i++) {
            int lin = tid + i*256;
            int r = lin >> 6, nn = lin & 63;
            int didx = r*WNY + nn;
            int sidx = sl*2304 + lin;
            cp16(&wH[buf][didx], &g_wxh[sidx]);
            cp16(&wL[buf][didx], &g_wxl[sidx]);
        }
    };

    stage(0, 0); cp_commit();
    for (int sl = 0; sl < 16; sl++) {
        int buf = sl & 1;
        if (sl < 15) { stage(sl + 1, buf ^ 1); cp_commit(); cp_wait1(); }
        else cp_wait0();
        __syncthreads();
        float4* p4h = pH[buf]; float4* p4l = pL[buf];
        float4* w4h = wH[buf]; float4* w4l = wL[buf];

#pragma unroll
        for (int tap = 0; tap < 9; tap++) {
            int posoff = (tap/3)*18 + (tap%3);
            float4 ah[4], al[4];
#pragma unroll
            for (int t = 0; t < 4; t++) {
                int o = (pb[t] + posoff)*4 + kq;
                ah[t] = p4h[o]; al[t] = p4l[o];
            }
            unsigned Ah00[4] = {__float_as_uint(ah[0].x), __float_as_uint(ah[1].x),
                                __float_as_uint(ah[0].y), __float_as_uint(ah[1].y)};
            unsigned Ah01[4] = {__float_as_uint(ah[0].z), __float_as_uint(ah[1].z),
                                __float_as_uint(ah[0].w), __float_as_uint(ah[1].w)};
            unsigned Ah10[4] = {__float_as_uint(ah[2].x), __float_as_uint(ah[3].x),
                                __float_as_uint(ah[2].y), __float_as_uint(ah[3].y)};
            unsigned Ah11[4] = {__float_as_uint(ah[2].z), __float_as_uint(ah[3].z),
                                __float_as_uint(ah[2].w), __float_as_uint(ah[3].w)};
            unsigned Al00[4] = {__float_as_uint(al[0].x), __float_as_uint(al[1].x),
                                __float_as_uint(al[0].y), __float_as_uint(al[1].y)};
            unsigned Al01[4] = {__float_as_uint(al[0].z), __float_as_uint(al[1].z),
                                __float_as_uint(al[0].w), __float_as_uint(al[1].w)};
            unsigned Al10[4] = {__float_as_uint(al[2].x), __float_as_uint(al[3].x),
                                __float_as_uint(al[2].y), __float_as_uint(al[3].y)};
            unsigned Al11[4] = {__float_as_uint(al[2].z), __float_as_uint(al[3].z),
                                __float_as_uint(al[2].w), __float_as_uint(al[3].w)};
            int wr = (tap*4 + kq)*WNY + n0w + nq;
#pragma unroll
            for (int nt = 0; nt < 4; nt++) {
                float4 bh = w4h[wr + nt*8];
                float4 bl = w4l[wr + nt*8];
                unsigned bhx = __float_as_uint(bh.x), bhy = __float_as_uint(bh.y);
                unsigned bhz = __float_as_uint(bh.z), bhw = __float_as_uint(bh.w);
                unsigned blx = __float_as_uint(bl.x), bly = __float_as_uint(bl.y);
                unsigned blz = __float_as_uint(bl.z), blw = __float_as_uint(bl.w);
                mma_tf32(acc[nt], Ah00, bhx, bhy);
                mma_tf32(acc[nt], Ah01, bhz, bhw);
                mma_tf32(acc[nt], Ah00, blx, bly);
                mma_tf32(acc[nt], Ah01, blz, blw);
                mma_tf32(acc[nt], Al00, bhx, bhy);
                mma_tf32(acc[nt], Al01, bhz, bhw);
                mma_tf32(acc[4+nt], Ah10, bhx, bhy);
                mma_tf32(acc[4+nt], Ah11, bhz, bhw);
                mma_tf32(acc[4+nt], Ah10, blx, bly);
                mma_tf32(acc[4+nt], Ah11, blz, blw);
                mma_tf32(acc[4+nt], Al10, bhx, bhy);
                mma_tf32(acc[4+nt], Al11, bhz, bhw);
            }
        }
        __syncthreads();
    }

#pragma unroll
    for (int mt = 0; mt < 2; mt++) {
#pragma unroll
        for (int half = 0; half < 2; half++) {
            int m = m0w + mt*16 + half*8 + nq;
            int py = by + (m >> 4), px = bx + (m & 15);
            int p = py*kW + px;
            int f = p / 144, pm = p % 144;
#pragma unroll
            for (int nt = 0; nt < 4; nt++) {
                int c = n0w + nt*8 + 2*kq;
                float v0 = acc[mt*4 + nt][half*2]     + bias[c];
                float v1 = acc[mt*4 + nt][half*2 + 1] + bias[c+1];
                g_x[((size_t)n*kL + pm*64 + c    )*kC + f] = v0;
                g_x[((size_t)n*kL + pm*64 + c + 1)*kC + f] = v1;
            }
        }
    }
}

// ---------------- asm conv (y path), bf16 m16n8k16 MMA, double buffer ------
__global__ __launch_bounds__(512, 1) void convy_mma_kernel(const float* __restrict__ bias)
{
    extern __shared__ uint2 smy2[];
    uint2* pB[2] = {smy2,        smy2 + 1296};
    uint2* wB[2] = {smy2 + 2592, smy2 + 2592 + 2448};

    int n    = blockIdx.x / 36;
    int tile = blockIdx.x % 36;
    int by = (tile / 6) * 16, bx = (tile % 6) * 16;
    int cog = blockIdx.y;
    int co0 = cog * 64;
    int tid = threadIdx.x;
    int wid = tid >> 5, lane = tid & 31;
    int m0w = (wid >> 1) * 32;
    int n0w = (wid & 1) * 32;
    int kq = lane & 3;
    int nq = lane >> 2;

    long long p_gidx[2];
#pragma unroll
    for (int i = 0; i < 2; i++) {
        int lin = tid + i*512;
        p_gidx[i] = -1;
        if (lin < 648) {
            int pos = lin >> 1;
            int yy = pos / 18, xx = pos % 18;
            int hh = by + yy - 1, ww = bx + xx - 1;
            if (hh >= 0 && hh < kH && ww >= 0 && ww < kW)
                p_gidx[i] = ((long long)((n*kH + hh)*kW + ww))*64 + (lin & 1)*2;
        }
    }
#pragma unroll
    for (int i = 0; i < 2; i++) {
        int lin = tid + i*512;
        if (lin < 648 && p_gidx[i] < 0) {
            uint2 z = {0u, 0u};
            int d = (lin >> 1)*4 + (lin & 1)*2;
            pB[0][d] = z; pB[0][d+1] = z;
            pB[1][d] = z; pB[1][d+1] = z;
        }
    }

    float acc[8][4];
#pragma unroll
    for (int i = 0; i < 8; i++)
#pragma unroll
        for (int j = 0; j < 4; j++) acc[i][j] = 0.f;

    int pb[4];
#pragma unroll
    for (int t = 0; t < 4; t++) {
        int m = m0w + t*8 + nq;
        pb[t] = (m >> 4)*18 + (m & 15);
    }

    const uint2* wsrc = &g_wybf[cog*36864];

    auto stage = [&](int sl, int buf) {
#pragma unroll
        for (int i = 0; i < 2; i++) {
            int lin = tid + i*512;
            if (lin < 648 && p_gidx[i] >= 0)
                cp16(&pB[buf][(lin >> 1)*4 + (lin & 1)*2], &g_inbf[p_gidx[i] + sl*4]);
        }
#pragma unroll
        for (int i = 0; i < 3; i++) {
            int lin = tid + i*512;
            if (lin < 1152) {
                int idx = lin*2;
                int r = idx >> 6, nn = idx & 63;
                cp16(&wB[buf][r*WYS + nn], &wsrc[sl*2304 + idx]);
            }
        }
    };

    stage(0, 0); cp_commit();
    for (int sl = 0; sl < 16; sl++) {
        int buf = sl & 1;
        if (sl < 15) { stage(sl + 1, buf ^ 1); cp_commit(); cp_wait1(); }
        else cp_wait0();
        __syncthreads();
        uint2* up2 = pB[buf];
        uint2* w2  = wB[buf];

#pragma unroll
        for (int tap = 0; tap < 9; tap++) {
            int posoff = (tap/3)*18 + (tap%3);
            uint2 aL0 = up2[(pb[0] + posoff)*4 + kq];
            uint2 aH0 = up2[(pb[1] + posoff)*4 + kq];
            uint2 aL1 = up2[(pb[2] + posoff)*4 + kq];
            uint2 aH1 = up2[(pb[3] + posoff)*4 + kq];
            unsigned A0[4] = {aL0.x, aH0.x, aL0.y, aH0.y};
            unsigned A1[4] = {aL1.x, aH1.x, aL1.y, aH1.y};
            int wr = (tap*4 + kq)*WYS + n0w + nq;
#pragma unroll
            for (int nt = 0; nt < 4; nt++) {
                uint2 bw = w2[wr + nt*8];
                mma_bf16(acc[nt],     A0, bw.x, bw.y);
                mma_bf16(acc[4 + nt], A1, bw.x, bw.y);
            }
        }
        __syncthreads();
    }

#pragma unroll
    for (int mt = 0; mt < 2; mt++) {
#pragma unroll
        for (int half = 0; half < 2; half++) {
            int m = m0w + mt*16 + half*8 + nq;
            int py = by + (m >> 4), px = bx + (m & 15);
            int p = py*kW + px;
            int e = p / 36, pm = p % 36;
#pragma unroll
            for (int nt = 0; nt < 4; nt++) {
                int c = co0 + n0w + nt*8 + 2*kq;
                float v0 = acc[mt*4 + nt][half*2]     + bias[c];
                float v1 = acc[mt*4 + nt][half*2 + 1] + bias[c+1];
                g_yb[((size_t)n*kL + pm*256 + c    )*kCh + e] = __float2bfloat16_rn(v0);
                g_yb[((size_t)n*kL + pm*256 + c + 1)*kCh + e] = __float2bfloat16_rn(v1);
            }
        }
    }
}

// ---------------- LSH hashing ----------------
__global__ __launch_bounds__(256) void hash_kernel(const float* __restrict__ rot)
{
    __shared__ float Rsm[8192];
    __shared__ float xrow[8][64];
    int tid = threadIdx.x;
    for (int lin = tid; lin < 8192; lin += 256) Rsm[lin] = rot[lin];
    int wid = tid >> 5, lane = tid & 31;
    int idx = blockIdx.x*8 + wid;
    int n = idx / kL, t = idx % kL;
    const float* xr = &g_x[((size_t)n*kL + t)*kC];
    xrow[wid][lane]      = xr[lane];
    xrow[wid][lane + 32] = xr[lane + 32];
    __syncthreads();
#pragma unroll
    for (int h = 0; h < 4; h++) {
        float s = 0.f;
#pragma unroll
        for (int f = 0; f < 64; f++) s += xrow[wid][f] * Rsm[f*128 + h*32 + lane];
        float bv; int bi;
        if (s >= -s) { bv = s;  bi = lane; }
        else         { bv = -s; bi = lane + 32; }
#pragma unroll
        for (int off = 16; off > 0; off >>= 1) {
            float ov = __shfl_xor_sync(0xffffffffu, bv, off);
            int   oi = __shfl_xor_sync(0xffffffffu, bi, off);
            if (ov > bv || (ov == bv && oi < bi)) { bv = ov; bi = oi; }
        }
        if (lane == 0) g_codes[n*kTOTJ + h*kL + t] = bi + h*kHB;
    }
}

// ---------------- stable counting sort (argsort) ----------------
__global__ __launch_bounds__(256) void sortA_kernel()
{
    __shared__ int hist[256];
    int b = blockIdx.x; int n = b / 144, blk = b % 144; int tid = threadIdx.x;
    hist[tid] = 0; __syncthreads();
    int code = g_codes[n*kTOTJ + blk*256 + tid];
    atomicAdd(&hist[code], 1);
    __syncthreads();
    g_hist[(n*144 + blk)*256 + tid] = hist[tid];
}

__global__ __launch_bounds__(256) void sortBC_kernel()
{
    __shared__ int scanbuf[256];
    __shared__ int comb[256];
    __shared__ int cs[256];
    int b = blockIdx.x; int n = b / 144, blk = b % 144; int v = threadIdx.x;

    int tot = 0, off = 0;
    const int* hb = &g_hist[n*144*256 + v];
    for (int bb = 0; bb < 144; bb++) {
        int hv = hb[bb*256];
        tot += hv;
        if (bb < blk) off += hv;
    }
    scanbuf[v] = tot;
    __syncthreads();
    for (int d = 1; d < 256; d <<= 1) {
        int y = (v >= d) ? scanbuf[v - d] : 0;
        __syncthreads();
        scanbuf[v] += y;
        __syncthreads();
    }
    comb[v] = (scanbuf[v] - tot) + off;
    int c = g_codes[n*kTOTJ + blk*256 + v];
    cs[v] = c;
    __syncthreads();
    int rank = 0;
    for (int j = 0; j < v; j++) rank += (cs[j] == c);
    g_sorted[n*kTOTJ + comb[c] + rank] = blk*256 + v;
}

// ---------------- fused chunk attention: tf32 QK + bf16 ldmatrix PV --------
__global__ __launch_bounds__(ATHR, 1) void attn_kernel()
{
    extern __shared__ float sm[];
    float* Qr  = sm;                              // 9792 floats
    float* Kp  = Qr + 144*QRS;                    // 4864 floats (float2 pairs)
    unsigned* vs_u32  = (unsigned*)(sm + 14656);  // 80 rows x VSSU u32 (bf16 V)
    unsigned* psm_u32 = (unsigned*)(sm + 25216);  // 144 x PU32S u32 (bf16 P pairs)
    float* m_r = sm + 31552;                      // 144
    float* rowsumA = m_r + 144;                   // 144
    float* rowsumB = rowsumA + 144;               // 144
    int* tIdx = (int*)(rowsumB + 144);            // 432

    float2* kp2 = (float2*)Kp;

    int g = blockIdx.x;
    int n = g >> 8, k = g & 255;
    int h = k >> 6, kl = k & 63;
    int tid = threadIdx.x;
    int wid = tid >> 5, lane = tid & 31;
    int kq = lane & 3, nq = lane >> 2;

    for (int j = tid; j < kJW; j += ATHR) {
        int cchunk = j / kCHK, i = j % kCHK;
        int skl = (cchunk == 0) ? kl : (cchunk == 1) ? ((kl + 63) & 63) : ((kl + 1) & 63);
        int s = (h*64 + skl)*kCHK + i;
        tIdx[j] = g_sorted[n*kTOTJ + s] % kL;
    }
    for (int i = tid; i < kCHK; i += ATHR) { rowsumA[i] = 0.f; rowsumB[i] = 0.f; }
    for (int i = tid; i < 144*8; i += ATHR)
        psm_u32[(i >> 3)*PU32S + 36 + (i & 7)] = 0u;
    for (int i = tid; i < 8*VSSU; i += ATHR)
        vs_u32[72*VSSU + i] = 0u;
    __syncthreads();

    {
#pragma unroll
        for (int rr = 0; rr < 8; rr++) {
            int r = wid*8 + rr;
            const float* xr = &g_x[((size_t)n*kL + tIdx[r])*kC];
            float a = xr[lane], b = xr[lane + 32];
            Qr[r*QRS + lane] = a;
            Qr[r*QRS + lane + 32] = b;
            float ss = a*a + b*b;
#pragma unroll
            for (int off = 16; off > 0; off >>= 1)
                ss += __shfl_xor_sync(0xffffffffu, ss, off);
            if (lane == 0) m_r[r] = ss * rsqrtf(fmaxf(ss, 5e-5f));
        }
    }
    __syncthreads();

    int wq = wid % 9;
    int halfq = wid / 9;
    int m0 = wq * 16;
    float mA = m_r[m0 + nq], mB = m_r[m0 + 8 + nq];

    float Oacc[16][4];
#pragma unroll
    for (int i = 0; i < 16; i++)
#pragma unroll
        for (int j = 0; j < 4; j++) Oacc[i][j] = 0.f;

    unsigned pbase = (unsigned)__cvta_generic_to_shared(psm_u32);
    unsigned vbase = (unsigned)__cvta_generic_to_shared(vs_u32);
    unsigned aaddr = pbase + (unsigned)((m0 + (lane & 15))*(PU32S*4) + (lane >> 4)*16);
    unsigned baddr = vbase + (unsigned)((lane & 15)*(VSSU*4) + ((halfq*128 + (lane >> 4)*8) << 1));

    for (int jc = 0; jc < 6; jc++) {
        int j0 = jc*72;
        if (wid < 9) {
            int col = wid*8 + (lane >> 2);
            int fq = lane & 3;
            int fs = fq * 16;
            const float4* xr = (const float4*)&g_x[((size_t)n*kL + tIdx[j0 + col])*kC + fs];
            float4 v0 = xr[0], v1 = xr[1], v2 = xr[2], v3 = xr[3];
            float ss = v0.x*v0.x + v0.y*v0.y + v0.z*v0.z + v0.w*v0.w
                     + v1.x*v1.x + v1.y*v1.y + v1.z*v1.z + v1.w*v1.w
                     + v2.x*v2.x + v2.y*v2.y + v2.z*v2.z + v2.w*v2.w
                     + v3.x*v3.x + v3.y*v3.y + v3.z*v3.z + v3.w*v3.w;
            ss += __shfl_xor_sync(0xffffffffu, ss, 1);
            ss += __shfl_xor_sync(0xffffffffu, ss, 2);
            float r = rsqrtf(fmaxf(ss, 5e-5f));
            int ks0 = fq * 2;
            float2 t0; t0.x = v0.x*r; t0.y = v1.x*r; kp2[((ks0)*4 + 0)*KP2S + col] = t0;
            float2 t1; t1.x = v0.y*r; t1.y = v1.y*r; kp2[((ks0)*4 + 1)*KP2S + col] = t1;
            float2 t2; t2.x = v0.z*r; t2.y = v1.z*r; kp2[((ks0)*4 + 2)*KP2S + col] = t2;
            float2 t3; t3.x = v0.w*r; t3.y = v1.w*r; kp2[((ks0)*4 + 3)*KP2S + col] = t3;
            float2 t4; t4.x = v2.x*r; t4.y = v3.x*r; kp2[((ks0+1)*4 + 0)*KP2S + col] = t4;
            float2 t5; t5.x = v2.y*r; t5.y = v3.y*r; kp2[((ks0+1)*4 + 1)*KP2S + col] = t5;
            float2 t6; t6.x = v2.z*r; t6.y = v3.z*r; kp2[((ks0+1)*4 + 2)*KP2S + col] = t6;
            float2 t7; t7.x = v2.w*r; t7.y = v3.w*r; kp2[((ks0+1)*4 + 3)*KP2S + col] = t7;
        } else {
            int w2 = wid - 9;
#pragma unroll
            for (int r = 0; r < 8; r++) {
                int row = w2*8 + r;
                uint4 v = ((const uint4*)&g_yb[((size_t)n*kL + tIdx[j0 + row])*kCh])[lane];
                ((uint4*)vs_u32)[row*(VSSU/4) + lane] = v;
            }
        }
        __syncthreads();

        // QK MMA (tf32) + exp + bf16 P pairs to smem
        {
            unsigned Af[8][4];
#pragma unroll
            for (int ks = 0; ks < 8; ks++) {
                const float* q0 = &Qr[(m0 + nq)*QRS + ks*8 + kq];
                const float* q1 = &Qr[(m0 + 8 + nq)*QRS + ks*8 + kq];
                Af[ks][0] = __float_as_uint(q0[0]);
                Af[ks][1] = __float_as_uint(q1[0]);
                Af[ks][2] = __float_as_uint(q0[4]);
                Af[ks][3] = __float_as_uint(q1[4]);
            }
            float s0 = 0.f, s1 = 0.f;
            int ntBeg = halfq ? 5 : 0;
            int ntEnd = halfq ? 9 : 5;
            for (int nt = ntBeg; nt < ntEnd; nt++) {
                float acc[4] = {0.f, 0.f, 0.f, 0.f};
#pragma unroll
                for (int ks = 0; ks < 8; ks++) {
                    float2 bp = kp2[(ks*4 + kq)*KP2S + nt*8 + nq];
                    mma_tf32(acc, Af[ks], __float_as_uint(bp.x), __float_as_uint(bp.y));
                }
                float e0 = __expf(acc[0] - mA), e1 = __expf(acc[1] - mA);
                float e2 = __expf(acc[2] - mB), e3 = __expf(acc[3] - mB);
                s0 += e0 + e1; s1 += e2 + e3;
                psm_u32[(m0 + nq)*PU32S + nt*4 + kq]     = pack_bf2(e0, e1);
                psm_u32[(m0 + 8 + nq)*PU32S + nt*4 + kq] = pack_bf2(e2, e3);
            }
            s0 += __shfl_xor_sync(0xffffffffu, s0, 1);
            s0 += __shfl_xor_sync(0xffffffffu, s0, 2);
            s1 += __shfl_xor_sync(0xffffffffu, s1, 1);
            s1 += __shfl_xor_sync(0xffffffffu, s1, 2);
            if (kq == 0) {
                float* rs = halfq ? rowsumB : rowsumA;
                rs[m0 + nq] += s0;
                rs[m0 + 8 + nq] += s1;
            }
        }
        // partner-pair barrier: warps (wq,0) and (wq,1) exchange their P halves.
        asm volatile("bar.sync %0, 64;" :: "r"(1 + wq) : "memory");

        // PV MMA (bf16 m16n8k16 via ldmatrix), 5 uniform k16 groups
        {
#pragma unroll
            for (int gg = 0; gg < 5; gg++) {
                unsigned A[4];
                ldm_x4(A, aaddr + gg*32);
#pragma unroll
                for (int np = 0; np < 8; np++) {
                    unsigned B[4];
                    ldm_x4t(B, baddr + gg*16*(VSSU*4) + np*32);
                    mma_bf16(Oacc[2*np],     A, B[0], B[1]);
                    mma_bf16(Oacc[2*np + 1], A, B[2], B[3]);
                }
            }
        }
        __syncthreads();
    }

    {
        int n0 = halfq * 128;
        int rA = m0 + nq, rB = rA + 8;
        float sumA = rowsumA[rA] + rowsumB[rA];
        float sumB = rowsumA[rB] + rowsumB[rB];
        float invA = 1.f / sumA;
        float invB = 1.f / sumB;
        size_t baseA = ((size_t)(n*4 + h)*kL + tIdx[rA])*kCh;
        size_t baseB = ((size_t)(n*4 + h)*kL + tIdx[rB])*kCh;
#pragma unroll
        for (int nt = 0; nt < 16; nt++) {
            int cA = n0 + nt*8 + 2*kq;
            g_retb[(baseA + cA) >> 1] = pack_bf2(Oacc[nt][0]*invA, Oacc[nt][1]*invA);
            g_retb[(baseB + cA) >> 1] = pack_bf2(Oacc[nt][2]*invB, Oacc[nt][3]*invB);
        }
        if (wid < 9 && lane < 16) {
            int row = wid*16 + lane;
            float s = rowsumA[row] + rowsumB[row];
            g_bs[(size_t)(n*4 + h)*kL + tIdx[row]] = m_r[row] + __logf(s);
        }
    }
}

// ---------------- head combine + residual + output layout ----------------
__global__ __launch_bounds__(256) void combine_kernel(
    const float* __restrict__ in, float* __restrict__ out)
{
    __shared__ float accs[256*33];
    __shared__ float probs[4*256];
    int n = blockIdx.x / 36, q = blockIdx.x % 36;
    int e0 = blockIdx.y * 32;
    int tid = threadIdx.x;

    {
        int t = q*256 + tid;
        float b0 = g_bs[(size_t)(n*4 + 0)*kL + t];
        float b1 = g_bs[(size_t)(n*4 + 1)*kL + t];
        float b2 = g_bs[(size_t)(n*4 + 2)*kL + t];
        float b3 = g_bs[(size_t)(n*4 + 3)*kL + t];
        float m = fmaxf(fmaxf(b0, b1), fmaxf(b2, b3));
        float x0 = __expf(b0 - m), x1 = __expf(b1 - m);
        float x2 = __expf(b2 - m), x3 = __expf(b3 - m);
        float sinv = 1.f / (x0 + x1 + x2 + x3);
        probs[0*256 + tid] = x0*sinv; probs[1*256 + tid] = x1*sinv;
        probs[2*256 + tid] = x2*sinv; probs[3*256 + tid] = x3*sinv;
    }
    for (int lin = tid; lin < 256*33; lin += 256) accs[lin] = 0.f;
    __syncthreads();

    for (int h = 0; h < 4; h++) {
        for (int lin = tid; lin < 256*16; lin += 256) {
            int cc = lin >> 4, ep = lin & 15;
            unsigned pv = g_retb[(((size_t)(n*4 + h)*kL + q*256 + cc)*kCh + e0) / 2 + ep];
            __nv_bfloat162 b = *(__nv_bfloat162*)&pv;
            float pr = probs[h*256 + cc];
            accs[cc*33 + 2*ep]     += pr * __low2float(b);
            accs[cc*33 + 2*ep + 1] += pr * __high2float(b);
        }
    }
    __syncthreads();

    for (int lin = tid; lin < 32*256; lin += 256) {
        int e = lin >> 8, c = lin & 255;
        int p = (e0 + e)*36 + q;
        size_t oi = ((size_t)n*kL + p)*kCh + c;
        out[oi] = 0.1f*accs[c*33 + e] + in[oi];
    }
}

// ---------------- launch: stream-forked (capture-safe fork/join) ----------
extern "C" void kernel_launch(void* const* d_in, const int* in_sizes, int n_in,
                              void* d_out, int out_size)
{
    const float* input     = (const float*)d_in[0];
    const float* w_match   = (const float*)d_in[1];
    const float* b_match   = (const float*)d_in[2];
    const float* w_asm     = (const float*)d_in[3];
    const float* b_asm     = (const float*)d_in[4];
    const float* rotations = (const float*)d_in[5];
    float* out = (float*)d_out;

    const int CONVX_SMEM = 12384 * 16;                                  // 198144
    const int CONVY_SMEM = (2592 + 2448*2) * 8;                         // 59904
    const int ATT_SMEM   = 32416 * 4;                                   // 129664

    static cudaStream_t sY = nullptr;
    static cudaEvent_t evFork = nullptr, evJoin = nullptr;
    if (sY == nullptr) {
        cudaStreamCreateWithFlags(&sY, cudaStreamNonBlocking);
        cudaEventCreateWithFlags(&evFork, cudaEventDisableTiming);
        cudaEventCreateWithFlags(&evJoin, cudaEventDisableTiming);
        cudaFuncSetAttribute(convx_mma_kernel, cudaFuncAttributeMaxDynamicSharedMemorySize, CONVX_SMEM);
        cudaFuncSetAttribute(convy_mma_kernel, cudaFuncAttributeMaxDynamicSharedMemorySize, CONVY_SMEM);
        cudaFuncSetAttribute(attn_kernel,      cudaFuncAttributeMaxDynamicSharedMemorySize, ATT_SMEM);
    }

    cudaEventRecord(evFork, 0);
    cudaStreamWaitEvent(sY, evFork, 0);

    prep_in_kernel<<<kN*kL*64/256, 256>>>(input);                       // s0 (#1)
    prep_inbf_kernel<<<kN*kL*64/256, 256, 0, sY>>>(input);              // sY (#2)
    prep_wybf_kernel<<<576, 256, 0, sY>>>(w_asm);                       // sY (#3)
    convy_mma_kernel<<<dim3(kN*36, 4), 512, CONVY_SMEM, sY>>>(b_asm);   // sY (#4, ncu slot)
    cudaEventRecord(evJoin, sY);
    prep_wx_kernel<<<144, 256>>>(w_match);                              // s0
    convx_mma_kernel<<<kN*72, 256, CONVX_SMEM>>>(input, b_match);
    hash_kernel<<<kN*kL/8, 256>>>(rotations);
    sortA_kernel<<<kN*144, 256>>>();
    sortBC_kernel<<<kN*144, 256>>>();
    cudaStreamWaitEvent(0, evJoin, 0);
    attn_kernel<<<kN*256, ATHR, ATT_SMEM>>>();
    combine_kernel<<<dim3(kN*36, 8), 256>>>(input, out);
}

// round 16
// speedup vs baseline: 1.6351x; 1.1223x over previous
#include <cuda_runtime.h>
#include <cuda_bf16.h>
#include <math.h>

// Problem constants
#define kN 4
#define kH 96
#define kW 96
#define kCh 256
#define kC 64
#define kL 9216          // 96*96
#define kNH 4
#define kHB 64           // hash buckets
#define kCHK 144
#define kTOTJ 36864      // kNH*kL
#define kJW 432          // 3*kCHK

// smem strides (attn)
#define QRS 68
#define KP2S 76          // float2 col stride for K pair layout
#define PU32S 44         // u32 stride for P bf16-pair rows (CF write + ldmatrix)
#define VSSU 132         // u32 stride for V bf16 rows (264 bf16; CF)
#define ATHR 576

// conv packed layouts
#define WYS 68           // uint2 row stride, conv bf16 weights (CF)

__device__ __forceinline__ unsigned pack_bf2(float lo, float hi) {
    __nv_bfloat162 t = __floats2bfloat162_rn(lo, hi);
    return *(unsigned*)&t;
}
__device__ __forceinline__ float bf_hi(float v) {
    return __bfloat162float(__float2bfloat16_rn(v));
}
__device__ __forceinline__ void mma_tf32(float* d, const unsigned* a, unsigned b0, unsigned b1) {
    asm("mma.sync.aligned.m16n8k8.row.col.f32.tf32.tf32.f32 "
        "{%0,%1,%2,%3},{%4,%5,%6,%7},{%8,%9},{%0,%1,%2,%3};"
        : "+f"(d[0]), "+f"(d[1]), "+f"(d[2]), "+f"(d[3])
        : "r"(a[0]), "r"(a[1]), "r"(a[2]), "r"(a[3]), "r"(b0), "r"(b1));
}
__device__ __forceinline__ void mma_bf16(float* d, const unsigned* a, unsigned b0, unsigned b1) {
    asm("mma.sync.aligned.m16n8k16.row.col.f32.bf16.bf16.f32 "
        "{%0,%1,%2,%3},{%4,%5,%6,%7},{%8,%9},{%0,%1,%2,%3};"
        : "+f"(d[0]), "+f"(d[1]), "+f"(d[2]), "+f"(d[3])
        : "r"(a[0]), "r"(a[1]), "r"(a[2]), "r"(a[3]), "r"(b0), "r"(b1));
}
__device__ __forceinline__ void ldm_x4(unsigned* r, unsigned saddr) {
    asm volatile("ldmatrix.sync.aligned.m8n8.x4.shared.b16 {%0,%1,%2,%3},[%4];"
        : "=r"(r[0]), "=r"(r[1]), "=r"(r[2]), "=r"(r[3]) : "r"(saddr));
}
__device__ __forceinline__ void ldm_x4t(unsigned* r, unsigned saddr) {
    asm volatile("ldmatrix.sync.aligned.m8n8.x4.trans.shared.b16 {%0,%1,%2,%3},[%4];"
        : "=r"(r[0]), "=r"(r[1]), "=r"(r[2]), "=r"(r[3]) : "r"(saddr));
}
__device__ __forceinline__ void cp16(void* dst, const void* src) {
    unsigned s = (unsigned)__cvta_generic_to_shared(dst);
    asm volatile("cp.async.cg.shared.global [%0],[%1],16;" :: "r"(s), "l"(src));
}
__device__ __forceinline__ void cp_commit() { asm volatile("cp.async.commit_group;"); }
__device__ __forceinline__ void cp_wait1() { asm volatile("cp.async.wait_group 1;"); }
__device__ __forceinline__ void cp_wait0() { asm volatile("cp.async.wait_group 0;"); }

// -------- scratch (device globals; no allocation allowed) --------
__device__ float g_x[(size_t)kN*kL*kC];            // x_embed (n,t,f)
__device__ __nv_bfloat16 g_yb[(size_t)kN*kL*kCh];  // y_embed bf16 (n,t,e)
__device__ int   g_codes[kN*kTOTJ];
__device__ int   g_sorted[kN*kTOTJ];
__device__ int   g_hist[kN*144*256];
__device__ unsigned g_retb[(size_t)kN*kNH*kL*kCh/2]; // attention out bf16 pairs
__device__ float g_bs[kN*kNH*kL];                  // lse (n,h,t)
// prepacked operands (bf16 hi/lo pair layouts for m16n8k16 fragments)
__device__ uint2  g_wybf[4*16*36*64];              // convy weights [cog][sl][r][nn]
__device__ uint2  g_wxbh[16*36*64];                // convx weights hi
__device__ uint2  g_wxbl[16*36*64];                // convx weights lo
__device__ uint2  g_inbf[(size_t)kN*kL*64];        // input hi pairs [pix][sl][kq]
__device__ uint2  g_inbl[(size_t)kN*kL*64];        // input lo pairs

// ---------------- prepack kernels ----------------
// input: hi = bf16(v), lo = bf16(v - hi). pair layout (k,k+1 | k+8,k+9)
__global__ __launch_bounds__(256) void prep_inbf2_kernel(const float* __restrict__ in)
{
    size_t i = (size_t)blockIdx.x*256 + threadIdx.x;
    int kq = (int)(i & 3);
    int sl = (int)((i >> 2) & 15);
    size_t pix = i >> 6;
    const float* p = &in[pix*256 + sl*16 + 2*kq];
    float v0 = p[0], v1 = p[1], v8 = p[8], v9 = p[9];
    float h0 = bf_hi(v0), h1 = bf_hi(v1), h8 = bf_hi(v8), h9 = bf_hi(v9);
    uint2 oh, ol;
    oh.x = pack_bf2(h0, h1);        oh.y = pack_bf2(h8, h9);
    ol.x = pack_bf2(v0-h0, v1-h1);  ol.y = pack_bf2(v8-h8, v9-h9);
    g_inbf[i] = oh;
    g_inbl[i] = ol;
}

__global__ __launch_bounds__(256) void prep_wxbf_kernel(const float* __restrict__ w)
{
    int i = blockIdx.x*256 + threadIdx.x;              // < 36864
    int nn = i & 63;
    int r  = (i >> 6) % 36;
    int sl = i / 2304;
    int tap = r >> 2, kq = r & 3;
    int cin = sl*16 + 2*kq;
    const float* wp = &w[(tap*kCh + cin)*kC + nn];
    float w0 = wp[0], w1 = wp[kC], w8 = wp[8*kC], w9 = wp[9*kC];
    float h0 = bf_hi(w0), h1 = bf_hi(w1), h8 = bf_hi(w8), h9 = bf_hi(w9);
    uint2 oh, ol;
    oh.x = pack_bf2(h0, h1);        oh.y = pack_bf2(h8, h9);
    ol.x = pack_bf2(w0-h0, w1-h1);  ol.y = pack_bf2(w8-h8, w9-h9);
    g_wxbh[i] = oh;
    g_wxbl[i] = ol;
}

__global__ __launch_bounds__(256) void prep_wybf_kernel(const float* __restrict__ w)
{
    int i = blockIdx.x*256 + threadIdx.x;              // < 4*36864
    int nn = i & 63;
    int r  = (i >> 6) % 36;
    int sl = (i >> 6) / 36 % 16;
    int cog = i / 36864;
    int tap = r >> 2, kq = r & 3;
    int cin = sl*16 + 2*kq;
    const float* wp = &w[(size_t)(tap*kCh + cin)*kCh + cog*64 + nn];
    uint2 o;
    o.x = pack_bf2(wp[0], wp[kCh]);
    o.y = pack_bf2(wp[8*kCh], wp[9*kCh]);
    g_wybf[i] = o;
}

// ---------------- match conv (x path), bf16x2 3-product MMA, dbuf ----------
// block tile: 256 pixels (16x16) x 64 cout. 16 warps, warp M=32, N=32.
// x = (Ah+Al)(Bh+Bl) ~= AhBh + AhBl + AlBh  (b1B1 dropped, ~2^-18)
__global__ __launch_bounds__(512, 1) void convx_mma_kernel(const float* __restrict__ bias)
{
    extern __shared__ uint2 smc[];
    uint2* pBh[2] = {smc,         smc + 1296};
    uint2* pBl[2] = {smc + 2592,  smc + 3888};
    uint2* wBh[2] = {smc + 5184,  smc + 5184 + 2448};
    uint2* wBl[2] = {smc + 10080, smc + 10080 + 2448};

    int n    = blockIdx.x / 36;
    int tile = blockIdx.x % 36;
    int by = (tile / 6) * 16, bx = (tile % 6) * 16;
    int tid = threadIdx.x;
    int wid = tid >> 5, lane = tid & 31;
    int m0w = (wid >> 1) * 32;
    int n0w = (wid & 1) * 32;
    int kq = lane & 3;
    int nq = lane >> 2;

    long long p_gidx[2];
#pragma unroll
    for (int i = 0; i < 2; i++) {
        int lin = tid + i*512;
        p_gidx[i] = -1;
        if (lin < 648) {
            int pos = lin >> 1;
            int yy = pos / 18, xx = pos % 18;
            int hh = by + yy - 1, ww = bx + xx - 1;
            if (hh >= 0 && hh < kH && ww >= 0 && ww < kW)
                p_gidx[i] = ((long long)((n*kH + hh)*kW + ww))*64 + (lin & 1)*2;
        }
    }
#pragma unroll
    for (int i = 0; i < 2; i++) {
        int lin = tid + i*512;
        if (lin < 648 && p_gidx[i] < 0) {
            uint2 z = {0u, 0u};
            int d = (lin >> 1)*4 + (lin & 1)*2;
            pBh[0][d] = z; pBh[0][d+1] = z; pBh[1][d] = z; pBh[1][d+1] = z;
            pBl[0][d] = z; pBl[0][d+1] = z; pBl[1][d] = z; pBl[1][d+1] = z;
        }
    }

    float acc[8][4];
#pragma unroll
    for (int i = 0; i < 8; i++)
#pragma unroll
        for (int j = 0; j < 4; j++) acc[i][j] = 0.f;

    int pb[4];
#pragma unroll
    for (int t = 0; t < 4; t++) {
        int m = m0w + t*8 + nq;
        pb[t] = (m >> 4)*18 + (m & 15);
    }

    auto stage = [&](int sl, int buf) {
#pragma unroll
        for (int i = 0; i < 2; i++) {
            int lin = tid + i*512;
            if (lin < 648 && p_gidx[i] >= 0) {
                int d = (lin >> 1)*4 + (lin & 1)*2;
                cp16(&pBh[buf][d], &g_inbf[p_gidx[i] + sl*4]);
                cp16(&pBl[buf][d], &g_inbl[p_gidx[i] + sl*4]);
            }
        }
#pragma unroll
        for (int i = 0; i < 3; i++) {
            int lin = tid + i*512;
            if (lin < 1152) {
                int idx = lin*2;
                int r = idx >> 6, nn = idx & 63;
                int d = r*WYS + nn;
                cp16(&wBh[buf][d], &g_wxbh[sl*2304 + idx]);
                cp16(&wBl[buf][d], &g_wxbl[sl*2304 + idx]);
            }
        }
    };

    stage(0, 0); cp_commit();
    for (int sl = 0; sl < 16; sl++) {
        int buf = sl & 1;
        if (sl < 15) { stage(sl + 1, buf ^ 1); cp_commit(); cp_wait1(); }
        else cp_wait0();
        __syncthreads();
        uint2* ph = pBh[buf]; uint2* pl = pBl[buf];
        uint2* wh = wBh[buf]; uint2* wl = wBl[buf];

#pragma unroll
        for (int tap = 0; tap < 9; tap++) {
            int posoff = (tap/3)*18 + (tap%3);
            uint2 hL0 = ph[(pb[0] + posoff)*4 + kq];
            uint2 hH0 = ph[(pb[1] + posoff)*4 + kq];
            uint2 hL1 = ph[(pb[2] + posoff)*4 + kq];
            uint2 hH1 = ph[(pb[3] + posoff)*4 + kq];
            uint2 lL0 = pl[(pb[0] + posoff)*4 + kq];
            uint2 lH0 = pl[(pb[1] + posoff)*4 + kq];
            uint2 lL1 = pl[(pb[2] + posoff)*4 + kq];
            uint2 lH1 = pl[(pb[3] + posoff)*4 + kq];
            unsigned A0h[4] = {hL0.x, hH0.x, hL0.y, hH0.y};
            unsigned A1h[4] = {hL1.x, hH1.x, hL1.y, hH1.y};
            unsigned A0l[4] = {lL0.x, lH0.x, lL0.y, lH0.y};
            unsigned A1l[4] = {lL1.x, lH1.x, lL1.y, lH1.y};
            int wr = (tap*4 + kq)*WYS + n0w + nq;
#pragma unroll
            for (int nt = 0; nt < 4; nt++) {
                uint2 bh = wh[wr + nt*8];
                uint2 bl = wl[wr + nt*8];
                mma_bf16(acc[nt],     A0h, bh.x, bh.y);
                mma_bf16(acc[nt],     A0h, bl.x, bl.y);
                mma_bf16(acc[nt],     A0l, bh.x, bh.y);
                mma_bf16(acc[4 + nt], A1h, bh.x, bh.y);
                mma_bf16(acc[4 + nt], A1h, bl.x, bl.y);
                mma_bf16(acc[4 + nt], A1l, bh.x, bh.y);
            }
        }
        __syncthreads();
    }

    // epilogue: scatter f32 to g_x embed layout (p = f*144 + t/64, c = t%64)
#pragma unroll
    for (int mt = 0; mt < 2; mt++) {
#pragma unroll
        for (int half = 0; half < 2; half++) {
            int m = m0w + mt*16 + half*8 + nq;
            int py = by + (m >> 4), px = bx + (m & 15);
            int p = py*kW + px;
            int f = p / 144, pm = p % 144;
#pragma unroll
            for (int nt = 0; nt < 4; nt++) {
                int c = n0w + nt*8 + 2*kq;
                float v0 = acc[mt*4 + nt][half*2]     + bias[c];
                float v1 = acc[mt*4 + nt][half*2 + 1] + bias[c+1];
                g_x[((size_t)n*kL + pm*64 + c    )*kC + f] = v0;
                g_x[((size_t)n*kL + pm*64 + c + 1)*kC + f] = v1;
            }
        }
    }
}

// ---------------- asm conv (y path), bf16 m16n8k16 MMA, double buffer ------
__global__ __launch_bounds__(512, 1) void convy_mma_kernel(const float* __restrict__ bias)
{
    extern __shared__ uint2 smy2[];
    uint2* pB[2] = {smy2,        smy2 + 1296};
    uint2* wB[2] = {smy2 + 2592, smy2 + 2592 + 2448};

    int n    = blockIdx.x / 36;
    int tile = blockIdx.x % 36;
    int by = (tile / 6) * 16, bx = (tile % 6) * 16;
    int cog = blockIdx.y;
    int co0 = cog * 64;
    int tid = threadIdx.x;
    int wid = tid >> 5, lane = tid & 31;
    int m0w = (wid >> 1) * 32;
    int n0w = (wid & 1) * 32;
    int kq = lane & 3;
    int nq = lane >> 2;

    long long p_gidx[2];
#pragma unroll
    for (int i = 0; i < 2; i++) {
        int lin = tid + i*512;
        p_gidx[i] = -1;
        if (lin < 648) {
            int pos = lin >> 1;
            int yy = pos / 18, xx = pos % 18;
            int hh = by + yy - 1, ww = bx + xx - 1;
            if (hh >= 0 && hh < kH && ww >= 0 && ww < kW)
                p_gidx[i] = ((long long)((n*kH + hh)*kW + ww))*64 + (lin & 1)*2;
        }
    }
#pragma unroll
    for (int i = 0; i < 2; i++) {
        int lin = tid + i*512;
        if (lin < 648 && p_gidx[i] < 0) {
            uint2 z = {0u, 0u};
            int d = (lin >> 1)*4 + (lin & 1)*2;
            pB[0][d] = z; pB[0][d+1] = z;
            pB[1][d] = z; pB[1][d+1] = z;
        }
    }

    float acc[8][4];
#pragma unroll
    for (int i = 0; i < 8; i++)
#pragma unroll
        for (int j = 0; j < 4; j++) acc[i][j] = 0.f;

    int pb[4];
#pragma unroll
    for (int t = 0; t < 4; t++) {
        int m = m0w + t*8 + nq;
        pb[t] = (m >> 4)*18 + (m & 15);
    }

    const uint2* wsrc = &g_wybf[cog*36864];

    auto stage = [&](int sl, int buf) {
#pragma unroll
        for (int i = 0; i < 2; i++) {
            int lin = tid + i*512;
            if (lin < 648 && p_gidx[i] >= 0)
                cp16(&pB[buf][(lin >> 1)*4 + (lin & 1)*2], &g_inbf[p_gidx[i] + sl*4]);
        }
#pragma unroll
        for (int i = 0; i < 3; i++) {
            int lin = tid + i*512;
            if (lin < 1152) {
                int idx = lin*2;
                int r = idx >> 6, nn = idx & 63;
                cp16(&wB[buf][r*WYS + nn], &wsrc[sl*2304 + idx]);
            }
        }
    };

    stage(0, 0); cp_commit();
    for (int sl = 0; sl < 16; sl++) {
        int buf = sl & 1;
        if (sl < 15) { stage(sl + 1, buf ^ 1); cp_commit(); cp_wait1(); }
        else cp_wait0();
        __syncthreads();
        uint2* up2 = pB[buf];
        uint2* w2  = wB[buf];

#pragma unroll
        for (int tap = 0; tap < 9; tap++) {
            int posoff = (tap/3)*18 + (tap%3);
            uint2 aL0 = up2[(pb[0] + posoff)*4 + kq];
            uint2 aH0 = up2[(pb[1] + posoff)*4 + kq];
            uint2 aL1 = up2[(pb[2] + posoff)*4 + kq];
            uint2 aH1 = up2[(pb[3] + posoff)*4 + kq];
            unsigned A0[4] = {aL0.x, aH0.x, aL0.y, aH0.y};
            unsigned A1[4] = {aL1.x, aH1.x, aL1.y, aH1.y};
            int wr = (tap*4 + kq)*WYS + n0w + nq;
#pragma unroll
            for (int nt = 0; nt < 4; nt++) {
                uint2 bw = w2[wr + nt*8];
                mma_bf16(acc[nt],     A0, bw.x, bw.y);
                mma_bf16(acc[4 + nt], A1, bw.x, bw.y);
            }
        }
        __syncthreads();
    }

#pragma unroll
    for (int mt = 0; mt < 2; mt++) {
#pragma unroll
        for (int half = 0; half < 2; half++) {
            int m = m0w + mt*16 + half*8 + nq;
            int py = by + (m >> 4), px = bx + (m & 15);
            int p = py*kW + px;
            int e = p / 36, pm = p % 36;
#pragma unroll
            for (int nt = 0; nt < 4; nt++) {
                int c = co0 + n0w + nt*8 + 2*kq;
                float v0 = acc[mt*4 + nt][half*2]     + bias[c];
                float v1 = acc[mt*4 + nt][half*2 + 1] + bias[c+1];
                g_yb[((size_t)n*kL + pm*256 + c    )*kCh + e] = __float2bfloat16_rn(v0);
                g_yb[((size_t)n*kL + pm*256 + c + 1)*kCh + e] = __float2bfloat16_rn(v1);
            }
        }
    }
}

// ---------------- LSH hashing ----------------
__global__ __launch_bounds__(256) void hash_kernel(const float* __restrict__ rot)
{
    __shared__ float Rsm[8192];
    __shared__ float xrow[8][64];
    int tid = threadIdx.x;
    for (int lin = tid; lin < 8192; lin += 256) Rsm[lin] = rot[lin];
    int wid = tid >> 5, lane = tid & 31;
    int idx = blockIdx.x*8 + wid;
    int n = idx / kL, t = idx % kL;
    const float* xr = &g_x[((size_t)n*kL + t)*kC];
    xrow[wid][lane]      = xr[lane];
    xrow[wid][lane + 32] = xr[lane + 32];
    __syncthreads();
#pragma unroll
    for (int h = 0; h < 4; h++) {
        float s = 0.f;
#pragma unroll
        for (int f = 0; f < 64; f++) s += xrow[wid][f] * Rsm[f*128 + h*32 + lane];
        float bv; int bi;
        if (s >= -s) { bv = s;  bi = lane; }
        else         { bv = -s; bi = lane + 32; }
#pragma unroll
        for (int off = 16; off > 0; off >>= 1) {
            float ov = __shfl_xor_sync(0xffffffffu, bv, off);
            int   oi = __shfl_xor_sync(0xffffffffu, bi, off);
            if (ov > bv || (ov == bv && oi < bi)) { bv = ov; bi = oi; }
        }
        if (lane == 0) g_codes[n*kTOTJ + h*kL + t] = bi + h*kHB;
    }
}

// ---------------- stable counting sort (argsort) ----------------
__global__ __launch_bounds__(256) void sortA_kernel()
{
    __shared__ int hist[256];
    int b = blockIdx.x; int n = b / 144, blk = b % 144; int tid = threadIdx.x;
    hist[tid] = 0; __syncthreads();
    int code = g_codes[n*kTOTJ + blk*256 + tid];
    atomicAdd(&hist[code], 1);
    __syncthreads();
    g_hist[(n*144 + blk)*256 + tid] = hist[tid];
}

__global__ __launch_bounds__(256) void sortBC_kernel()
{
    __shared__ int scanbuf[256];
    __shared__ int comb[256];
    __shared__ int cs[256];
    int b = blockIdx.x; int n = b / 144, blk = b % 144; int v = threadIdx.x;

    int tot = 0, off = 0;
    const int* hb = &g_hist[n*144*256 + v];
    for (int bb = 0; bb < 144; bb++) {
        int hv = hb[bb*256];
        tot += hv;
        if (bb < blk) off += hv;
    }
    scanbuf[v] = tot;
    __syncthreads();
    for (int d = 1; d < 256; d <<= 1) {
        int y = (v >= d) ? scanbuf[v - d] : 0;
        __syncthreads();
        scanbuf[v] += y;
        __syncthreads();
    }
    comb[v] = (scanbuf[v] - tot) + off;
    int c = g_codes[n*kTOTJ + blk*256 + v];
    cs[v] = c;
    __syncthreads();
    int rank = 0;
    for (int j = 0; j < v; j++) rank += (cs[j] == c);
    g_sorted[n*kTOTJ + comb[c] + rank] = blk*256 + v;
}

// ---------------- fused chunk attention: tf32 QK + bf16 ldmatrix PV --------
__global__ __launch_bounds__(ATHR, 1) void attn_kernel()
{
    extern __shared__ float sm[];
    float* Qr  = sm;                              // 9792 floats
    float* Kp  = Qr + 144*QRS;                    // 4864 floats (float2 pairs)
    unsigned* vs_u32  = (unsigned*)(sm + 14656);  // 80 rows x VSSU u32 (bf16 V)
    unsigned* psm_u32 = (unsigned*)(sm + 25216);  // 144 x PU32S u32 (bf16 P pairs)
    float* m_r = sm + 31552;                      // 144
    float* rowsumA = m_r + 144;                   // 144
    float* rowsumB = rowsumA + 144;               // 144
    int* tIdx = (int*)(rowsumB + 144);            // 432

    float2* kp2 = (float2*)Kp;

    int g = blockIdx.x;
    int n = g >> 8, k = g & 255;
    int h = k >> 6, kl = k & 63;
    int tid = threadIdx.x;
    int wid = tid >> 5, lane = tid & 31;
    int kq = lane & 3, nq = lane >> 2;

    for (int j = tid; j < kJW; j += ATHR) {
        int cchunk = j / kCHK, i = j % kCHK;
        int skl = (cchunk == 0) ? kl : (cchunk == 1) ? ((kl + 63) & 63) : ((kl + 1) & 63);
        int s = (h*64 + skl)*kCHK + i;
        tIdx[j] = g_sorted[n*kTOTJ + s] % kL;
    }
    for (int i = tid; i < kCHK; i += ATHR) { rowsumA[i] = 0.f; rowsumB[i] = 0.f; }
    for (int i = tid; i < 144*8; i += ATHR)
        psm_u32[(i >> 3)*PU32S + 36 + (i & 7)] = 0u;
    for (int i = tid; i < 8*VSSU; i += ATHR)
        vs_u32[72*VSSU + i] = 0u;
    __syncthreads();

    {
#pragma unroll
        for (int rr = 0; rr < 8; rr++) {
            int r = wid*8 + rr;
            const float* xr = &g_x[((size_t)n*kL + tIdx[r])*kC];
            float a = xr[lane], b = xr[lane + 32];
            Qr[r*QRS + lane] = a;
            Qr[r*QRS + lane + 32] = b;
            float ss = a*a + b*b;
#pragma unroll
            for (int off = 16; off > 0; off >>= 1)
                ss += __shfl_xor_sync(0xffffffffu, ss, off);
            if (lane == 0) m_r[r] = ss * rsqrtf(fmaxf(ss, 5e-5f));
        }
    }
    __syncthreads();

    int wq = wid % 9;
    int halfq = wid / 9;
    int m0 = wq * 16;
    float mA = m_r[m0 + nq], mB = m_r[m0 + 8 + nq];

    float Oacc[16][4];
#pragma unroll
    for (int i = 0; i < 16; i++)
#pragma unroll
        for (int j = 0; j < 4; j++) Oacc[i][j] = 0.f;

    unsigned pbase = (unsigned)__cvta_generic_to_shared(psm_u32);
    unsigned vbase = (unsigned)__cvta_generic_to_shared(vs_u32);
    unsigned aaddr = pbase + (unsigned)((m0 + (lane & 15))*(PU32S*4) + (lane >> 4)*16);
    unsigned baddr = vbase + (unsigned)((lane & 15)*(VSSU*4) + ((halfq*128 + (lane >> 4)*8) << 1));

    for (int jc = 0; jc < 6; jc++) {
        int j0 = jc*72;
        if (wid < 9) {
            int col = wid*8 + (lane >> 2);
            int fq = lane & 3;
            int fs = fq * 16;
            const float4* xr = (const float4*)&g_x[((size_t)n*kL + tIdx[j0 + col])*kC + fs];
            float4 v0 = xr[0], v1 = xr[1], v2 = xr[2], v3 = xr[3];
            float ss = v0.x*v0.x + v0.y*v0.y + v0.z*v0.z + v0.w*v0.w
                     + v1.x*v1.x + v1.y*v1.y + v1.z*v1.z + v1.w*v1.w
                     + v2.x*v2.x + v2.y*v2.y + v2.z*v2.z + v2.w*v2.w
                     + v3.x*v3.x + v3.y*v3.y + v3.z*v3.z + v3.w*v3.w;
            ss += __shfl_xor_sync(0xffffffffu, ss, 1);
            ss += __shfl_xor_sync(0xffffffffu, ss, 2);
            float r = rsqrtf(fmaxf(ss, 5e-5f));
            int ks0 = fq * 2;
            float2 t0; t0.x = v0.x*r; t0.y = v1.x*r; kp2[((ks0)*4 + 0)*KP2S + col] = t0;
            float2 t1; t1.x = v0.y*r; t1.y = v1.y*r; kp2[((ks0)*4 + 1)*KP2S + col] = t1;
            float2 t2; t2.x = v0.z*r; t2.y = v1.z*r; kp2[((ks0)*4 + 2)*KP2S + col] = t2;
            float2 t3; t3.x = v0.w*r; t3.y = v1.w*r; kp2[((ks0)*4 + 3)*KP2S + col] = t3;
            float2 t4; t4.x = v2.x*r; t4.y = v3.x*r; kp2[((ks0+1)*4 + 0)*KP2S + col] = t4;
            float2 t5; t5.x = v2.y*r; t5.y = v3.y*r; kp2[((ks0+1)*4 + 1)*KP2S + col] = t5;
            float2 t6; t6.x = v2.z*r; t6.y = v3.z*r; kp2[((ks0+1)*4 + 2)*KP2S + col] = t6;
            float2 t7; t7.x = v2.w*r; t7.y = v3.w*r; kp2[((ks0+1)*4 + 3)*KP2S + col] = t7;
        } else {
            int w2 = wid - 9;
#pragma unroll
            for (int r = 0; r < 8; r++) {
                int row = w2*8 + r;
                uint4 v = ((const uint4*)&g_yb[((size_t)n*kL + tIdx[j0 + row])*kCh])[lane];
                ((uint4*)vs_u32)[row*(VSSU/4) + lane] = v;
            }
        }
        __syncthreads();

        // QK MMA (tf32) + exp + bf16 P pairs to smem
        {
            unsigned Af[8][4];
#pragma unroll
            for (int ks = 0; ks < 8; ks++) {
                const float* q0 = &Qr[(m0 + nq)*QRS + ks*8 + kq];
                const float* q1 = &Qr[(m0 + 8 + nq)*QRS + ks*8 + kq];
                Af[ks][0] = __float_as_uint(q0[0]);
                Af[ks][1] = __float_as_uint(q1[0]);
                Af[ks][2] = __float_as_uint(q0[4]);
                Af[ks][3] = __float_as_uint(q1[4]);
            }
            float s0 = 0.f, s1 = 0.f;
            int ntBeg = halfq ? 5 : 0;
            int ntEnd = halfq ? 9 : 5;
            for (int nt = ntBeg; nt < ntEnd; nt++) {
                float acc[4] = {0.f, 0.f, 0.f, 0.f};
#pragma unroll
                for (int ks = 0; ks < 8; ks++) {
                    float2 bp = kp2[(ks*4 + kq)*KP2S + nt*8 + nq];
                    mma_tf32(acc, Af[ks], __float_as_uint(bp.x), __float_as_uint(bp.y));
                }
                float e0 = __expf(acc[0] - mA), e1 = __expf(acc[1] - mA);
                float e2 = __expf(acc[2] - mB), e3 = __expf(acc[3] - mB);
                s0 += e0 + e1; s1 += e2 + e3;
                psm_u32[(m0 + nq)*PU32S + nt*4 + kq]     = pack_bf2(e0, e1);
                psm_u32[(m0 + 8 + nq)*PU32S + nt*4 + kq] = pack_bf2(e2, e3);
            }
            s0 += __shfl_xor_sync(0xffffffffu, s0, 1);
            s0 += __shfl_xor_sync(0xffffffffu, s0, 2);
            s1 += __shfl_xor_sync(0xffffffffu, s1, 1);
            s1 += __shfl_xor_sync(0xffffffffu, s1, 2);
            if (kq == 0) {
                float* rs = halfq ? rowsumB : rowsumA;
                rs[m0 + nq] += s0;
                rs[m0 + 8 + nq] += s1;
            }
        }
        // partner-pair barrier: warps (wq,0) and (wq,1) exchange their P halves
        asm volatile("bar.sync %0, 64;" :: "r"(1 + wq) : "memory");

        // PV MMA (bf16 m16n8k16 via ldmatrix), 5 uniform k16 groups
        {
#pragma unroll
            for (int gg = 0; gg < 5; gg++) {
                unsigned A[4];
                ldm_x4(A, aaddr + gg*32);
#pragma unroll
                for (int np = 0; np < 8; np++) {
                    unsigned B[4];
                    ldm_x4t(B, baddr + gg*16*(VSSU*4) + np*32);
                    mma_bf16(Oacc[2*np],     A, B[0], B[1]);
                    mma_bf16(Oacc[2*np + 1], A, B[2], B[3]);
                }
            }
        }
        __syncthreads();
    }

    {
        int n0 = halfq * 128;
        int rA = m0 + nq, rB = rA + 8;
        float sumA = rowsumA[rA] + rowsumB[rA];
        float sumB = rowsumA[rB] + rowsumB[rB];
        float invA = 1.f / sumA;
        float invB = 1.f / sumB;
        size_t baseA = ((size_t)(n*4 + h)*kL + tIdx[rA])*kCh;
        size_t baseB = ((size_t)(n*4 + h)*kL + tIdx[rB])*kCh;
#pragma unroll
        for (int nt = 0; nt < 16; nt++) {
            int cA = n0 + nt*8 + 2*kq;
            g_retb[(baseA + cA) >> 1] = pack_bf2(Oacc[nt][0]*invA, Oacc[nt][1]*invA);
            g_retb[(baseB + cA) >> 1] = pack_bf2(Oacc[nt][2]*invB, Oacc[nt][3]*invB);
        }
        if (wid < 9 && lane < 16) {
            int row = wid*16 + lane;
            float s = rowsumA[row] + rowsumB[row];
            g_bs[(size_t)(n*4 + h)*kL + tIdx[row]] = m_r[row] + __logf(s);
        }
    }
}

// ---------------- head combine + residual + output layout ----------------
__global__ __launch_bounds__(256) void combine_kernel(
    const float* __restrict__ in, float* __restrict__ out)
{
    __shared__ float accs[256*33];
    __shared__ float probs[4*256];
    int n = blockIdx.x / 36, q = blockIdx.x % 36;
    int e0 = blockIdx.y * 32;
    int tid = threadIdx.x;

    {
        int t = q*256 + tid;
        float b0 = g_bs[(size_t)(n*4 + 0)*kL + t];
        float b1 = g_bs[(size_t)(n*4 + 1)*kL + t];
        float b2 = g_bs[(size_t)(n*4 + 2)*kL + t];
        float b3 = g_bs[(size_t)(n*4 + 3)*kL + t];
        float m = fmaxf(fmaxf(b0, b1), fmaxf(b2, b3));
        float x0 = __expf(b0 - m), x1 = __expf(b1 - m);
        float x2 = __expf(b2 - m), x3 = __expf(b3 - m);
        float sinv = 1.f / (x0 + x1 + x2 + x3);
        probs[0*256 + tid] = x0*sinv; probs[1*256 + tid] = x1*sinv;
        probs[2*256 + tid] = x2*sinv; probs[3*256 + tid] = x3*sinv;
    }
    for (int lin = tid; lin < 256*33; lin += 256) accs[lin] = 0.f;
    __syncthreads();

    for (int h = 0; h < 4; h++) {
        for (int lin = tid; lin < 256*16; lin += 256) {
            int cc = lin >> 4, ep = lin & 15;
            unsigned pv = g_retb[(((size_t)(n*4 + h)*kL + q*256 + cc)*kCh + e0) / 2 + ep];
            __nv_bfloat162 b = *(__nv_bfloat162*)&pv;
            float pr = probs[h*256 + cc];
            accs[cc*33 + 2*ep]     += pr * __low2float(b);
            accs[cc*33 + 2*ep + 1] += pr * __high2float(b);
        }
    }
    __syncthreads();

    for (int lin = tid; lin < 32*256; lin += 256) {
        int e = lin >> 8, c = lin & 255;
        int p = (e0 + e)*36 + q;
        size_t oi = ((size_t)n*kL + p)*kCh + c;
        out[oi] = 0.1f*accs[c*33 + e] + in[oi];
    }
}

// ---------------- launch: stream-forked (capture-safe fork/join) ----------
extern "C" void kernel_launch(void* const* d_in, const int* in_sizes, int n_in,
                              void* d_out, int out_size)
{
    const float* input     = (const float*)d_in[0];
    const float* w_match   = (const float*)d_in[1];
    const float* b_match   = (const float*)d_in[2];
    const float* w_asm     = (const float*)d_in[3];
    const float* b_asm     = (const float*)d_in[4];
    const float* rotations = (const float*)d_in[5];
    float* out = (float*)d_out;

    const int CONVX_SMEM = 14976 * 8;                                   // 119808
    const int CONVY_SMEM = (2592 + 2448*2) * 8;                         // 59904
    const int ATT_SMEM   = 32416 * 4;                                   // 129664

    static cudaStream_t sY = nullptr;
    static cudaEvent_t evFork = nullptr, evJoin = nullptr;
    if (sY == nullptr) {
        cudaStreamCreateWithFlags(&sY, cudaStreamNonBlocking);
        cudaEventCreateWithFlags(&evFork, cudaEventDisableTiming);
        cudaEventCreateWithFlags(&evJoin, cudaEventDisableTiming);
        cudaFuncSetAttribute(convx_mma_kernel, cudaFuncAttributeMaxDynamicSharedMemorySize, CONVX_SMEM);
        cudaFuncSetAttribute(convy_mma_kernel, cudaFuncAttributeMaxDynamicSharedMemorySize, CONVY_SMEM);
        cudaFuncSetAttribute(attn_kernel,      cudaFuncAttributeMaxDynamicSharedMemorySize, ATT_SMEM);
    }

    // #1: merged input prepack (hi+lo bf16 pairs) — feeds BOTH conv arms
    prep_inbf2_kernel<<<kN*kL*64/256, 256>>>(input);
    cudaEventRecord(evFork, 0);
    cudaStreamWaitEvent(sY, evFork, 0);

    prep_wxbf_kernel<<<144, 256>>>(w_match);                            // s0 (#2)
    prep_wybf_kernel<<<576, 256, 0, sY>>>(w_asm);                       // sY (#3)
    convy_mma_kernel<<<dim3(kN*36, 4), 512, CONVY_SMEM, sY>>>(b_asm);   // sY (#4, ncu slot)
    cudaEventRecord(evJoin, sY);
    convx_mma_kernel<<<kN*36, 512, CONVX_SMEM>>>(b_match);              // s0
    hash_kernel<<<kN*kL/8, 256>>>(rotations);
    sortA_kernel<<<kN*144, 256>>>();
    sortBC_kernel<<<kN*144, 256>>>();
    cudaStreamWaitEvent(0, evJoin, 0);
    attn_kernel<<<kN*256, ATHR, ATT_SMEM>>>();
    combine_kernel<<<dim3(kN*36, 8), 256>>>(input, out);
}